// round 2
// baseline (speedup 1.0000x reference)
#include <cuda_runtime.h>
#include <cuda_bf16.h>
#include <math.h>

#define NNODES 50000
#define NEDGES 800000
#define INCH 256
#define HID 256
#define OUTCH 128

// ---------------- scratch (static device globals; no allocation) ----------------
__device__ float g_deg[NNODES];
__device__ float g_dinv[NNODES];
__device__ int   g_count[NNODES];
__device__ int   g_fill[NNODES];
__device__ int   g_rowptr[NNODES + 1];
__device__ int   g_csr_src[NEDGES];
__device__ float g_csr_w[NEDGES];
__device__ float g_xa[(size_t)NNODES * 256];   // A @ x
__device__ float g_h [(size_t)NNODES * 256];   // conv1 output (post film/relu/LN)
__device__ float g_h2[(size_t)NNODES * 128];   // h @ conv2_w
__device__ float g_s[256];                     // signature vector
__device__ float g_gamma1[256], g_beta1[256];
__device__ float g_gamma2[128], g_beta2[128];

// ---------------- init ----------------
__global__ void k_init()
{
    int i = blockIdx.x * blockDim.x + threadIdx.x;
    if (i < NNODES) {
        g_deg[i] = 1.0f;   // self loop contributes 1 to src-degree
        g_count[i] = 0;
        g_fill[i] = 0;
    }
    if (i < 256) g_s[i] = 0.0f;
}

// ---------------- degree over src + histogram over dst ----------------
__global__ void k_deg_count(const int* __restrict__ ei)
{
    int e = blockIdx.x * blockDim.x + threadIdx.x;
    if (e < NEDGES) {
        int s = ei[e];
        int d = ei[NEDGES + e];
        atomicAdd(&g_deg[s], 1.0f);
        atomicAdd(&g_count[d], 1);
    }
}

__global__ void k_dinv()
{
    int i = blockIdx.x * blockDim.x + threadIdx.x;
    if (i < NNODES) g_dinv[i] = rsqrtf(g_deg[i]);
}

// ---------------- single-block scan: rowptr = exclusive_scan(count) ----------------
__global__ void k_scan()
{
    __shared__ int sh[1024];
    __shared__ int s_off;
    int t = threadIdx.x;
    if (t == 0) s_off = 0;
    __syncthreads();
    for (int base = 0; base < NNODES; base += 1024) {
        int i = base + t;
        int v = (i < NNODES) ? g_count[i] : 0;
        sh[t] = v;
        __syncthreads();
        for (int ofs = 1; ofs < 1024; ofs <<= 1) {
            int a = (t >= ofs) ? sh[t - ofs] : 0;
            __syncthreads();
            sh[t] += a;
            __syncthreads();
        }
        int off = s_off;
        if (i < NNODES) g_rowptr[i] = off + sh[t] - v;
        int total = sh[1023];
        __syncthreads();
        if (t == 0) s_off += total;
        __syncthreads();
    }
    if (t == 0) g_rowptr[NNODES] = NEDGES;
}

// ---------------- CSR fill (per-dst edge lists with precomputed norm) ----------------
__global__ void k_fill(const int* __restrict__ ei)
{
    int e = blockIdx.x * blockDim.x + threadIdx.x;
    if (e < NEDGES) {
        int s = ei[e];
        int d = ei[NEDGES + e];
        int p = g_rowptr[d] + atomicAdd(&g_fill[d], 1);
        g_csr_src[p] = s;
        g_csr_w[p] = g_dinv[s] * g_dinv[d];
    }
}

// ---------------- xa = A @ x  (256-wide gather-sum per node) ----------------
__global__ void k_agg1(const float* __restrict__ x)
{
    int d = blockIdx.x;
    int c = threadIdx.x; // 256
    float dv = g_dinv[d];
    float acc = dv * dv * x[(size_t)d * 256 + c];
    int beg = g_rowptr[d], end = g_rowptr[d + 1];
    int j = beg;
    for (; j + 4 <= end; j += 4) {
        int s0 = g_csr_src[j], s1 = g_csr_src[j + 1];
        int s2 = g_csr_src[j + 2], s3 = g_csr_src[j + 3];
        float w0 = g_csr_w[j], w1 = g_csr_w[j + 1];
        float w2 = g_csr_w[j + 2], w3 = g_csr_w[j + 3];
        float v0 = x[(size_t)s0 * 256 + c];
        float v1 = x[(size_t)s1 * 256 + c];
        float v2 = x[(size_t)s2 * 256 + c];
        float v3 = x[(size_t)s3 * 256 + c];
        acc += w0 * v0 + w1 * v1 + w2 * v2 + w3 * v3;
    }
    for (; j < end; j++)
        acc += g_csr_w[j] * x[(size_t)g_csr_src[j] * 256 + c];
    g_xa[(size_t)d * 256 + c] = acc;
}

// ---------------- tiled SGEMM: C = A_glob @ B, fused epilogues ----------------
// MODE 0: A=g_h,  C=g_h2  (N=128, plain)                         [conv2]
// MODE 1: A=g_xa, C=g_h   (N=256, film(gamma1,beta1)+bias+relu)  [conv1]
// MODE 2: A=g_xa, no C    (N=256, bias+relu -> column sum to g_s)[sig]
template <int MODE, int NN>
__global__ void __launch_bounds__(256)
k_gemm(const float* __restrict__ B, const float* __restrict__ bias)
{
    const float* A = (MODE == 0) ? g_h : g_xa;
    __shared__ float As[16][132];
    __shared__ float Bs[16][128];
    const int bm = blockIdx.y * 128;
    const int bn = blockIdx.x * 128;
    const int tid = threadIdx.x;
    const int tx = tid & 15, ty = tid >> 4;

    float acc[8][8];
#pragma unroll
    for (int i = 0; i < 8; i++)
#pragma unroll
        for (int j = 0; j < 8; j++) acc[i][j] = 0.0f;

    const int arow = tid >> 2, akq = tid & 3;
    const int brow = tid >> 5, bcol = (tid & 31) * 4;

    for (int k0 = 0; k0 < 256; k0 += 16) {
#pragma unroll
        for (int h = 0; h < 2; h++) {
            int r = arow + h * 64;
            int grow = bm + r;
            float4 v = make_float4(0.f, 0.f, 0.f, 0.f);
            if (grow < NNODES)
                v = *(const float4*)&A[(size_t)grow * 256 + k0 + akq * 4];
            As[akq * 4 + 0][r] = v.x;
            As[akq * 4 + 1][r] = v.y;
            As[akq * 4 + 2][r] = v.z;
            As[akq * 4 + 3][r] = v.w;
        }
#pragma unroll
        for (int h = 0; h < 2; h++) {
            int k = k0 + brow + h * 8;
            float4 v = *(const float4*)&B[(size_t)k * NN + bn + bcol];
            *(float4*)&Bs[brow + h * 8][bcol] = v;
        }
        __syncthreads();
#pragma unroll
        for (int kk = 0; kk < 16; kk++) {
            float a[8], b[8];
#pragma unroll
            for (int i = 0; i < 8; i++) a[i] = As[kk][ty * 8 + i];
#pragma unroll
            for (int j = 0; j < 8; j++) b[j] = Bs[kk][tx * 8 + j];
#pragma unroll
            for (int i = 0; i < 8; i++)
#pragma unroll
                for (int j = 0; j < 8; j++) acc[i][j] += a[i] * b[j];
        }
        __syncthreads();
    }

    if (MODE == 0) {
#pragma unroll
        for (int i = 0; i < 8; i++) {
            int r = bm + ty * 8 + i;
            if (r < NNODES) {
#pragma unroll
                for (int j = 0; j < 8; j++)
                    g_h2[(size_t)r * 128 + bn + tx * 8 + j] = acc[i][j];
            }
        }
    }
    if (MODE == 1) {
#pragma unroll
        for (int j = 0; j < 8; j++) {
            int c = bn + tx * 8 + j;
            float ga = g_gamma1[c];
            float be = g_beta1[c] + bias[c];
#pragma unroll
            for (int i = 0; i < 8; i++) {
                int r = bm + ty * 8 + i;
                if (r < NNODES)
                    g_h[(size_t)r * 256 + c] = fmaxf(ga * acc[i][j] + be, 0.0f);
            }
        }
    }
    if (MODE == 2) {
        float part[8];
#pragma unroll
        for (int j = 0; j < 8; j++) {
            int c = bn + tx * 8 + j;
            float bb = bias[c];
            float p = 0.f;
#pragma unroll
            for (int i = 0; i < 8; i++) {
                int r = bm + ty * 8 + i;
                if (r < NNODES) p += fmaxf(acc[i][j] + bb, 0.0f);
            }
            part[j] = p;
        }
        __shared__ float red[16][128];
#pragma unroll
        for (int j = 0; j < 8; j++) red[ty][tx * 8 + j] = part[j];
        __syncthreads();
        if (tid < 128) {
            float s = 0.f;
#pragma unroll
            for (int t = 0; t < 16; t++) s += red[t][tid];
            atomicAdd(&g_s[bn + tid], s);
        }
    }
}

// ---------------- tiny FC heads: gamma/beta = tanh(W s + b) ----------------
__global__ void k_fcs(const float* __restrict__ fc1_w, const float* __restrict__ fc1_b,
                      const float* __restrict__ fc2_w, const float* __restrict__ fc2_b,
                      const float* __restrict__ fc3_w, const float* __restrict__ fc3_b,
                      const float* __restrict__ fc4_w, const float* __restrict__ fc4_b)
{
    __shared__ float sh_s[256];
    int t = threadIdx.x;
    sh_s[t] = g_s[t];
    __syncthreads();
    float a1 = fc1_b[t], a2 = fc2_b[t];
    float a3 = (t < 128) ? fc3_b[t] : 0.f;
    float a4 = (t < 128) ? fc4_b[t] : 0.f;
    for (int k = 0; k < 256; k++) {
        float sv = sh_s[k];
        a1 += fc1_w[t * 256 + k] * sv;
        a2 += fc2_w[t * 256 + k] * sv;
        if (t < 128) {
            a3 += fc3_w[t * 256 + k] * sv;
            a4 += fc4_w[t * 256 + k] * sv;
        }
    }
    g_gamma1[t] = tanhf(a1);
    g_beta1[t]  = tanhf(a2);
    if (t < 128) {
        g_gamma2[t] = tanhf(a3);
        g_beta2[t]  = tanhf(a4);
    }
}

// ---------------- layernorm (width 256, in place on g_h) ----------------
__global__ void k_ln256()
{
    int row = blockIdx.x;
    int t = threadIdx.x;
    float v = g_h[(size_t)row * 256 + t];
    float s1 = v, s2 = v * v;
#pragma unroll
    for (int o = 16; o; o >>= 1) {
        s1 += __shfl_xor_sync(0xffffffffu, s1, o);
        s2 += __shfl_xor_sync(0xffffffffu, s2, o);
    }
    __shared__ float shs[16];
    __shared__ float s_mu, s_rstd;
    if ((t & 31) == 0) { shs[t >> 5] = s1; shs[8 + (t >> 5)] = s2; }
    __syncthreads();
    if (t == 0) {
        float a = 0.f, b = 0.f;
        for (int i = 0; i < 8; i++) { a += shs[i]; b += shs[8 + i]; }
        float mu = a * (1.0f / 256.0f);
        float var = b * (1.0f / 256.0f) - mu * mu;
        s_mu = mu;
        s_rstd = rsqrtf(var + 1e-5f);
    }
    __syncthreads();
    g_h[(size_t)row * 256 + t] = (v - s_mu) * s_rstd;
}

// ---------------- final: agg(h2) + film + layernorm -> out ----------------
__global__ void k_agg2(const float* __restrict__ bias, float* __restrict__ out)
{
    int d = blockIdx.x;
    int c = threadIdx.x; // 128
    float dv = g_dinv[d];
    float acc = dv * dv * g_h2[(size_t)d * 128 + c];
    int beg = g_rowptr[d], end = g_rowptr[d + 1];
    int j = beg;
    for (; j + 4 <= end; j += 4) {
        int s0 = g_csr_src[j], s1 = g_csr_src[j + 1];
        int s2 = g_csr_src[j + 2], s3 = g_csr_src[j + 3];
        float w0 = g_csr_w[j], w1 = g_csr_w[j + 1];
        float w2 = g_csr_w[j + 2], w3 = g_csr_w[j + 3];
        acc += w0 * g_h2[(size_t)s0 * 128 + c] + w1 * g_h2[(size_t)s1 * 128 + c]
             + w2 * g_h2[(size_t)s2 * 128 + c] + w3 * g_h2[(size_t)s3 * 128 + c];
    }
    for (; j < end; j++)
        acc += g_csr_w[j] * g_h2[(size_t)g_csr_src[j] * 128 + c];

    float y = g_gamma2[c] * acc + g_beta2[c] + bias[c];
    float s1 = y, s2 = y * y;
#pragma unroll
    for (int o = 16; o; o >>= 1) {
        s1 += __shfl_xor_sync(0xffffffffu, s1, o);
        s2 += __shfl_xor_sync(0xffffffffu, s2, o);
    }
    __shared__ float shs[8];
    __shared__ float s_mu, s_rstd;
    if ((c & 31) == 0) { shs[c >> 5] = s1; shs[4 + (c >> 5)] = s2; }
    __syncthreads();
    if (c == 0) {
        float a = 0.f, b = 0.f;
        for (int i = 0; i < 4; i++) { a += shs[i]; b += shs[4 + i]; }
        float mu = a * (1.0f / 128.0f);
        float var = b * (1.0f / 128.0f) - mu * mu;
        s_mu = mu;
        s_rstd = rsqrtf(var + 1e-5f);
    }
    __syncthreads();
    out[(size_t)d * 128 + c] = (y - s_mu) * s_rstd;
}

// ---------------- launch ----------------
extern "C" void kernel_launch(void* const* d_in, const int* in_sizes, int n_in,
                              void* d_out, int out_size)
{
    const float* x       = (const float*)d_in[0];
    const int*   ei      = (const int*)d_in[1];   // int32! (JAX x64 disabled downcasts int64)
    const float* conv1_w = (const float*)d_in[2];
    const float* conv1_b = (const float*)d_in[3];
    const float* conv2_w = (const float*)d_in[4];
    const float* conv2_b = (const float*)d_in[5];
    const float* sig_w   = (const float*)d_in[6];
    const float* sig_b   = (const float*)d_in[7];
    const float* fc1_w   = (const float*)d_in[8];
    const float* fc1_b   = (const float*)d_in[9];
    const float* fc2_w   = (const float*)d_in[10];
    const float* fc2_b   = (const float*)d_in[11];
    const float* fc3_w   = (const float*)d_in[12];
    const float* fc3_b   = (const float*)d_in[13];
    const float* fc4_w   = (const float*)d_in[14];
    const float* fc4_b   = (const float*)d_in[15];
    float*       out     = (float*)d_out;

    const int TB = 256;
    k_init<<<(NNODES + TB - 1) / TB, TB>>>();
    k_deg_count<<<(NEDGES + TB - 1) / TB, TB>>>(ei);
    k_dinv<<<(NNODES + TB - 1) / TB, TB>>>();
    k_scan<<<1, 1024>>>();
    k_fill<<<(NEDGES + TB - 1) / TB, TB>>>(ei);
    k_agg1<<<NNODES, 256>>>(x);

    dim3 g256(2, (NNODES + 127) / 128);   // N=256
    dim3 g128(1, (NNODES + 127) / 128);   // N=128

    k_gemm<2, 256><<<g256, 256>>>(sig_w, sig_b);                  // signature colsum
    k_fcs<<<1, 256>>>(fc1_w, fc1_b, fc2_w, fc2_b, fc3_w, fc3_b, fc4_w, fc4_b);
    k_gemm<1, 256><<<g256, 256>>>(conv1_w, conv1_b);              // conv1 + film + relu
    k_ln256<<<NNODES, 256>>>();
    k_gemm<0, 128><<<g128, 256>>>(conv2_w, nullptr);              // conv2 linear part
    k_agg2<<<NNODES, 128>>>(conv2_b, out);                        // agg + film + LN
}

// round 3
// speedup vs baseline: 1.1068x; 1.1068x over previous
#include <cuda_runtime.h>
#include <cuda_bf16.h>
#include <math.h>

#define NNODES 50000
#define NEDGES 800000

typedef unsigned long long u64;

__device__ __forceinline__ u64 pack2(float lo, float hi) {
    u64 r; asm("mov.b64 %0, {%1, %2};" : "=l"(r) : "f"(lo), "f"(hi)); return r;
}
__device__ __forceinline__ void unpack2(u64 v, float& lo, float& hi) {
    asm("mov.b64 {%0, %1}, %2;" : "=f"(lo), "=f"(hi) : "l"(v));
}
#define FMA2(d, a, b) asm("fma.rn.f32x2 %0, %1, %2, %0;" : "+l"(d) : "l"(a), "l"(b))

// ---------------- scratch (static device globals; no allocation) ----------------
__device__ float g_deg[NNODES];
__device__ float g_dinv[NNODES];
__device__ int   g_count[NNODES];
__device__ int   g_fill[NNODES];
__device__ int   g_rowptr[NNODES + 1];
__device__ int   g_bsum[64];
__device__ int   g_boff[64];
__device__ int   g_csr_src[NEDGES];
__device__ float g_csr_w[NEDGES];
__device__ float g_xa[(size_t)NNODES * 256];   // A @ x
__device__ float g_h [(size_t)NNODES * 256];   // conv1 output (pre-LN, post film/relu)
__device__ float g_h2[(size_t)NNODES * 128];   // LN(h) @ conv2_w
__device__ float g_mu[NNODES], g_rstd[NNODES];
__device__ float g_s[256];
__device__ float g_gamma1[256], g_beta1[256];
__device__ float g_gamma2[128], g_beta2[128];

// ---------------- init ----------------
__global__ void k_init()
{
    int i = blockIdx.x * blockDim.x + threadIdx.x;
    if (i < NNODES) {
        g_deg[i] = 1.0f;
        g_count[i] = 0;
        g_fill[i] = 0;
    }
    if (i < 256) g_s[i] = 0.0f;
}

__global__ void k_deg_count(const int* __restrict__ ei)
{
    int e = blockIdx.x * blockDim.x + threadIdx.x;
    if (e < NEDGES) {
        atomicAdd(&g_deg[ei[e]], 1.0f);
        atomicAdd(&g_count[ei[NEDGES + e]], 1);
    }
}

__global__ void k_dinv()
{
    int i = blockIdx.x * blockDim.x + threadIdx.x;
    if (i < NNODES) g_dinv[i] = rsqrtf(g_deg[i]);
}

// ---------------- 3-stage scan: rowptr = exclusive_scan(count) ----------------
__global__ void k_scan1()
{
    __shared__ int sh[1024];
    int t = threadIdx.x;
    int i = blockIdx.x * 1024 + t;
    int v = (i < NNODES) ? g_count[i] : 0;
    sh[t] = v;
    __syncthreads();
#pragma unroll
    for (int ofs = 1; ofs < 1024; ofs <<= 1) {
        int a = (t >= ofs) ? sh[t - ofs] : 0;
        __syncthreads();
        sh[t] += a;
        __syncthreads();
    }
    if (i < NNODES) g_rowptr[i] = sh[t] - v;   // block-local exclusive
    if (t == 1023) g_bsum[blockIdx.x] = sh[1023];
}

__global__ void k_scan2(int nblk)
{
    __shared__ int sh[64];
    int t = threadIdx.x;
    int v = (t < nblk) ? g_bsum[t] : 0;
    sh[t] = v;
    __syncthreads();
#pragma unroll
    for (int ofs = 1; ofs < 64; ofs <<= 1) {
        int a = (t >= ofs) ? sh[t - ofs] : 0;
        __syncthreads();
        sh[t] += a;
        __syncthreads();
    }
    g_boff[t] = sh[t] - v;   // exclusive
}

__global__ void k_scan3()
{
    int i = blockIdx.x * 1024 + threadIdx.x;
    if (i < NNODES) g_rowptr[i] += g_boff[blockIdx.x];
    if (i == 0) g_rowptr[NNODES] = NEDGES;
}

// ---------------- CSR fill ----------------
__global__ void k_fill(const int* __restrict__ ei)
{
    int e = blockIdx.x * blockDim.x + threadIdx.x;
    if (e < NEDGES) {
        int s = ei[e];
        int d = ei[NEDGES + e];
        int p = g_rowptr[d] + atomicAdd(&g_fill[d], 1);
        g_csr_src[p] = s;
        g_csr_w[p] = g_dinv[s] * g_dinv[d];
    }
}

// ---------------- xa = A @ x  (256-wide gather-sum per node) ----------------
__global__ void k_agg1(const float* __restrict__ x)
{
    int d = blockIdx.x;
    int c = threadIdx.x;
    float dv = g_dinv[d];
    float acc = dv * dv * x[(size_t)d * 256 + c];
    int beg = g_rowptr[d], end = g_rowptr[d + 1];
    int j = beg;
    for (; j + 4 <= end; j += 4) {
        int s0 = g_csr_src[j], s1 = g_csr_src[j + 1];
        int s2 = g_csr_src[j + 2], s3 = g_csr_src[j + 3];
        float w0 = g_csr_w[j], w1 = g_csr_w[j + 1];
        float w2 = g_csr_w[j + 2], w3 = g_csr_w[j + 3];
        acc += w0 * x[(size_t)s0 * 256 + c] + w1 * x[(size_t)s1 * 256 + c]
             + w2 * x[(size_t)s2 * 256 + c] + w3 * x[(size_t)s3 * 256 + c];
    }
    for (; j < end; j++)
        acc += g_csr_w[j] * x[(size_t)g_csr_src[j] * 256 + c];
    g_xa[(size_t)d * 256 + c] = acc;
}

// ---------------- tiled SGEMM with f32x2 packed FMA ----------------
// MODE 0: A=LN(g_h), C=g_h2 (N=128)                 [conv2]
// MODE 1: A=g_xa,    C=g_h  (N=256, film+bias+relu) [conv1]
// MODE 2: A=g_xa, no C (N=256, bias+relu -> colsum) [sig]
template <int MODE, int NN>
__global__ void __launch_bounds__(256)
k_gemm(const float* __restrict__ B, const float* __restrict__ bias)
{
    const float* A = (MODE == 0) ? g_h : g_xa;
    __shared__ float As[16][132];
    __shared__ float Bs[16][128];
    const int bm = blockIdx.y * 128;
    const int bn = blockIdx.x * 128;
    const int tid = threadIdx.x;
    const int tx = tid & 15, ty = tid >> 4;

    u64 acc2[8][4];
#pragma unroll
    for (int i = 0; i < 8; i++)
#pragma unroll
        for (int j = 0; j < 4; j++) acc2[i][j] = 0ull;

    const int arow = tid >> 2, akq = tid & 3;
    const int brow = tid >> 5, bcol = (tid & 31) * 4;

    float4 aereg[2], bereg[2];
    float mu0 = 0.f, rs0 = 0.f, mu1 = 0.f, rs1 = 0.f;

    // prologue: load tile k0=0 into regs
    {
        int g0 = bm + arow, g1 = bm + arow + 64;
        aereg[0] = make_float4(0.f, 0.f, 0.f, 0.f);
        aereg[1] = make_float4(0.f, 0.f, 0.f, 0.f);
        if (g0 < NNODES) {
            aereg[0] = *(const float4*)&A[(size_t)g0 * 256 + akq * 4];
            if (MODE == 0) { mu0 = g_mu[g0]; rs0 = g_rstd[g0]; }
        }
        if (g1 < NNODES) {
            aereg[1] = *(const float4*)&A[(size_t)g1 * 256 + akq * 4];
            if (MODE == 0) { mu1 = g_mu[g1]; rs1 = g_rstd[g1]; }
        }
        bereg[0] = *(const float4*)&B[(size_t)(brow) * NN + bn + bcol];
        bereg[1] = *(const float4*)&B[(size_t)(brow + 8) * NN + bn + bcol];
    }

    for (int k0 = 0; k0 < 256; k0 += 16) {
        // store regs -> smem (apply LN on the fly for MODE 0)
        {
            float4 v0 = aereg[0], v1 = aereg[1];
            if (MODE == 0) {
                v0.x = (v0.x - mu0) * rs0; v0.y = (v0.y - mu0) * rs0;
                v0.z = (v0.z - mu0) * rs0; v0.w = (v0.w - mu0) * rs0;
                v1.x = (v1.x - mu1) * rs1; v1.y = (v1.y - mu1) * rs1;
                v1.z = (v1.z - mu1) * rs1; v1.w = (v1.w - mu1) * rs1;
            }
            As[akq * 4 + 0][arow] = v0.x;
            As[akq * 4 + 1][arow] = v0.y;
            As[akq * 4 + 2][arow] = v0.z;
            As[akq * 4 + 3][arow] = v0.w;
            As[akq * 4 + 0][arow + 64] = v1.x;
            As[akq * 4 + 1][arow + 64] = v1.y;
            As[akq * 4 + 2][arow + 64] = v1.z;
            As[akq * 4 + 3][arow + 64] = v1.w;
            *(float4*)&Bs[brow][bcol] = bereg[0];
            *(float4*)&Bs[brow + 8][bcol] = bereg[1];
        }
        __syncthreads();

        // prefetch next tile (LDG latency hidden behind compute)
        int kn = k0 + 16;
        if (kn < 256) {
            int g0 = bm + arow, g1 = bm + arow + 64;
            aereg[0] = make_float4(0.f, 0.f, 0.f, 0.f);
            aereg[1] = make_float4(0.f, 0.f, 0.f, 0.f);
            if (g0 < NNODES) aereg[0] = *(const float4*)&A[(size_t)g0 * 256 + kn + akq * 4];
            if (g1 < NNODES) aereg[1] = *(const float4*)&A[(size_t)g1 * 256 + kn + akq * 4];
            bereg[0] = *(const float4*)&B[(size_t)(kn + brow) * NN + bn + bcol];
            bereg[1] = *(const float4*)&B[(size_t)(kn + brow + 8) * NN + bn + bcol];
        }

#pragma unroll
        for (int kk = 0; kk < 16; kk++) {
            u64 b2[4];
            const u64* bsrc = (const u64*)&Bs[kk][tx * 8];
#pragma unroll
            for (int j = 0; j < 4; j++) b2[j] = bsrc[j];
#pragma unroll
            for (int i = 0; i < 8; i++) {
                float av = As[kk][ty * 8 + i];
                u64 a2 = pack2(av, av);
#pragma unroll
                for (int j = 0; j < 4; j++) FMA2(acc2[i][j], a2, b2[j]);
            }
        }
        __syncthreads();
    }

    if (MODE == 0) {
#pragma unroll
        for (int i = 0; i < 8; i++) {
            int r = bm + ty * 8 + i;
            if (r < NNODES) {
#pragma unroll
                for (int j = 0; j < 4; j++)
                    *(u64*)&g_h2[(size_t)r * 128 + bn + tx * 8 + 2 * j] = acc2[i][j];
            }
        }
    }
    if (MODE == 1) {
#pragma unroll
        for (int j = 0; j < 4; j++) {
            int c = bn + tx * 8 + 2 * j;
            float ga0 = g_gamma1[c],     be0 = g_beta1[c] + bias[c];
            float ga1 = g_gamma1[c + 1], be1 = g_beta1[c + 1] + bias[c + 1];
#pragma unroll
            for (int i = 0; i < 8; i++) {
                int r = bm + ty * 8 + i;
                if (r < NNODES) {
                    float lo, hi;
                    unpack2(acc2[i][j], lo, hi);
                    float2 o;
                    o.x = fmaxf(ga0 * lo + be0, 0.0f);
                    o.y = fmaxf(ga1 * hi + be1, 0.0f);
                    *(float2*)&g_h[(size_t)r * 256 + c] = o;
                }
            }
        }
    }
    if (MODE == 2) {
        __shared__ float red[16][128];
#pragma unroll
        for (int j = 0; j < 4; j++) {
            int c = bn + tx * 8 + 2 * j;
            float b0 = bias[c], b1 = bias[c + 1];
            float p0 = 0.f, p1 = 0.f;
#pragma unroll
            for (int i = 0; i < 8; i++) {
                int r = bm + ty * 8 + i;
                if (r < NNODES) {
                    float lo, hi;
                    unpack2(acc2[i][j], lo, hi);
                    p0 += fmaxf(lo + b0, 0.0f);
                    p1 += fmaxf(hi + b1, 0.0f);
                }
            }
            red[ty][tx * 8 + 2 * j] = p0;
            red[ty][tx * 8 + 2 * j + 1] = p1;
        }
        __syncthreads();
        if (tid < 128) {
            float s = 0.f;
#pragma unroll
            for (int t = 0; t < 16; t++) s += red[t][tid];
            atomicAdd(&g_s[bn + tid], s);
        }
    }
}

// ---------------- tiny FC heads: gamma/beta = tanh(W s + b) ----------------
__global__ void k_fcs(const float* __restrict__ fc1_w, const float* __restrict__ fc1_b,
                      const float* __restrict__ fc2_w, const float* __restrict__ fc2_b,
                      const float* __restrict__ fc3_w, const float* __restrict__ fc3_b,
                      const float* __restrict__ fc4_w, const float* __restrict__ fc4_b)
{
    __shared__ float sh_s[256];
    int t = threadIdx.x;
    sh_s[t] = g_s[t];
    __syncthreads();
    float a1 = fc1_b[t], a2 = fc2_b[t];
    float a3 = (t < 128) ? fc3_b[t] : 0.f;
    float a4 = (t < 128) ? fc4_b[t] : 0.f;
    for (int k = 0; k < 256; k++) {
        float sv = sh_s[k];
        a1 += fc1_w[t * 256 + k] * sv;
        a2 += fc2_w[t * 256 + k] * sv;
        if (t < 128) {
            a3 += fc3_w[t * 256 + k] * sv;
            a4 += fc4_w[t * 256 + k] * sv;
        }
    }
    g_gamma1[t] = tanhf(a1);
    g_beta1[t]  = tanhf(a2);
    if (t < 128) {
        g_gamma2[t] = tanhf(a3);
        g_beta2[t]  = tanhf(a4);
    }
}

// ---------------- LN-256 stats (mu/rstd only; applied inside conv2 GEMM) --------
__global__ void k_lnstats()
{
    int row = blockIdx.x;
    int t = threadIdx.x;
    float v = g_h[(size_t)row * 256 + t];
    float s1 = v, s2 = v * v;
#pragma unroll
    for (int o = 16; o; o >>= 1) {
        s1 += __shfl_xor_sync(0xffffffffu, s1, o);
        s2 += __shfl_xor_sync(0xffffffffu, s2, o);
    }
    __shared__ float shs[16];
    if ((t & 31) == 0) { shs[t >> 5] = s1; shs[8 + (t >> 5)] = s2; }
    __syncthreads();
    if (t == 0) {
        float a = 0.f, b = 0.f;
        for (int i = 0; i < 8; i++) { a += shs[i]; b += shs[8 + i]; }
        float mu = a * (1.0f / 256.0f);
        float var = b * (1.0f / 256.0f) - mu * mu;
        g_mu[row] = mu;
        g_rstd[row] = rsqrtf(var + 1e-5f);
    }
}

// ---------------- final: agg(h2) + film + layernorm -> out ----------------
__global__ void k_agg2(const float* __restrict__ bias, float* __restrict__ out)
{
    int d = blockIdx.x;
    int c = threadIdx.x;
    float dv = g_dinv[d];
    float acc = dv * dv * g_h2[(size_t)d * 128 + c];
    int beg = g_rowptr[d], end = g_rowptr[d + 1];
    int j = beg;
    for (; j + 4 <= end; j += 4) {
        int s0 = g_csr_src[j], s1 = g_csr_src[j + 1];
        int s2 = g_csr_src[j + 2], s3 = g_csr_src[j + 3];
        float w0 = g_csr_w[j], w1 = g_csr_w[j + 1];
        float w2 = g_csr_w[j + 2], w3 = g_csr_w[j + 3];
        acc += w0 * g_h2[(size_t)s0 * 128 + c] + w1 * g_h2[(size_t)s1 * 128 + c]
             + w2 * g_h2[(size_t)s2 * 128 + c] + w3 * g_h2[(size_t)s3 * 128 + c];
    }
    for (; j < end; j++)
        acc += g_csr_w[j] * g_h2[(size_t)g_csr_src[j] * 128 + c];

    float y = g_gamma2[c] * acc + g_beta2[c] + bias[c];
    float s1 = y, s2 = y * y;
#pragma unroll
    for (int o = 16; o; o >>= 1) {
        s1 += __shfl_xor_sync(0xffffffffu, s1, o);
        s2 += __shfl_xor_sync(0xffffffffu, s2, o);
    }
    __shared__ float shs[8];
    __shared__ float s_mu, s_rstd;
    if ((c & 31) == 0) { shs[c >> 5] = s1; shs[4 + (c >> 5)] = s2; }
    __syncthreads();
    if (c == 0) {
        float a = 0.f, b = 0.f;
        for (int i = 0; i < 4; i++) { a += shs[i]; b += shs[4 + i]; }
        float mu = a * (1.0f / 128.0f);
        float var = b * (1.0f / 128.0f) - mu * mu;
        s_mu = mu;
        s_rstd = rsqrtf(var + 1e-5f);
    }
    __syncthreads();
    out[(size_t)d * 128 + c] = (y - s_mu) * s_rstd;
}

// ---------------- launch ----------------
extern "C" void kernel_launch(void* const* d_in, const int* in_sizes, int n_in,
                              void* d_out, int out_size)
{
    const float* x       = (const float*)d_in[0];
    const int*   ei      = (const int*)d_in[1];
    const float* conv1_w = (const float*)d_in[2];
    const float* conv1_b = (const float*)d_in[3];
    const float* conv2_w = (const float*)d_in[4];
    const float* conv2_b = (const float*)d_in[5];
    const float* sig_w   = (const float*)d_in[6];
    const float* sig_b   = (const float*)d_in[7];
    const float* fc1_w   = (const float*)d_in[8];
    const float* fc1_b   = (const float*)d_in[9];
    const float* fc2_w   = (const float*)d_in[10];
    const float* fc2_b   = (const float*)d_in[11];
    const float* fc3_w   = (const float*)d_in[12];
    const float* fc3_b   = (const float*)d_in[13];
    const float* fc4_w   = (const float*)d_in[14];
    const float* fc4_b   = (const float*)d_in[15];
    float*       out     = (float*)d_out;

    const int TB = 256;
    const int NSB = (NNODES + 1023) / 1024;   // 49 scan blocks
    k_init<<<(NNODES + TB - 1) / TB, TB>>>();
    k_deg_count<<<(NEDGES + TB - 1) / TB, TB>>>(ei);
    k_dinv<<<(NNODES + TB - 1) / TB, TB>>>();
    k_scan1<<<NSB, 1024>>>();
    k_scan2<<<1, 64>>>(NSB);
    k_scan3<<<NSB, 1024>>>();
    k_fill<<<(NEDGES + TB - 1) / TB, TB>>>(ei);
    k_agg1<<<NNODES, 256>>>(x);

    dim3 g256(2, (NNODES + 127) / 128);
    dim3 g128(1, (NNODES + 127) / 128);

    k_gemm<2, 256><<<g256, 256>>>(sig_w, sig_b);
    k_fcs<<<1, 256>>>(fc1_w, fc1_b, fc2_w, fc2_b, fc3_w, fc3_b, fc4_w, fc4_b);
    k_gemm<1, 256><<<g256, 256>>>(conv1_w, conv1_b);
    k_lnstats<<<NNODES, 256>>>();
    k_gemm<0, 128><<<g128, 256>>>(conv2_w, nullptr);
    k_agg2<<<NNODES, 128>>>(conv2_b, out);
}

// round 4
// speedup vs baseline: 1.3618x; 1.2304x over previous
#include <cuda_runtime.h>
#include <cuda_bf16.h>
#include <math.h>

#define NNODES 50000
#define NEDGES 800000

// ---------------- scratch ----------------
__device__ float g_deg[NNODES];
__device__ float g_dinv[NNODES];
__device__ int   g_count[NNODES];
__device__ int   g_fill[NNODES];
__device__ int   g_rowptr[NNODES + 1];
__device__ int   g_bsum[64];
__device__ int   g_boff[64];
__device__ int   g_csr_src[NEDGES];
__device__ float g_csr_w[NEDGES];
__device__ float g_xa[(size_t)NNODES * 256];
__device__ float g_h [(size_t)NNODES * 256];
__device__ float g_h2[(size_t)NNODES * 128];
__device__ float g_mu[NNODES], g_rstd[NNODES];
__device__ float g_s[256];
__device__ float g_gamma1[256], g_beta1[256];
__device__ float g_gamma2[128], g_beta2[128];

// ---------------- init ----------------
__global__ void k_init()
{
    int i = blockIdx.x * blockDim.x + threadIdx.x;
    if (i < NNODES) {
        g_deg[i] = 1.0f;
        g_count[i] = 0;
        g_fill[i] = 0;
    }
    if (i < 256) g_s[i] = 0.0f;
}

__global__ void k_deg_count(const int* __restrict__ ei)
{
    int e = blockIdx.x * blockDim.x + threadIdx.x;
    if (e < NEDGES) {
        atomicAdd(&g_deg[ei[e]], 1.0f);
        atomicAdd(&g_count[ei[NEDGES + e]], 1);
    }
}

// ---------------- scan stage 1 (+ dinv fused) ----------------
__global__ void k_scan1()
{
    __shared__ int sh[1024];
    int t = threadIdx.x;
    int i = blockIdx.x * 1024 + t;
    if (i < NNODES) g_dinv[i] = rsqrtf(g_deg[i]);
    int v = (i < NNODES) ? g_count[i] : 0;
    sh[t] = v;
    __syncthreads();
#pragma unroll
    for (int ofs = 1; ofs < 1024; ofs <<= 1) {
        int a = (t >= ofs) ? sh[t - ofs] : 0;
        __syncthreads();
        sh[t] += a;
        __syncthreads();
    }
    if (i < NNODES) g_rowptr[i] = sh[t] - v;   // block-local exclusive
    if (t == 1023) g_bsum[blockIdx.x] = sh[1023];
}

__global__ void k_scan2(int nblk)
{
    __shared__ int sh[64];
    int t = threadIdx.x;
    int v = (t < nblk) ? g_bsum[t] : 0;
    sh[t] = v;
    __syncthreads();
#pragma unroll
    for (int ofs = 1; ofs < 64; ofs <<= 1) {
        int a = (t >= ofs) ? sh[t - ofs] : 0;
        __syncthreads();
        sh[t] += a;
        __syncthreads();
    }
    g_boff[t] = sh[t] - v;   // exclusive block offsets
}

__device__ __forceinline__ int row_beg(int d) { return g_rowptr[d] + g_boff[d >> 10]; }
__device__ __forceinline__ int row_end(int d) {
    return (d + 1 == NNODES) ? NEDGES : g_rowptr[d + 1] + g_boff[(d + 1) >> 10];
}

// ---------------- CSR fill ----------------
__global__ void k_fill(const int* __restrict__ ei)
{
    int e = blockIdx.x * blockDim.x + threadIdx.x;
    if (e < NEDGES) {
        int s = ei[e];
        int d = ei[NEDGES + e];
        int p = g_rowptr[d] + g_boff[d >> 10] + atomicAdd(&g_fill[d], 1);
        g_csr_src[p] = s;
        g_csr_w[p] = g_dinv[s] * g_dinv[d];
    }
}

// ---------------- xa = A @ x  (64 threads/node, float4 lanes) ----------------
__global__ void __launch_bounds__(256) k_agg1(const float* __restrict__ x)
{
    int grp  = threadIdx.x >> 6;       // 0..3
    int lane = threadIdx.x & 63;       // 0..63
    int d = blockIdx.x * 4 + grp;
    int c = lane * 4;
    float dv = g_dinv[d];
    float w0 = dv * dv;
    float4 v = *(const float4*)&x[(size_t)d * 256 + c];
    float4 acc = make_float4(w0 * v.x, w0 * v.y, w0 * v.z, w0 * v.w);
    int beg = row_beg(d), end = row_end(d);
    int j = beg;
    for (; j + 2 <= end; j += 2) {
        int s0 = g_csr_src[j], s1 = g_csr_src[j + 1];
        float wa = g_csr_w[j], wb = g_csr_w[j + 1];
        float4 a = *(const float4*)&x[(size_t)s0 * 256 + c];
        float4 b = *(const float4*)&x[(size_t)s1 * 256 + c];
        acc.x += wa * a.x + wb * b.x;
        acc.y += wa * a.y + wb * b.y;
        acc.z += wa * a.z + wb * b.z;
        acc.w += wa * a.w + wb * b.w;
    }
    if (j < end) {
        float w = g_csr_w[j];
        float4 a = *(const float4*)&x[(size_t)g_csr_src[j] * 256 + c];
        acc.x += w * a.x; acc.y += w * a.y; acc.z += w * a.z; acc.w += w * a.w;
    }
    *(float4*)&g_xa[(size_t)d * 256 + c] = acc;
}

// ---------------- tiled SGEMM, conflict-free fragments ----------------
// MODE 0: A=LN(g_h), C=g_h2 (N=128)                 [conv2]
// MODE 1: A=g_xa,    C=g_h  (N=256, film+bias+relu) [conv1]
// MODE 2: A=g_xa, no C (N=256, bias+relu -> colsum) [sig]
template <int MODE, int NN>
__global__ void __launch_bounds__(256)
k_gemm(const float* __restrict__ B, const float* __restrict__ bias)
{
    const float* A = (MODE == 0) ? g_h : g_xa;
    __shared__ float As[16][132];
    __shared__ float Bs[16][128];
    const int bm = blockIdx.y * 128;
    const int bn = blockIdx.x * 128;
    const int tid = threadIdx.x;
    const int tx = tid & 15, ty = tid >> 4;

    float acc[2][4][2][4];   // [rowHalf][i][colHalf][j]
#pragma unroll
    for (int rh = 0; rh < 2; rh++)
#pragma unroll
        for (int i = 0; i < 4; i++)
#pragma unroll
            for (int ch = 0; ch < 2; ch++)
#pragma unroll
                for (int j = 0; j < 4; j++) acc[rh][i][ch][j] = 0.0f;

    const int arow = tid >> 2, akq = tid & 3;
    const int brow = tid >> 5, bcol = (tid & 31) * 4;

    float4 aereg[2], bereg[2];
    float mu0 = 0.f, rs0 = 0.f, mu1 = 0.f, rs1 = 0.f;

    {   // prologue tile k0=0
        int g0 = bm + arow, g1 = bm + arow + 64;
        aereg[0] = make_float4(0.f, 0.f, 0.f, 0.f);
        aereg[1] = make_float4(0.f, 0.f, 0.f, 0.f);
        if (g0 < NNODES) {
            aereg[0] = *(const float4*)&A[(size_t)g0 * 256 + akq * 4];
            if (MODE == 0) { mu0 = g_mu[g0]; rs0 = g_rstd[g0]; }
        }
        if (g1 < NNODES) {
            aereg[1] = *(const float4*)&A[(size_t)g1 * 256 + akq * 4];
            if (MODE == 0) { mu1 = g_mu[g1]; rs1 = g_rstd[g1]; }
        }
        bereg[0] = *(const float4*)&B[(size_t)(brow) * NN + bn + bcol];
        bereg[1] = *(const float4*)&B[(size_t)(brow + 8) * NN + bn + bcol];
    }

    for (int k0 = 0; k0 < 256; k0 += 16) {
        {
            float4 v0 = aereg[0], v1 = aereg[1];
            if (MODE == 0) {
                v0.x = (v0.x - mu0) * rs0; v0.y = (v0.y - mu0) * rs0;
                v0.z = (v0.z - mu0) * rs0; v0.w = (v0.w - mu0) * rs0;
                v1.x = (v1.x - mu1) * rs1; v1.y = (v1.y - mu1) * rs1;
                v1.z = (v1.z - mu1) * rs1; v1.w = (v1.w - mu1) * rs1;
            }
            As[akq * 4 + 0][arow] = v0.x;
            As[akq * 4 + 1][arow] = v0.y;
            As[akq * 4 + 2][arow] = v0.z;
            As[akq * 4 + 3][arow] = v0.w;
            As[akq * 4 + 0][arow + 64] = v1.x;
            As[akq * 4 + 1][arow + 64] = v1.y;
            As[akq * 4 + 2][arow + 64] = v1.z;
            As[akq * 4 + 3][arow + 64] = v1.w;
            *(float4*)&Bs[brow][bcol] = bereg[0];
            *(float4*)&Bs[brow + 8][bcol] = bereg[1];
        }
        __syncthreads();

        int kn = k0 + 16;
        if (kn < 256) {
            int g0 = bm + arow, g1 = bm + arow + 64;
            aereg[0] = make_float4(0.f, 0.f, 0.f, 0.f);
            aereg[1] = make_float4(0.f, 0.f, 0.f, 0.f);
            if (g0 < NNODES) aereg[0] = *(const float4*)&A[(size_t)g0 * 256 + kn + akq * 4];
            if (g1 < NNODES) aereg[1] = *(const float4*)&A[(size_t)g1 * 256 + kn + akq * 4];
            bereg[0] = *(const float4*)&B[(size_t)(kn + brow) * NN + bn + bcol];
            bereg[1] = *(const float4*)&B[(size_t)(kn + brow + 8) * NN + bn + bcol];
        }

#pragma unroll
        for (int kk = 0; kk < 16; kk++) {
            float4 a0 = *(const float4*)&As[kk][ty * 4];
            float4 a1 = *(const float4*)&As[kk][ty * 4 + 64];
            float4 b0 = *(const float4*)&Bs[kk][tx * 4];
            float4 b1 = *(const float4*)&Bs[kk][tx * 4 + 64];
            const float* ap0 = (const float*)&a0;
            const float* ap1 = (const float*)&a1;
            const float* bp0 = (const float*)&b0;
            const float* bp1 = (const float*)&b1;
#pragma unroll
            for (int i = 0; i < 4; i++) {
#pragma unroll
                for (int j = 0; j < 4; j++) {
                    acc[0][i][0][j] += ap0[i] * bp0[j];
                    acc[0][i][1][j] += ap0[i] * bp1[j];
                    acc[1][i][0][j] += ap1[i] * bp0[j];
                    acc[1][i][1][j] += ap1[i] * bp1[j];
                }
            }
        }
        __syncthreads();
    }

    if (MODE == 0) {
#pragma unroll
        for (int rh = 0; rh < 2; rh++)
#pragma unroll
            for (int i = 0; i < 4; i++) {
                int r = bm + rh * 64 + ty * 4 + i;
                if (r < NNODES) {
#pragma unroll
                    for (int ch = 0; ch < 2; ch++) {
                        float4 o = make_float4(acc[rh][i][ch][0], acc[rh][i][ch][1],
                                               acc[rh][i][ch][2], acc[rh][i][ch][3]);
                        *(float4*)&g_h2[(size_t)r * 128 + bn + ch * 64 + tx * 4] = o;
                    }
                }
            }
    }
    if (MODE == 1) {
        float ga[2][4], be[2][4];
#pragma unroll
        for (int ch = 0; ch < 2; ch++)
#pragma unroll
            for (int j = 0; j < 4; j++) {
                int c = bn + ch * 64 + tx * 4 + j;
                ga[ch][j] = g_gamma1[c];
                be[ch][j] = g_beta1[c] + bias[c];
            }
#pragma unroll
        for (int rh = 0; rh < 2; rh++)
#pragma unroll
            for (int i = 0; i < 4; i++) {
                int r = bm + rh * 64 + ty * 4 + i;
                if (r < NNODES) {
#pragma unroll
                    for (int ch = 0; ch < 2; ch++) {
                        float4 o;
                        o.x = fmaxf(ga[ch][0] * acc[rh][i][ch][0] + be[ch][0], 0.f);
                        o.y = fmaxf(ga[ch][1] * acc[rh][i][ch][1] + be[ch][1], 0.f);
                        o.z = fmaxf(ga[ch][2] * acc[rh][i][ch][2] + be[ch][2], 0.f);
                        o.w = fmaxf(ga[ch][3] * acc[rh][i][ch][3] + be[ch][3], 0.f);
                        *(float4*)&g_h[(size_t)r * 256 + bn + ch * 64 + tx * 4] = o;
                    }
                }
            }
    }
    if (MODE == 2) {
        __shared__ float red[16][128];
#pragma unroll
        for (int ch = 0; ch < 2; ch++)
#pragma unroll
            for (int j = 0; j < 4; j++) {
                int cc = ch * 64 + tx * 4 + j;
                float bb = bias[bn + cc];
                float p = 0.f;
#pragma unroll
                for (int rh = 0; rh < 2; rh++)
#pragma unroll
                    for (int i = 0; i < 4; i++) {
                        int r = bm + rh * 64 + ty * 4 + i;
                        if (r < NNODES) p += fmaxf(acc[rh][i][ch][j] + bb, 0.f);
                    }
                red[ty][cc] = p;
            }
        __syncthreads();
        if (tid < 128) {
            float s = 0.f;
#pragma unroll
            for (int t = 0; t < 16; t++) s += red[t][tid];
            atomicAdd(&g_s[bn + tid], s);
        }
    }
}

// ---------------- tiny FC heads ----------------
__global__ void k_fcs(const float* __restrict__ fc1_w, const float* __restrict__ fc1_b,
                      const float* __restrict__ fc2_w, const float* __restrict__ fc2_b,
                      const float* __restrict__ fc3_w, const float* __restrict__ fc3_b,
                      const float* __restrict__ fc4_w, const float* __restrict__ fc4_b)
{
    __shared__ float sh_s[256];
    int t = threadIdx.x;
    sh_s[t] = g_s[t];
    __syncthreads();
    float a1 = fc1_b[t], a2 = fc2_b[t];
    float a3 = (t < 128) ? fc3_b[t] : 0.f;
    float a4 = (t < 128) ? fc4_b[t] : 0.f;
    for (int k = 0; k < 256; k++) {
        float sv = sh_s[k];
        a1 += fc1_w[t * 256 + k] * sv;
        a2 += fc2_w[t * 256 + k] * sv;
        if (t < 128) {
            a3 += fc3_w[t * 256 + k] * sv;
            a4 += fc4_w[t * 256 + k] * sv;
        }
    }
    g_gamma1[t] = tanhf(a1);
    g_beta1[t]  = tanhf(a2);
    if (t < 128) {
        g_gamma2[t] = tanhf(a3);
        g_beta2[t]  = tanhf(a4);
    }
}

// ---------------- LN-256 stats ----------------
__global__ void k_lnstats()
{
    int row = blockIdx.x;
    int t = threadIdx.x;
    float v = g_h[(size_t)row * 256 + t];
    float s1 = v, s2 = v * v;
#pragma unroll
    for (int o = 16; o; o >>= 1) {
        s1 += __shfl_xor_sync(0xffffffffu, s1, o);
        s2 += __shfl_xor_sync(0xffffffffu, s2, o);
    }
    __shared__ float shs[16];
    if ((t & 31) == 0) { shs[t >> 5] = s1; shs[8 + (t >> 5)] = s2; }
    __syncthreads();
    if (t == 0) {
        float a = 0.f, b = 0.f;
        for (int i = 0; i < 8; i++) { a += shs[i]; b += shs[8 + i]; }
        float mu = a * (1.0f / 256.0f);
        float var = b * (1.0f / 256.0f) - mu * mu;
        g_mu[row] = mu;
        g_rstd[row] = rsqrtf(var + 1e-5f);
    }
}

// ---------------- final: agg(h2) + film + LN (1 warp/node, float4) ----------------
__global__ void __launch_bounds__(256) k_agg2(const float* __restrict__ bias,
                                              float* __restrict__ out)
{
    int d = blockIdx.x * 8 + (threadIdx.x >> 5);
    int lane = threadIdx.x & 31;
    int c = lane * 4;
    float dv = g_dinv[d];
    float w0 = dv * dv;
    float4 v = *(const float4*)&g_h2[(size_t)d * 128 + c];
    float4 acc = make_float4(w0 * v.x, w0 * v.y, w0 * v.z, w0 * v.w);
    int beg = row_beg(d), end = row_end(d);
    int j = beg;
    for (; j + 2 <= end; j += 2) {
        int s0 = g_csr_src[j], s1 = g_csr_src[j + 1];
        float wa = g_csr_w[j], wb = g_csr_w[j + 1];
        float4 a = *(const float4*)&g_h2[(size_t)s0 * 128 + c];
        float4 b = *(const float4*)&g_h2[(size_t)s1 * 128 + c];
        acc.x += wa * a.x + wb * b.x;
        acc.y += wa * a.y + wb * b.y;
        acc.z += wa * a.z + wb * b.z;
        acc.w += wa * a.w + wb * b.w;
    }
    if (j < end) {
        float w = g_csr_w[j];
        float4 a = *(const float4*)&g_h2[(size_t)g_csr_src[j] * 128 + c];
        acc.x += w * a.x; acc.y += w * a.y; acc.z += w * a.z; acc.w += w * a.w;
    }
    float4 y;
    y.x = g_gamma2[c + 0] * acc.x + g_beta2[c + 0] + bias[c + 0];
    y.y = g_gamma2[c + 1] * acc.y + g_beta2[c + 1] + bias[c + 1];
    y.z = g_gamma2[c + 2] * acc.z + g_beta2[c + 2] + bias[c + 2];
    y.w = g_gamma2[c + 3] * acc.w + g_beta2[c + 3] + bias[c + 3];

    float s1 = y.x + y.y + y.z + y.w;
    float s2 = y.x * y.x + y.y * y.y + y.z * y.z + y.w * y.w;
#pragma unroll
    for (int o = 16; o; o >>= 1) {
        s1 += __shfl_xor_sync(0xffffffffu, s1, o);
        s2 += __shfl_xor_sync(0xffffffffu, s2, o);
    }
    float mu = s1 * (1.0f / 128.0f);
    float var = s2 * (1.0f / 128.0f) - mu * mu;
    float rstd = rsqrtf(var + 1e-5f);
    float4 o4;
    o4.x = (y.x - mu) * rstd;
    o4.y = (y.y - mu) * rstd;
    o4.z = (y.z - mu) * rstd;
    o4.w = (y.w - mu) * rstd;
    *(float4*)&out[(size_t)d * 128 + c] = o4;
}

// ---------------- launch ----------------
extern "C" void kernel_launch(void* const* d_in, const int* in_sizes, int n_in,
                              void* d_out, int out_size)
{
    const float* x       = (const float*)d_in[0];
    const int*   ei      = (const int*)d_in[1];
    const float* conv1_w = (const float*)d_in[2];
    const float* conv1_b = (const float*)d_in[3];
    const float* conv2_w = (const float*)d_in[4];
    const float* conv2_b = (const float*)d_in[5];
    const float* sig_w   = (const float*)d_in[6];
    const float* sig_b   = (const float*)d_in[7];
    const float* fc1_w   = (const float*)d_in[8];
    const float* fc1_b   = (const float*)d_in[9];
    const float* fc2_w   = (const float*)d_in[10];
    const float* fc2_b   = (const float*)d_in[11];
    const float* fc3_w   = (const float*)d_in[12];
    const float* fc3_b   = (const float*)d_in[13];
    const float* fc4_w   = (const float*)d_in[14];
    const float* fc4_b   = (const float*)d_in[15];
    float*       out     = (float*)d_out;

    const int TB = 256;
    const int NSB = (NNODES + 1023) / 1024;   // 49
    k_init<<<(NNODES + TB - 1) / TB, TB>>>();                 // 1
    k_deg_count<<<(NEDGES + TB - 1) / TB, TB>>>(ei);          // 2
    k_scan1<<<NSB, 1024>>>();                                 // 3 (incl. dinv)
    k_scan2<<<1, 64>>>(NSB);                                  // 4
    k_fill<<<(NEDGES + TB - 1) / TB, TB>>>(ei);               // 5
    k_agg1<<<NNODES / 4, 256>>>(x);                           // 6 <- ncu slot

    dim3 g256(2, (NNODES + 127) / 128);
    dim3 g128(1, (NNODES + 127) / 128);

    k_gemm<2, 256><<<g256, 256>>>(sig_w, sig_b);              // 7
    k_fcs<<<1, 256>>>(fc1_w, fc1_b, fc2_w, fc2_b, fc3_w, fc3_b, fc4_w, fc4_b); // 8
    k_gemm<1, 256><<<g256, 256>>>(conv1_w, conv1_b);          // 9
    k_lnstats<<<NNODES, 256>>>();                             // 10
    k_gemm<0, 128><<<g128, 256>>>(conv2_w, nullptr);          // 11
    k_agg2<<<NNODES / 8, 256>>>(conv2_b, out);                // 12
}

// round 5
// speedup vs baseline: 2.0966x; 1.5396x over previous
#include <cuda_runtime.h>
#include <cuda_bf16.h>
#include <math.h>

#define NNODES 50000
#define NEDGES 800000

// ---------------- scratch ----------------
__device__ float g_deg[NNODES];
__device__ float g_dinv[NNODES];
__device__ int   g_count[NNODES];
__device__ int   g_fill[NNODES];
__device__ int   g_rowptr[NNODES + 1];
__device__ int   g_bsum[64];
__device__ int   g_boff[64];
__device__ int   g_csr_src[NEDGES];
__device__ float g_csr_w[NEDGES];
__device__ float g_xa[(size_t)NNODES * 256];
__device__ float g_h [(size_t)NNODES * 256];
__device__ float g_h2[(size_t)NNODES * 128];
__device__ float g_mu[NNODES], g_rstd[NNODES];
__device__ float g_s[256];
__device__ float g_gamma1[256], g_beta1[256];
__device__ float g_gamma2[128], g_beta2[128];

__device__ __forceinline__ unsigned to_tf32(float f) {
    unsigned r; asm("cvt.rna.tf32.f32 %0, %1;" : "=r"(r) : "f"(f)); return r;
}
__device__ __forceinline__ uint4 cvt4(float4 v) {
    return make_uint4(to_tf32(v.x), to_tf32(v.y), to_tf32(v.z), to_tf32(v.w));
}
__device__ __forceinline__ void mma_tf32(float& c0, float& c1, float& c2, float& c3,
                                         unsigned a0, unsigned a1, unsigned a2, unsigned a3,
                                         unsigned b0, unsigned b1)
{
    asm("mma.sync.aligned.m16n8k8.row.col.f32.tf32.tf32.f32 "
        "{%0,%1,%2,%3},{%4,%5,%6,%7},{%8,%9},{%0,%1,%2,%3};"
        : "+f"(c0), "+f"(c1), "+f"(c2), "+f"(c3)
        : "r"(a0), "r"(a1), "r"(a2), "r"(a3), "r"(b0), "r"(b1));
}

// ---------------- init ----------------
__global__ void k_init()
{
    int i = blockIdx.x * blockDim.x + threadIdx.x;
    if (i < NNODES) {
        g_deg[i] = 1.0f;
        g_count[i] = 0;
        g_fill[i] = 0;
    }
    if (i < 256) g_s[i] = 0.0f;
}

__global__ void k_deg_count(const int* __restrict__ ei)
{
    int e = blockIdx.x * blockDim.x + threadIdx.x;
    if (e < NEDGES) {
        atomicAdd(&g_deg[ei[e]], 1.0f);
        atomicAdd(&g_count[ei[NEDGES + e]], 1);
    }
}

// ---------------- scan stage 1 (+ dinv fused) ----------------
__global__ void k_scan1()
{
    __shared__ int sh[1024];
    int t = threadIdx.x;
    int i = blockIdx.x * 1024 + t;
    if (i < NNODES) g_dinv[i] = rsqrtf(g_deg[i]);
    int v = (i < NNODES) ? g_count[i] : 0;
    sh[t] = v;
    __syncthreads();
#pragma unroll
    for (int ofs = 1; ofs < 1024; ofs <<= 1) {
        int a = (t >= ofs) ? sh[t - ofs] : 0;
        __syncthreads();
        sh[t] += a;
        __syncthreads();
    }
    if (i < NNODES) g_rowptr[i] = sh[t] - v;
    if (t == 1023) g_bsum[blockIdx.x] = sh[1023];
}

__global__ void k_scan2(int nblk)
{
    __shared__ int sh[64];
    int t = threadIdx.x;
    int v = (t < nblk) ? g_bsum[t] : 0;
    sh[t] = v;
    __syncthreads();
#pragma unroll
    for (int ofs = 1; ofs < 64; ofs <<= 1) {
        int a = (t >= ofs) ? sh[t - ofs] : 0;
        __syncthreads();
        sh[t] += a;
        __syncthreads();
    }
    g_boff[t] = sh[t] - v;
}

__device__ __forceinline__ int row_beg(int d) { return g_rowptr[d] + g_boff[d >> 10]; }
__device__ __forceinline__ int row_end(int d) {
    return (d + 1 == NNODES) ? NEDGES : g_rowptr[d + 1] + g_boff[(d + 1) >> 10];
}

// ---------------- CSR fill ----------------
__global__ void k_fill(const int* __restrict__ ei)
{
    int e = blockIdx.x * blockDim.x + threadIdx.x;
    if (e < NEDGES) {
        int s = ei[e];
        int d = ei[NEDGES + e];
        int p = g_rowptr[d] + g_boff[d >> 10] + atomicAdd(&g_fill[d], 1);
        g_csr_src[p] = s;
        g_csr_w[p] = g_dinv[s] * g_dinv[d];
    }
}

// ---------------- xa = A @ x ----------------
__global__ void __launch_bounds__(256) k_agg1(const float* __restrict__ x)
{
    int grp  = threadIdx.x >> 6;
    int lane = threadIdx.x & 63;
    int d = blockIdx.x * 4 + grp;
    int c = lane * 4;
    float dv = g_dinv[d];
    float w0 = dv * dv;
    float4 v = *(const float4*)&x[(size_t)d * 256 + c];
    float4 acc = make_float4(w0 * v.x, w0 * v.y, w0 * v.z, w0 * v.w);
    int beg = row_beg(d), end = row_end(d);
    int j = beg;
    for (; j + 2 <= end; j += 2) {
        int s0 = g_csr_src[j], s1 = g_csr_src[j + 1];
        float wa = g_csr_w[j], wb = g_csr_w[j + 1];
        float4 a = *(const float4*)&x[(size_t)s0 * 256 + c];
        float4 b = *(const float4*)&x[(size_t)s1 * 256 + c];
        acc.x += wa * a.x + wb * b.x;
        acc.y += wa * a.y + wb * b.y;
        acc.z += wa * a.z + wb * b.z;
        acc.w += wa * a.w + wb * b.w;
    }
    if (j < end) {
        float w = g_csr_w[j];
        float4 a = *(const float4*)&x[(size_t)g_csr_src[j] * 256 + c];
        acc.x += w * a.x; acc.y += w * a.y; acc.z += w * a.z; acc.w += w * a.w;
    }
    *(float4*)&g_xa[(size_t)d * 256 + c] = acc;
}

// ---------------- TF32 tensor-core GEMM ----------------
// MODE 0: A=LN(g_h), C=g_h2 (N=128)                 [conv2]
// MODE 1: A=g_xa,    C=g_h  (N=256, film+bias+relu) [conv1]
// MODE 2: A=g_xa, no C (N=256, bias+relu -> colsum) [sig]
template <int MODE, int NN>
__global__ void __launch_bounds__(256)
k_gemm(const float* __restrict__ B, const float* __restrict__ bias)
{
    const float* A = (MODE == 0) ? g_h : g_xa;
    __shared__ unsigned As[128][20];    // row-major [m][k], pad 20 -> conflict-free frags
    __shared__ unsigned Bs[16][136];    // [k][n], pad 136 -> conflict-free frags
    const int bm = blockIdx.y * 128;
    const int bn = blockIdx.x * 128;
    const int tid = threadIdx.x;

    const int wid = tid >> 5;
    const int wm = wid >> 2;        // 0..1  (m offset 64*wm)
    const int wn = wid & 3;         // 0..3  (n offset 32*wn)
    const int lane = tid & 31;
    const int gid = lane >> 2;      // 0..7
    const int tig = lane & 3;       // 0..3

    float acc[4][4][4];
#pragma unroll
    for (int mt = 0; mt < 4; mt++)
#pragma unroll
        for (int nt = 0; nt < 4; nt++)
#pragma unroll
            for (int r = 0; r < 4; r++) acc[mt][nt][r] = 0.0f;

    const int arow = tid >> 2, akq = tid & 3;
    const int brow = tid >> 5, bcol = (tid & 31) * 4;

    float4 aereg[2], bereg[2];
    float mu0 = 0.f, rs0 = 0.f, mu1 = 0.f, rs1 = 0.f;

    {   // prologue: tile k0=0
        int g0 = bm + arow, g1 = bm + arow + 64;
        aereg[0] = make_float4(0.f, 0.f, 0.f, 0.f);
        aereg[1] = make_float4(0.f, 0.f, 0.f, 0.f);
        if (g0 < NNODES) {
            aereg[0] = *(const float4*)&A[(size_t)g0 * 256 + akq * 4];
            if (MODE == 0) { mu0 = g_mu[g0]; rs0 = g_rstd[g0]; }
        }
        if (g1 < NNODES) {
            aereg[1] = *(const float4*)&A[(size_t)g1 * 256 + akq * 4];
            if (MODE == 0) { mu1 = g_mu[g1]; rs1 = g_rstd[g1]; }
        }
        bereg[0] = *(const float4*)&B[(size_t)(brow) * NN + bn + bcol];
        bereg[1] = *(const float4*)&B[(size_t)(brow + 8) * NN + bn + bcol];
    }

    for (int k0 = 0; k0 < 256; k0 += 16) {
        {   // stage with tf32 conversion (+ LN for MODE 0)
            float4 v0 = aereg[0], v1 = aereg[1];
            if (MODE == 0) {
                v0.x = (v0.x - mu0) * rs0; v0.y = (v0.y - mu0) * rs0;
                v0.z = (v0.z - mu0) * rs0; v0.w = (v0.w - mu0) * rs0;
                v1.x = (v1.x - mu1) * rs1; v1.y = (v1.y - mu1) * rs1;
                v1.z = (v1.z - mu1) * rs1; v1.w = (v1.w - mu1) * rs1;
            }
            *(uint4*)&As[arow][akq * 4]      = cvt4(v0);
            *(uint4*)&As[arow + 64][akq * 4] = cvt4(v1);
            *(uint4*)&Bs[brow][bcol]         = cvt4(bereg[0]);
            *(uint4*)&Bs[brow + 8][bcol]     = cvt4(bereg[1]);
        }
        __syncthreads();

        int kn = k0 + 16;
        if (kn < 256) {
            int g0 = bm + arow, g1 = bm + arow + 64;
            aereg[0] = make_float4(0.f, 0.f, 0.f, 0.f);
            aereg[1] = make_float4(0.f, 0.f, 0.f, 0.f);
            if (g0 < NNODES) aereg[0] = *(const float4*)&A[(size_t)g0 * 256 + kn + akq * 4];
            if (g1 < NNODES) aereg[1] = *(const float4*)&A[(size_t)g1 * 256 + kn + akq * 4];
            bereg[0] = *(const float4*)&B[(size_t)(kn + brow) * NN + bn + bcol];
            bereg[1] = *(const float4*)&B[(size_t)(kn + brow + 8) * NN + bn + bcol];
        }

#pragma unroll
        for (int kb = 0; kb < 16; kb += 8) {
            unsigned af[4][4], bf[4][2];
#pragma unroll
            for (int mt = 0; mt < 4; mt++) {
                int mr = wm * 64 + mt * 16 + gid;
                af[mt][0] = As[mr][kb + tig];
                af[mt][1] = As[mr + 8][kb + tig];
                af[mt][2] = As[mr][kb + tig + 4];
                af[mt][3] = As[mr + 8][kb + tig + 4];
            }
#pragma unroll
            for (int nt = 0; nt < 4; nt++) {
                int nc = wn * 32 + nt * 8 + gid;
                bf[nt][0] = Bs[kb + tig][nc];
                bf[nt][1] = Bs[kb + tig + 4][nc];
            }
#pragma unroll
            for (int mt = 0; mt < 4; mt++)
#pragma unroll
                for (int nt = 0; nt < 4; nt++)
                    mma_tf32(acc[mt][nt][0], acc[mt][nt][1], acc[mt][nt][2], acc[mt][nt][3],
                             af[mt][0], af[mt][1], af[mt][2], af[mt][3],
                             bf[nt][0], bf[nt][1]);
        }
        __syncthreads();
    }

    // ---------------- epilogues ----------------
    if (MODE == 0) {
#pragma unroll
        for (int mt = 0; mt < 4; mt++) {
            int r0 = bm + wm * 64 + mt * 16 + gid;
            int r1 = r0 + 8;
#pragma unroll
            for (int nt = 0; nt < 4; nt++) {
                int c = wn * 32 + nt * 8 + tig * 2;    // bn == 0 for NN=128
                if (r0 < NNODES) {
                    float2 o = make_float2(acc[mt][nt][0], acc[mt][nt][1]);
                    *(float2*)&g_h2[(size_t)r0 * 128 + c] = o;
                }
                if (r1 < NNODES) {
                    float2 o = make_float2(acc[mt][nt][2], acc[mt][nt][3]);
                    *(float2*)&g_h2[(size_t)r1 * 128 + c] = o;
                }
            }
        }
    }
    if (MODE == 1) {
        float ga[4][2], be[4][2];
#pragma unroll
        for (int nt = 0; nt < 4; nt++) {
            int c = bn + wn * 32 + nt * 8 + tig * 2;
            ga[nt][0] = g_gamma1[c];     be[nt][0] = g_beta1[c] + bias[c];
            ga[nt][1] = g_gamma1[c + 1]; be[nt][1] = g_beta1[c + 1] + bias[c + 1];
        }
#pragma unroll
        for (int mt = 0; mt < 4; mt++) {
            int r0 = bm + wm * 64 + mt * 16 + gid;
            int r1 = r0 + 8;
#pragma unroll
            for (int nt = 0; nt < 4; nt++) {
                int c = bn + wn * 32 + nt * 8 + tig * 2;
                if (r0 < NNODES) {
                    float2 o;
                    o.x = fmaxf(ga[nt][0] * acc[mt][nt][0] + be[nt][0], 0.f);
                    o.y = fmaxf(ga[nt][1] * acc[mt][nt][1] + be[nt][1], 0.f);
                    *(float2*)&g_h[(size_t)r0 * 256 + c] = o;
                }
                if (r1 < NNODES) {
                    float2 o;
                    o.x = fmaxf(ga[nt][0] * acc[mt][nt][2] + be[nt][0], 0.f);
                    o.y = fmaxf(ga[nt][1] * acc[mt][nt][3] + be[nt][1], 0.f);
                    *(float2*)&g_h[(size_t)r1 * 256 + c] = o;
                }
            }
        }
    }
    if (MODE == 2) {
#pragma unroll
        for (int nt = 0; nt < 4; nt++) {
            int c = bn + wn * 32 + nt * 8 + tig * 2;
            float b0 = bias[c], b1 = bias[c + 1];
            float p0 = 0.f, p1 = 0.f;
#pragma unroll
            for (int mt = 0; mt < 4; mt++) {
                int r0 = bm + wm * 64 + mt * 16 + gid;
                int r1 = r0 + 8;
                if (r0 < NNODES) {
                    p0 += fmaxf(acc[mt][nt][0] + b0, 0.f);
                    p1 += fmaxf(acc[mt][nt][1] + b1, 0.f);
                }
                if (r1 < NNODES) {
                    p0 += fmaxf(acc[mt][nt][2] + b0, 0.f);
                    p1 += fmaxf(acc[mt][nt][3] + b1, 0.f);
                }
            }
#pragma unroll
            for (int o = 4; o <= 16; o <<= 1) {
                p0 += __shfl_xor_sync(0xffffffffu, p0, o);
                p1 += __shfl_xor_sync(0xffffffffu, p1, o);
            }
            if (gid == 0) {
                atomicAdd(&g_s[c], p0);
                atomicAdd(&g_s[c + 1], p1);
            }
        }
    }
}

// ---------------- tiny FC heads ----------------
__global__ void k_fcs(const float* __restrict__ fc1_w, const float* __restrict__ fc1_b,
                      const float* __restrict__ fc2_w, const float* __restrict__ fc2_b,
                      const float* __restrict__ fc3_w, const float* __restrict__ fc3_b,
                      const float* __restrict__ fc4_w, const float* __restrict__ fc4_b)
{
    __shared__ float sh_s[256];
    int t = threadIdx.x;
    sh_s[t] = g_s[t];
    __syncthreads();
    float a1 = fc1_b[t], a2 = fc2_b[t];
    float a3 = (t < 128) ? fc3_b[t] : 0.f;
    float a4 = (t < 128) ? fc4_b[t] : 0.f;
    for (int k = 0; k < 256; k++) {
        float sv = sh_s[k];
        a1 += fc1_w[t * 256 + k] * sv;
        a2 += fc2_w[t * 256 + k] * sv;
        if (t < 128) {
            a3 += fc3_w[t * 256 + k] * sv;
            a4 += fc4_w[t * 256 + k] * sv;
        }
    }
    g_gamma1[t] = tanhf(a1);
    g_beta1[t]  = tanhf(a2);
    if (t < 128) {
        g_gamma2[t] = tanhf(a3);
        g_beta2[t]  = tanhf(a4);
    }
}

// ---------------- LN-256 stats ----------------
__global__ void k_lnstats()
{
    int row = blockIdx.x;
    int t = threadIdx.x;
    float v = g_h[(size_t)row * 256 + t];
    float s1 = v, s2 = v * v;
#pragma unroll
    for (int o = 16; o; o >>= 1) {
        s1 += __shfl_xor_sync(0xffffffffu, s1, o);
        s2 += __shfl_xor_sync(0xffffffffu, s2, o);
    }
    __shared__ float shs[16];
    if ((t & 31) == 0) { shs[t >> 5] = s1; shs[8 + (t >> 5)] = s2; }
    __syncthreads();
    if (t == 0) {
        float a = 0.f, b = 0.f;
        for (int i = 0; i < 8; i++) { a += shs[i]; b += shs[8 + i]; }
        float mu = a * (1.0f / 256.0f);
        float var = b * (1.0f / 256.0f) - mu * mu;
        g_mu[row] = mu;
        g_rstd[row] = rsqrtf(var + 1e-5f);
    }
}

// ---------------- final: agg(h2) + film + LN ----------------
__global__ void __launch_bounds__(256) k_agg2(const float* __restrict__ bias,
                                              float* __restrict__ out)
{
    int d = blockIdx.x * 8 + (threadIdx.x >> 5);
    int lane = threadIdx.x & 31;
    int c = lane * 4;
    float dv = g_dinv[d];
    float w0 = dv * dv;
    float4 v = *(const float4*)&g_h2[(size_t)d * 128 + c];
    float4 acc = make_float4(w0 * v.x, w0 * v.y, w0 * v.z, w0 * v.w);
    int beg = row_beg(d), end = row_end(d);
    int j = beg;
    for (; j + 2 <= end; j += 2) {
        int s0 = g_csr_src[j], s1 = g_csr_src[j + 1];
        float wa = g_csr_w[j], wb = g_csr_w[j + 1];
        float4 a = *(const float4*)&g_h2[(size_t)s0 * 128 + c];
        float4 b = *(const float4*)&g_h2[(size_t)s1 * 128 + c];
        acc.x += wa * a.x + wb * b.x;
        acc.y += wa * a.y + wb * b.y;
        acc.z += wa * a.z + wb * b.z;
        acc.w += wa * a.w + wb * b.w;
    }
    if (j < end) {
        float w = g_csr_w[j];
        float4 a = *(const float4*)&g_h2[(size_t)g_csr_src[j] * 128 + c];
        acc.x += w * a.x; acc.y += w * a.y; acc.z += w * a.z; acc.w += w * a.w;
    }
    float4 y;
    y.x = g_gamma2[c + 0] * acc.x + g_beta2[c + 0] + bias[c + 0];
    y.y = g_gamma2[c + 1] * acc.y + g_beta2[c + 1] + bias[c + 1];
    y.z = g_gamma2[c + 2] * acc.z + g_beta2[c + 2] + bias[c + 2];
    y.w = g_gamma2[c + 3] * acc.w + g_beta2[c + 3] + bias[c + 3];

    float s1 = y.x + y.y + y.z + y.w;
    float s2 = y.x * y.x + y.y * y.y + y.z * y.z + y.w * y.w;
#pragma unroll
    for (int o = 16; o; o >>= 1) {
        s1 += __shfl_xor_sync(0xffffffffu, s1, o);
        s2 += __shfl_xor_sync(0xffffffffu, s2, o);
    }
    float mu = s1 * (1.0f / 128.0f);
    float var = s2 * (1.0f / 128.0f) - mu * mu;
    float rstd = rsqrtf(var + 1e-5f);
    float4 o4;
    o4.x = (y.x - mu) * rstd;
    o4.y = (y.y - mu) * rstd;
    o4.z = (y.z - mu) * rstd;
    o4.w = (y.w - mu) * rstd;
    *(float4*)&out[(size_t)d * 128 + c] = o4;
}

// ---------------- launch ----------------
extern "C" void kernel_launch(void* const* d_in, const int* in_sizes, int n_in,
                              void* d_out, int out_size)
{
    const float* x       = (const float*)d_in[0];
    const int*   ei      = (const int*)d_in[1];
    const float* conv1_w = (const float*)d_in[2];
    const float* conv1_b = (const float*)d_in[3];
    const float* conv2_w = (const float*)d_in[4];
    const float* conv2_b = (const float*)d_in[5];
    const float* sig_w   = (const float*)d_in[6];
    const float* sig_b   = (const float*)d_in[7];
    const float* fc1_w   = (const float*)d_in[8];
    const float* fc1_b   = (const float*)d_in[9];
    const float* fc2_w   = (const float*)d_in[10];
    const float* fc2_b   = (const float*)d_in[11];
    const float* fc3_w   = (const float*)d_in[12];
    const float* fc3_b   = (const float*)d_in[13];
    const float* fc4_w   = (const float*)d_in[14];
    const float* fc4_b   = (const float*)d_in[15];
    float*       out     = (float*)d_out;

    const int TB = 256;
    const int NSB = (NNODES + 1023) / 1024;
    k_init<<<(NNODES + TB - 1) / TB, TB>>>();
    k_deg_count<<<(NEDGES + TB - 1) / TB, TB>>>(ei);
    k_scan1<<<NSB, 1024>>>();
    k_scan2<<<1, 64>>>(NSB);
    k_fill<<<(NEDGES + TB - 1) / TB, TB>>>(ei);
    k_agg1<<<NNODES / 4, 256>>>(x);

    dim3 g256(2, (NNODES + 127) / 128);
    dim3 g128(1, (NNODES + 127) / 128);

    k_gemm<2, 256><<<g256, 256>>>(sig_w, sig_b);
    k_fcs<<<1, 256>>>(fc1_w, fc1_b, fc2_w, fc2_b, fc3_w, fc3_b, fc4_w, fc4_b);
    k_gemm<1, 256><<<g256, 256>>>(conv1_w, conv1_b);
    k_lnstats<<<NNODES, 256>>>();
    k_gemm<0, 128><<<g128, 256>>>(conv2_w, nullptr);
    k_agg2<<<NNODES / 8, 256>>>(conv2_b, out);
}

// round 6
// speedup vs baseline: 2.2259x; 1.0617x over previous
#include <cuda_runtime.h>
#include <cuda_bf16.h>
#include <math.h>

#define NNODES 50000
#define NEDGES 800000

// ---------------- scratch ----------------
__device__ float g_deg[NNODES];
__device__ float g_dinv[NNODES];
__device__ int   g_count[NNODES];
__device__ int   g_fill[NNODES];
__device__ int   g_rowptr[NNODES + 1];
__device__ int   g_bsum[64];
__device__ int   g_boff[64];
__device__ int2  g_csr[NEDGES];              // packed {src, w}
__device__ float g_xa[(size_t)NNODES * 256];
__device__ float g_h [(size_t)NNODES * 256];
__device__ float g_h2[(size_t)NNODES * 128];
__device__ float g_ls1[NNODES], g_ls2[NNODES];   // LN row sums (from conv1 epilogue)
__device__ float g_s[256];
__device__ float g_gamma1[256], g_beta1[256];
__device__ float g_gamma2[128], g_beta2[128];

__device__ __forceinline__ unsigned to_tf32(float f) {
    unsigned r; asm("cvt.rna.tf32.f32 %0, %1;" : "=r"(r) : "f"(f)); return r;
}
__device__ __forceinline__ uint4 cvt4(float4 v) {
    return make_uint4(to_tf32(v.x), to_tf32(v.y), to_tf32(v.z), to_tf32(v.w));
}
__device__ __forceinline__ void mma_tf32(float& c0, float& c1, float& c2, float& c3,
                                         unsigned a0, unsigned a1, unsigned a2, unsigned a3,
                                         unsigned b0, unsigned b1)
{
    asm("mma.sync.aligned.m16n8k8.row.col.f32.tf32.tf32.f32 "
        "{%0,%1,%2,%3},{%4,%5,%6,%7},{%8,%9},{%0,%1,%2,%3};"
        : "+f"(c0), "+f"(c1), "+f"(c2), "+f"(c3)
        : "r"(a0), "r"(a1), "r"(a2), "r"(a3), "r"(b0), "r"(b1));
}

// ---------------- init ----------------
__global__ void k_init()
{
    int i = blockIdx.x * blockDim.x + threadIdx.x;
    if (i < NNODES) {
        g_deg[i] = 1.0f;
        g_count[i] = 0;
        g_fill[i] = 0;
        g_ls1[i] = 0.0f;
        g_ls2[i] = 0.0f;
    }
    if (i < 256) g_s[i] = 0.0f;
}

__global__ void k_deg_count(const int* __restrict__ ei)
{
    int e = blockIdx.x * blockDim.x + threadIdx.x;
    if (e < NEDGES) {
        atomicAdd(&g_deg[ei[e]], 1.0f);
        atomicAdd(&g_count[ei[NEDGES + e]], 1);
    }
}

// ---------------- scan (+ dinv fused) ----------------
__global__ void k_scan1()
{
    __shared__ int sh[1024];
    int t = threadIdx.x;
    int i = blockIdx.x * 1024 + t;
    if (i < NNODES) g_dinv[i] = rsqrtf(g_deg[i]);
    int v = (i < NNODES) ? g_count[i] : 0;
    sh[t] = v;
    __syncthreads();
#pragma unroll
    for (int ofs = 1; ofs < 1024; ofs <<= 1) {
        int a = (t >= ofs) ? sh[t - ofs] : 0;
        __syncthreads();
        sh[t] += a;
        __syncthreads();
    }
    if (i < NNODES) g_rowptr[i] = sh[t] - v;
    if (t == 1023) g_bsum[blockIdx.x] = sh[1023];
}

__global__ void k_scan2(int nblk)
{
    __shared__ int sh[64];
    int t = threadIdx.x;
    int v = (t < nblk) ? g_bsum[t] : 0;
    sh[t] = v;
    __syncthreads();
#pragma unroll
    for (int ofs = 1; ofs < 64; ofs <<= 1) {
        int a = (t >= ofs) ? sh[t - ofs] : 0;
        __syncthreads();
        sh[t] += a;
        __syncthreads();
    }
    g_boff[t] = sh[t] - v;
}

__device__ __forceinline__ int row_beg(int d) { return g_rowptr[d] + g_boff[d >> 10]; }
__device__ __forceinline__ int row_end(int d) {
    return (d + 1 == NNODES) ? NEDGES : g_rowptr[d + 1] + g_boff[(d + 1) >> 10];
}

// ---------------- CSR fill (packed) ----------------
__global__ void k_fill(const int* __restrict__ ei)
{
    int e = blockIdx.x * blockDim.x + threadIdx.x;
    if (e < NEDGES) {
        int s = ei[e];
        int d = ei[NEDGES + e];
        int p = g_rowptr[d] + g_boff[d >> 10] + atomicAdd(&g_fill[d], 1);
        float w = g_dinv[s] * g_dinv[d];
        g_csr[p] = make_int2(s, __float_as_int(w));
    }
}

// ---------------- xa = A @ x ----------------
__global__ void __launch_bounds__(256) k_agg1(const float* __restrict__ x)
{
    int grp  = threadIdx.x >> 6;
    int lane = threadIdx.x & 63;
    int d = blockIdx.x * 4 + grp;
    int c = lane * 4;
    float dv = g_dinv[d];
    float w0 = dv * dv;
    float4 v = *(const float4*)&x[(size_t)d * 256 + c];
    float4 acc = make_float4(w0 * v.x, w0 * v.y, w0 * v.z, w0 * v.w);
    int beg = row_beg(d), end = row_end(d);
    int j = beg;
    for (; j + 2 <= end; j += 2) {
        int2 e0 = g_csr[j], e1 = g_csr[j + 1];
        float wa = __int_as_float(e0.y), wb = __int_as_float(e1.y);
        float4 a = *(const float4*)&x[(size_t)e0.x * 256 + c];
        float4 b = *(const float4*)&x[(size_t)e1.x * 256 + c];
        acc.x += wa * a.x + wb * b.x;
        acc.y += wa * a.y + wb * b.y;
        acc.z += wa * a.z + wb * b.z;
        acc.w += wa * a.w + wb * b.w;
    }
    if (j < end) {
        int2 e0 = g_csr[j];
        float w = __int_as_float(e0.y);
        float4 a = *(const float4*)&x[(size_t)e0.x * 256 + c];
        acc.x += w * a.x; acc.y += w * a.y; acc.z += w * a.z; acc.w += w * a.w;
    }
    *(float4*)&g_xa[(size_t)d * 256 + c] = acc;
}

// ---------------- TF32 tensor-core GEMM (double-buffered) ----------------
// MODE 0: A=LN(g_h), C=g_h2 (N=128)                            [conv2]
// MODE 1: A=g_xa,    C=g_h  (N=256, film+bias+relu, LN stats)  [conv1]
// MODE 2: A=g_xa, no C (N=256, bias+relu -> colsum)            [sig]
template <int MODE, int NN>
__global__ void __launch_bounds__(256, 2)
k_gemm(const float* __restrict__ B, const float* __restrict__ bias)
{
    const float* A = (MODE == 0) ? g_h : g_xa;
    __shared__ unsigned As[2][128][20];
    __shared__ unsigned Bs[2][16][136];
    const int bm = blockIdx.y * 128;
    const int bn = blockIdx.x * 128;
    const int tid = threadIdx.x;

    const int wid = tid >> 5;
    const int wm = wid >> 2;
    const int wn = wid & 3;
    const int lane = tid & 31;
    const int gid = lane >> 2;
    const int tig = lane & 3;

    float acc[4][4][4];
#pragma unroll
    for (int mt = 0; mt < 4; mt++)
#pragma unroll
        for (int nt = 0; nt < 4; nt++)
#pragma unroll
            for (int r = 0; r < 4; r++) acc[mt][nt][r] = 0.0f;

    const int arow = tid >> 2, akq = tid & 3;
    const int brow = tid >> 5, bcol = (tid & 31) * 4;
    const int g0 = bm + arow, g1 = bm + arow + 64;
    const bool v0ok = (g0 < NNODES), v1ok = (g1 < NNODES);

    float4 aereg[2], bereg[2];
    float mu0 = 0.f, rs0 = 0.f, mu1 = 0.f, rs1 = 0.f;
    if (MODE == 0) {
        if (v0ok) {
            float s1 = g_ls1[g0], s2 = g_ls2[g0];
            mu0 = s1 * (1.0f / 256.0f);
            rs0 = rsqrtf(s2 * (1.0f / 256.0f) - mu0 * mu0 + 1e-5f);
        }
        if (v1ok) {
            float s1 = g_ls1[g1], s2 = g_ls2[g1];
            mu1 = s1 * (1.0f / 256.0f);
            rs1 = rsqrtf(s2 * (1.0f / 256.0f) - mu1 * mu1 + 1e-5f);
        }
    }

    auto load_tile = [&](int k0) {
        aereg[0] = make_float4(0.f, 0.f, 0.f, 0.f);
        aereg[1] = make_float4(0.f, 0.f, 0.f, 0.f);
        if (v0ok) aereg[0] = *(const float4*)&A[(size_t)g0 * 256 + k0 + akq * 4];
        if (v1ok) aereg[1] = *(const float4*)&A[(size_t)g1 * 256 + k0 + akq * 4];
        bereg[0] = *(const float4*)&B[(size_t)(k0 + brow) * NN + bn + bcol];
        bereg[1] = *(const float4*)&B[(size_t)(k0 + brow + 8) * NN + bn + bcol];
    };
    auto stage = [&](int buf) {
        float4 v0 = aereg[0], v1 = aereg[1];
        if (MODE == 0) {
            v0.x = (v0.x - mu0) * rs0; v0.y = (v0.y - mu0) * rs0;
            v0.z = (v0.z - mu0) * rs0; v0.w = (v0.w - mu0) * rs0;
            v1.x = (v1.x - mu1) * rs1; v1.y = (v1.y - mu1) * rs1;
            v1.z = (v1.z - mu1) * rs1; v1.w = (v1.w - mu1) * rs1;
        }
        *(uint4*)&As[buf][arow][akq * 4]      = cvt4(v0);
        *(uint4*)&As[buf][arow + 64][akq * 4] = cvt4(v1);
        *(uint4*)&Bs[buf][brow][bcol]         = cvt4(bereg[0]);
        *(uint4*)&Bs[buf][brow + 8][bcol]     = cvt4(bereg[1]);
    };

    load_tile(0);
    stage(0);
    load_tile(16);
    __syncthreads();

    const int NT = 256 / 16;
    for (int t = 0; t < NT; t++) {
        int cur = t & 1;
        if (t + 1 < NT) stage(cur ^ 1);            // regs hold tile t+1
        if (t + 2 < NT) load_tile((t + 2) * 16);   // prefetch t+2
#pragma unroll
        for (int kb = 0; kb < 16; kb += 8) {
            unsigned af[4][4], bf[4][2];
#pragma unroll
            for (int mt = 0; mt < 4; mt++) {
                int mr = wm * 64 + mt * 16 + gid;
                af[mt][0] = As[cur][mr][kb + tig];
                af[mt][1] = As[cur][mr + 8][kb + tig];
                af[mt][2] = As[cur][mr][kb + tig + 4];
                af[mt][3] = As[cur][mr + 8][kb + tig + 4];
            }
#pragma unroll
            for (int nt = 0; nt < 4; nt++) {
                int nc = wn * 32 + nt * 8 + gid;
                bf[nt][0] = Bs[cur][kb + tig][nc];
                bf[nt][1] = Bs[cur][kb + tig + 4][nc];
            }
#pragma unroll
            for (int mt = 0; mt < 4; mt++)
#pragma unroll
                for (int nt = 0; nt < 4; nt++)
                    mma_tf32(acc[mt][nt][0], acc[mt][nt][1], acc[mt][nt][2], acc[mt][nt][3],
                             af[mt][0], af[mt][1], af[mt][2], af[mt][3],
                             bf[nt][0], bf[nt][1]);
        }
        __syncthreads();
    }

    // ---------------- epilogues ----------------
    if (MODE == 0) {
#pragma unroll
        for (int mt = 0; mt < 4; mt++) {
            int r0 = bm + wm * 64 + mt * 16 + gid;
            int r1 = r0 + 8;
#pragma unroll
            for (int nt = 0; nt < 4; nt++) {
                int c = wn * 32 + nt * 8 + tig * 2;
                if (r0 < NNODES)
                    *(float2*)&g_h2[(size_t)r0 * 128 + c] =
                        make_float2(acc[mt][nt][0], acc[mt][nt][1]);
                if (r1 < NNODES)
                    *(float2*)&g_h2[(size_t)r1 * 128 + c] =
                        make_float2(acc[mt][nt][2], acc[mt][nt][3]);
            }
        }
    }
    if (MODE == 1) {
        float ga[4][2], be[4][2];
#pragma unroll
        for (int nt = 0; nt < 4; nt++) {
            int c = bn + wn * 32 + nt * 8 + tig * 2;
            ga[nt][0] = g_gamma1[c];     be[nt][0] = g_beta1[c] + bias[c];
            ga[nt][1] = g_gamma1[c + 1]; be[nt][1] = g_beta1[c + 1] + bias[c + 1];
        }
#pragma unroll
        for (int mt = 0; mt < 4; mt++) {
            int r0 = bm + wm * 64 + mt * 16 + gid;
            int r1 = r0 + 8;
            float s1a = 0.f, s2a = 0.f, s1b = 0.f, s2b = 0.f;
#pragma unroll
            for (int nt = 0; nt < 4; nt++) {
                int c = bn + wn * 32 + nt * 8 + tig * 2;
                float o0 = fmaxf(ga[nt][0] * acc[mt][nt][0] + be[nt][0], 0.f);
                float o1 = fmaxf(ga[nt][1] * acc[mt][nt][1] + be[nt][1], 0.f);
                float o2 = fmaxf(ga[nt][0] * acc[mt][nt][2] + be[nt][0], 0.f);
                float o3 = fmaxf(ga[nt][1] * acc[mt][nt][3] + be[nt][1], 0.f);
                if (r0 < NNODES) *(float2*)&g_h[(size_t)r0 * 256 + c] = make_float2(o0, o1);
                if (r1 < NNODES) *(float2*)&g_h[(size_t)r1 * 256 + c] = make_float2(o2, o3);
                s1a += o0 + o1;  s2a += o0 * o0 + o1 * o1;
                s1b += o2 + o3;  s2b += o2 * o2 + o3 * o3;
            }
            // reduce across tig lanes (xor 1, 2), then one atomic per row slice
            s1a += __shfl_xor_sync(0xffffffffu, s1a, 1);
            s1a += __shfl_xor_sync(0xffffffffu, s1a, 2);
            s2a += __shfl_xor_sync(0xffffffffu, s2a, 1);
            s2a += __shfl_xor_sync(0xffffffffu, s2a, 2);
            s1b += __shfl_xor_sync(0xffffffffu, s1b, 1);
            s1b += __shfl_xor_sync(0xffffffffu, s1b, 2);
            s2b += __shfl_xor_sync(0xffffffffu, s2b, 1);
            s2b += __shfl_xor_sync(0xffffffffu, s2b, 2);
            if (tig == 0) {
                if (r0 < NNODES) {
                    atomicAdd(&g_ls1[r0], s1a);
                    atomicAdd(&g_ls2[r0], s2a);
                }
                if (r1 < NNODES) {
                    atomicAdd(&g_ls1[r1], s1b);
                    atomicAdd(&g_ls2[r1], s2b);
                }
            }
        }
    }
    if (MODE == 2) {
#pragma unroll
        for (int nt = 0; nt < 4; nt++) {
            int c = bn + wn * 32 + nt * 8 + tig * 2;
            float b0 = bias[c], b1 = bias[c + 1];
            float p0 = 0.f, p1 = 0.f;
#pragma unroll
            for (int mt = 0; mt < 4; mt++) {
                int r0 = bm + wm * 64 + mt * 16 + gid;
                int r1 = r0 + 8;
                if (r0 < NNODES) {
                    p0 += fmaxf(acc[mt][nt][0] + b0, 0.f);
                    p1 += fmaxf(acc[mt][nt][1] + b1, 0.f);
                }
                if (r1 < NNODES) {
                    p0 += fmaxf(acc[mt][nt][2] + b0, 0.f);
                    p1 += fmaxf(acc[mt][nt][3] + b1, 0.f);
                }
            }
#pragma unroll
            for (int o = 4; o <= 16; o <<= 1) {
                p0 += __shfl_xor_sync(0xffffffffu, p0, o);
                p1 += __shfl_xor_sync(0xffffffffu, p1, o);
            }
            if (gid == 0) {
                atomicAdd(&g_s[c], p0);
                atomicAdd(&g_s[c + 1], p1);
            }
        }
    }
}

// ---------------- tiny FC heads ----------------
__global__ void k_fcs(const float* __restrict__ fc1_w, const float* __restrict__ fc1_b,
                      const float* __restrict__ fc2_w, const float* __restrict__ fc2_b,
                      const float* __restrict__ fc3_w, const float* __restrict__ fc3_b,
                      const float* __restrict__ fc4_w, const float* __restrict__ fc4_b)
{
    __shared__ float sh_s[256];
    int t = threadIdx.x;
    sh_s[t] = g_s[t];
    __syncthreads();
    float a1 = fc1_b[t], a2 = fc2_b[t];
    float a3 = (t < 128) ? fc3_b[t] : 0.f;
    float a4 = (t < 128) ? fc4_b[t] : 0.f;
    for (int k = 0; k < 256; k++) {
        float sv = sh_s[k];
        a1 += fc1_w[t * 256 + k] * sv;
        a2 += fc2_w[t * 256 + k] * sv;
        if (t < 128) {
            a3 += fc3_w[t * 256 + k] * sv;
            a4 += fc4_w[t * 256 + k] * sv;
        }
    }
    g_gamma1[t] = tanhf(a1);
    g_beta1[t]  = tanhf(a2);
    if (t < 128) {
        g_gamma2[t] = tanhf(a3);
        g_beta2[t]  = tanhf(a4);
    }
}

// ---------------- final: agg(h2) + film + LN ----------------
__global__ void __launch_bounds__(256) k_agg2(const float* __restrict__ bias,
                                              float* __restrict__ out)
{
    int d = blockIdx.x * 8 + (threadIdx.x >> 5);
    int lane = threadIdx.x & 31;
    int c = lane * 4;
    float dv = g_dinv[d];
    float w0 = dv * dv;
    float4 v = *(const float4*)&g_h2[(size_t)d * 128 + c];
    float4 acc = make_float4(w0 * v.x, w0 * v.y, w0 * v.z, w0 * v.w);
    int beg = row_beg(d), end = row_end(d);
    int j = beg;
    for (; j + 2 <= end; j += 2) {
        int2 e0 = g_csr[j], e1 = g_csr[j + 1];
        float wa = __int_as_float(e0.y), wb = __int_as_float(e1.y);
        float4 a = *(const float4*)&g_h2[(size_t)e0.x * 128 + c];
        float4 b = *(const float4*)&g_h2[(size_t)e1.x * 128 + c];
        acc.x += wa * a.x + wb * b.x;
        acc.y += wa * a.y + wb * b.y;
        acc.z += wa * a.z + wb * b.z;
        acc.w += wa * a.w + wb * b.w;
    }
    if (j < end) {
        int2 e0 = g_csr[j];
        float w = __int_as_float(e0.y);
        float4 a = *(const float4*)&g_h2[(size_t)e0.x * 128 + c];
        acc.x += w * a.x; acc.y += w * a.y; acc.z += w * a.z; acc.w += w * a.w;
    }
    float4 y;
    y.x = g_gamma2[c + 0] * acc.x + g_beta2[c + 0] + bias[c + 0];
    y.y = g_gamma2[c + 1] * acc.y + g_beta2[c + 1] + bias[c + 1];
    y.z = g_gamma2[c + 2] * acc.z + g_beta2[c + 2] + bias[c + 2];
    y.w = g_gamma2[c + 3] * acc.w + g_beta2[c + 3] + bias[c + 3];

    float s1 = y.x + y.y + y.z + y.w;
    float s2 = y.x * y.x + y.y * y.y + y.z * y.z + y.w * y.w;
#pragma unroll
    for (int o = 16; o; o >>= 1) {
        s1 += __shfl_xor_sync(0xffffffffu, s1, o);
        s2 += __shfl_xor_sync(0xffffffffu, s2, o);
    }
    float mu = s1 * (1.0f / 128.0f);
    float var = s2 * (1.0f / 128.0f) - mu * mu;
    float rstd = rsqrtf(var + 1e-5f);
    float4 o4;
    o4.x = (y.x - mu) * rstd;
    o4.y = (y.y - mu) * rstd;
    o4.z = (y.z - mu) * rstd;
    o4.w = (y.w - mu) * rstd;
    *(float4*)&out[(size_t)d * 128 + c] = o4;
}

// ---------------- launch ----------------
extern "C" void kernel_launch(void* const* d_in, const int* in_sizes, int n_in,
                              void* d_out, int out_size)
{
    const float* x       = (const float*)d_in[0];
    const int*   ei      = (const int*)d_in[1];
    const float* conv1_w = (const float*)d_in[2];
    const float* conv1_b = (const float*)d_in[3];
    const float* conv2_w = (const float*)d_in[4];
    const float* conv2_b = (const float*)d_in[5];
    const float* sig_w   = (const float*)d_in[6];
    const float* sig_b   = (const float*)d_in[7];
    const float* fc1_w   = (const float*)d_in[8];
    const float* fc1_b   = (const float*)d_in[9];
    const float* fc2_w   = (const float*)d_in[10];
    const float* fc2_b   = (const float*)d_in[11];
    const float* fc3_w   = (const float*)d_in[12];
    const float* fc3_b   = (const float*)d_in[13];
    const float* fc4_w   = (const float*)d_in[14];
    const float* fc4_b   = (const float*)d_in[15];
    float*       out     = (float*)d_out;

    const int TB = 256;
    const int NSB = (NNODES + 1023) / 1024;
    k_init<<<(NNODES + TB - 1) / TB, TB>>>();
    k_deg_count<<<(NEDGES + TB - 1) / TB, TB>>>(ei);
    k_scan1<<<NSB, 1024>>>();
    k_scan2<<<1, 64>>>(NSB);
    k_fill<<<(NEDGES + TB - 1) / TB, TB>>>(ei);
    k_agg1<<<NNODES / 4, 256>>>(x);

    dim3 g256(2, (NNODES + 127) / 128);
    dim3 g128(1, (NNODES + 127) / 128);

    k_gemm<2, 256><<<g256, 256>>>(sig_w, sig_b);
    k_fcs<<<1, 256>>>(fc1_w, fc1_b, fc2_w, fc2_b, fc3_w, fc3_b, fc4_w, fc4_b);
    k_gemm<1, 256><<<g256, 256>>>(conv1_w, conv1_b);
    k_gemm<0, 128><<<g128, 256>>>(conv2_w, nullptr);
    k_agg2<<<NNODES / 8, 256>>>(conv2_b, out);
}

// round 7
// speedup vs baseline: 2.3432x; 1.0527x over previous
#include <cuda_runtime.h>
#include <cuda_bf16.h>
#include <math.h>

#define NNODES 50000
#define NEDGES 800000
#define NSB ((NNODES + 1023) / 1024)

// ---------------- scratch (zero-initialized .bss; restored to zero each run) ---
__device__ int   g_degi[NNODES];             // src degree counts (zeroed at end)
__device__ int   g_count[NNODES];            // dst histogram     (zeroed at end)
__device__ int   g_fill[NNODES];             // fill cursors      (zeroed at end)
__device__ float g_ls1[NNODES], g_ls2[NNODES]; // LN row sums     (zeroed at end)
__device__ float g_s[256];                   // signature         (zeroed in sig kernel)
__device__ int   c_scan, c_sig;              // last-block counters (self-resetting)

__device__ float g_dinv[NNODES];
__device__ int   g_rowptr[NNODES + 1];
__device__ int   g_bsum[64];
__device__ int   g_boff[64];
__device__ int2  g_csr[NEDGES];
__device__ float g_xa[(size_t)NNODES * 256];
__device__ float g_h [(size_t)NNODES * 256];
__device__ float g_h2[(size_t)NNODES * 128];
__device__ float g_gamma1[256], g_beta1[256];
__device__ float g_gamma2[128], g_beta2[128];

__device__ __forceinline__ unsigned to_tf32(float f) {
    unsigned r; asm("cvt.rna.tf32.f32 %0, %1;" : "=r"(r) : "f"(f)); return r;
}
__device__ __forceinline__ uint4 cvt4(float4 v) {
    return make_uint4(to_tf32(v.x), to_tf32(v.y), to_tf32(v.z), to_tf32(v.w));
}
__device__ __forceinline__ void mma_tf32(float& c0, float& c1, float& c2, float& c3,
                                         unsigned a0, unsigned a1, unsigned a2, unsigned a3,
                                         unsigned b0, unsigned b1)
{
    asm("mma.sync.aligned.m16n8k8.row.col.f32.tf32.tf32.f32 "
        "{%0,%1,%2,%3},{%4,%5,%6,%7},{%8,%9},{%0,%1,%2,%3};"
        : "+f"(c0), "+f"(c1), "+f"(c2), "+f"(c3)
        : "r"(a0), "r"(a1), "r"(a2), "r"(a3), "r"(b0), "r"(b1));
}

// ---------------- degree + histogram ----------------
__global__ void k_deg_count(const int* __restrict__ ei)
{
    int e = blockIdx.x * blockDim.x + threadIdx.x;
    if (e < NEDGES) {
        atomicAdd(&g_degi[ei[e]], 1);
        atomicAdd(&g_count[ei[NEDGES + e]], 1);
    }
}

// ---------------- scan (local scan + dinv; last block reduces block sums) -----
__global__ void k_scan1()
{
    __shared__ int sh[1024];
    __shared__ bool isLast;
    int t = threadIdx.x;
    int i = blockIdx.x * 1024 + t;
    if (i < NNODES) g_dinv[i] = rsqrtf(1.0f + (float)g_degi[i]);
    int v = (i < NNODES) ? g_count[i] : 0;
    sh[t] = v;
    __syncthreads();
#pragma unroll
    for (int ofs = 1; ofs < 1024; ofs <<= 1) {
        int a = (t >= ofs) ? sh[t - ofs] : 0;
        __syncthreads();
        sh[t] += a;
        __syncthreads();
    }
    if (i < NNODES) g_rowptr[i] = sh[t] - v;   // block-local exclusive
    if (t == 1023) g_bsum[blockIdx.x] = sh[1023];

    __threadfence();
    if (t == 0) isLast = (atomicAdd(&c_scan, 1) == NSB - 1);
    __syncthreads();
    if (isLast) {
        // 64-wide exclusive scan of block sums (single warp pair, smem reuse)
        if (t < 64) {
            int bv = (t < NSB) ? g_bsum[t] : 0;
            sh[t] = bv;
        }
        __syncthreads();
        if (t < 64) {
            int acc = 0;
            for (int k = 0; k < t; k++) acc += sh[k];   // 64 elems, trivial
            g_boff[t] = acc;
        }
        if (t == 0) c_scan = 0;
    }
}

__device__ __forceinline__ int row_beg(int d) { return g_rowptr[d] + g_boff[d >> 10]; }
__device__ __forceinline__ int row_end(int d) {
    return (d + 1 == NNODES) ? NEDGES : g_rowptr[d + 1] + g_boff[(d + 1) >> 10];
}

// ---------------- CSR fill (packed) ----------------
__global__ void k_fill(const int* __restrict__ ei)
{
    int e = blockIdx.x * blockDim.x + threadIdx.x;
    if (e < NEDGES) {
        int s = ei[e];
        int d = ei[NEDGES + e];
        int p = g_rowptr[d] + g_boff[d >> 10] + atomicAdd(&g_fill[d], 1);
        float w = g_dinv[s] * g_dinv[d];
        g_csr[p] = make_int2(s, __float_as_int(w));
    }
}

// ---------------- xa = A @ x  (64 threads/node, 4-edge unroll) ----------------
__global__ void __launch_bounds__(256) k_agg1(const float* __restrict__ x)
{
    int grp  = threadIdx.x >> 6;
    int lane = threadIdx.x & 63;
    int d = blockIdx.x * 4 + grp;
    int c = lane * 4;
    float dv = g_dinv[d];
    float w0 = dv * dv;
    float4 v = *(const float4*)&x[(size_t)d * 256 + c];
    float4 acc = make_float4(w0 * v.x, w0 * v.y, w0 * v.z, w0 * v.w);
    int beg = row_beg(d), end = row_end(d);
    int j = beg;
    for (; j + 4 <= end; j += 4) {
        int2 e0 = g_csr[j],     e1 = g_csr[j + 1];
        int2 e2 = g_csr[j + 2], e3 = g_csr[j + 3];
        float wa = __int_as_float(e0.y), wb = __int_as_float(e1.y);
        float wc = __int_as_float(e2.y), wd = __int_as_float(e3.y);
        float4 a = *(const float4*)&x[(size_t)e0.x * 256 + c];
        float4 b = *(const float4*)&x[(size_t)e1.x * 256 + c];
        float4 cc = *(const float4*)&x[(size_t)e2.x * 256 + c];
        float4 dd = *(const float4*)&x[(size_t)e3.x * 256 + c];
        acc.x += wa * a.x + wb * b.x + wc * cc.x + wd * dd.x;
        acc.y += wa * a.y + wb * b.y + wc * cc.y + wd * dd.y;
        acc.z += wa * a.z + wb * b.z + wc * cc.z + wd * dd.z;
        acc.w += wa * a.w + wb * b.w + wc * cc.w + wd * dd.w;
    }
    for (; j < end; j++) {
        int2 e0 = g_csr[j];
        float w = __int_as_float(e0.y);
        float4 a = *(const float4*)&x[(size_t)e0.x * 256 + c];
        acc.x += w * a.x; acc.y += w * a.y; acc.z += w * a.z; acc.w += w * a.w;
    }
    *(float4*)&g_xa[(size_t)d * 256 + c] = acc;
}

// ---------------- TF32 tensor-core GEMM (double-buffered) ----------------
// MODE 0: A=LN(g_h), C=g_h2 (N=128)                            [conv2]
// MODE 1: A=g_xa,    C=g_h  (N=256, film+bias+relu, LN stats)  [conv1]
// MODE 2: A=g_xa, no C (N=256, bias+relu -> colsum, + FC heads)[sig]
template <int MODE, int NN>
__global__ void __launch_bounds__(256, 2)
k_gemm(const float* __restrict__ B, const float* __restrict__ bias,
       const float* __restrict__ fc1_w, const float* __restrict__ fc1_b,
       const float* __restrict__ fc2_w, const float* __restrict__ fc2_b,
       const float* __restrict__ fc3_w, const float* __restrict__ fc3_b,
       const float* __restrict__ fc4_w, const float* __restrict__ fc4_b)
{
    const float* A = (MODE == 0) ? g_h : g_xa;
    __shared__ unsigned As[2][128][20];
    __shared__ unsigned Bs[2][16][136];
    const int bm = blockIdx.y * 128;
    const int bn = blockIdx.x * 128;
    const int tid = threadIdx.x;

    const int wid = tid >> 5;
    const int wm = wid >> 2;
    const int wn = wid & 3;
    const int lane = tid & 31;
    const int gid = lane >> 2;
    const int tig = lane & 3;

    float acc[4][4][4];
#pragma unroll
    for (int mt = 0; mt < 4; mt++)
#pragma unroll
        for (int nt = 0; nt < 4; nt++)
#pragma unroll
            for (int r = 0; r < 4; r++) acc[mt][nt][r] = 0.0f;

    const int arow = tid >> 2, akq = tid & 3;
    const int brow = tid >> 5, bcol = (tid & 31) * 4;
    const int g0 = bm + arow, g1 = bm + arow + 64;
    const bool v0ok = (g0 < NNODES), v1ok = (g1 < NNODES);

    float4 aereg[2], bereg[2];
    float mu0 = 0.f, rs0 = 0.f, mu1 = 0.f, rs1 = 0.f;
    if (MODE == 0) {
        if (v0ok) {
            float s1 = g_ls1[g0], s2 = g_ls2[g0];
            mu0 = s1 * (1.0f / 256.0f);
            rs0 = rsqrtf(s2 * (1.0f / 256.0f) - mu0 * mu0 + 1e-5f);
        }
        if (v1ok) {
            float s1 = g_ls1[g1], s2 = g_ls2[g1];
            mu1 = s1 * (1.0f / 256.0f);
            rs1 = rsqrtf(s2 * (1.0f / 256.0f) - mu1 * mu1 + 1e-5f);
        }
    }

    auto load_tile = [&](int k0) {
        aereg[0] = make_float4(0.f, 0.f, 0.f, 0.f);
        aereg[1] = make_float4(0.f, 0.f, 0.f, 0.f);
        if (v0ok) aereg[0] = *(const float4*)&A[(size_t)g0 * 256 + k0 + akq * 4];
        if (v1ok) aereg[1] = *(const float4*)&A[(size_t)g1 * 256 + k0 + akq * 4];
        bereg[0] = *(const float4*)&B[(size_t)(k0 + brow) * NN + bn + bcol];
        bereg[1] = *(const float4*)&B[(size_t)(k0 + brow + 8) * NN + bn + bcol];
    };
    auto stage = [&](int buf) {
        float4 v0 = aereg[0], v1 = aereg[1];
        if (MODE == 0) {
            v0.x = (v0.x - mu0) * rs0; v0.y = (v0.y - mu0) * rs0;
            v0.z = (v0.z - mu0) * rs0; v0.w = (v0.w - mu0) * rs0;
            v1.x = (v1.x - mu1) * rs1; v1.y = (v1.y - mu1) * rs1;
            v1.z = (v1.z - mu1) * rs1; v1.w = (v1.w - mu1) * rs1;
        }
        *(uint4*)&As[buf][arow][akq * 4]      = cvt4(v0);
        *(uint4*)&As[buf][arow + 64][akq * 4] = cvt4(v1);
        *(uint4*)&Bs[buf][brow][bcol]         = cvt4(bereg[0]);
        *(uint4*)&Bs[buf][brow + 8][bcol]     = cvt4(bereg[1]);
    };

    load_tile(0);
    stage(0);
    load_tile(16);
    __syncthreads();

    const int NT = 256 / 16;
    for (int t = 0; t < NT; t++) {
        int cur = t & 1;
        if (t + 1 < NT) stage(cur ^ 1);
        if (t + 2 < NT) load_tile((t + 2) * 16);
#pragma unroll
        for (int kb = 0; kb < 16; kb += 8) {
            unsigned af[4][4], bf[4][2];
#pragma unroll
            for (int mt = 0; mt < 4; mt++) {
                int mr = wm * 64 + mt * 16 + gid;
                af[mt][0] = As[cur][mr][kb + tig];
                af[mt][1] = As[cur][mr + 8][kb + tig];
                af[mt][2] = As[cur][mr][kb + tig + 4];
                af[mt][3] = As[cur][mr + 8][kb + tig + 4];
            }
#pragma unroll
            for (int nt = 0; nt < 4; nt++) {
                int nc = wn * 32 + nt * 8 + gid;
                bf[nt][0] = Bs[cur][kb + tig][nc];
                bf[nt][1] = Bs[cur][kb + tig + 4][nc];
            }
#pragma unroll
            for (int mt = 0; mt < 4; mt++)
#pragma unroll
                for (int nt = 0; nt < 4; nt++)
                    mma_tf32(acc[mt][nt][0], acc[mt][nt][1], acc[mt][nt][2], acc[mt][nt][3],
                             af[mt][0], af[mt][1], af[mt][2], af[mt][3],
                             bf[nt][0], bf[nt][1]);
        }
        __syncthreads();
    }

    // ---------------- epilogues ----------------
    if (MODE == 0) {
#pragma unroll
        for (int mt = 0; mt < 4; mt++) {
            int r0 = bm + wm * 64 + mt * 16 + gid;
            int r1 = r0 + 8;
#pragma unroll
            for (int nt = 0; nt < 4; nt++) {
                int c = wn * 32 + nt * 8 + tig * 2;
                if (r0 < NNODES)
                    *(float2*)&g_h2[(size_t)r0 * 128 + c] =
                        make_float2(acc[mt][nt][0], acc[mt][nt][1]);
                if (r1 < NNODES)
                    *(float2*)&g_h2[(size_t)r1 * 128 + c] =
                        make_float2(acc[mt][nt][2], acc[mt][nt][3]);
            }
        }
    }
    if (MODE == 1) {
        float ga[4][2], be[4][2];
#pragma unroll
        for (int nt = 0; nt < 4; nt++) {
            int c = bn + wn * 32 + nt * 8 + tig * 2;
            ga[nt][0] = g_gamma1[c];     be[nt][0] = g_beta1[c] + bias[c];
            ga[nt][1] = g_gamma1[c + 1]; be[nt][1] = g_beta1[c + 1] + bias[c + 1];
        }
#pragma unroll
        for (int mt = 0; mt < 4; mt++) {
            int r0 = bm + wm * 64 + mt * 16 + gid;
            int r1 = r0 + 8;
            float s1a = 0.f, s2a = 0.f, s1b = 0.f, s2b = 0.f;
#pragma unroll
            for (int nt = 0; nt < 4; nt++) {
                int c = bn + wn * 32 + nt * 8 + tig * 2;
                float o0 = fmaxf(ga[nt][0] * acc[mt][nt][0] + be[nt][0], 0.f);
                float o1 = fmaxf(ga[nt][1] * acc[mt][nt][1] + be[nt][1], 0.f);
                float o2 = fmaxf(ga[nt][0] * acc[mt][nt][2] + be[nt][0], 0.f);
                float o3 = fmaxf(ga[nt][1] * acc[mt][nt][3] + be[nt][1], 0.f);
                if (r0 < NNODES) *(float2*)&g_h[(size_t)r0 * 256 + c] = make_float2(o0, o1);
                if (r1 < NNODES) *(float2*)&g_h[(size_t)r1 * 256 + c] = make_float2(o2, o3);
                s1a += o0 + o1;  s2a += o0 * o0 + o1 * o1;
                s1b += o2 + o3;  s2b += o2 * o2 + o3 * o3;
            }
            s1a += __shfl_xor_sync(0xffffffffu, s1a, 1);
            s1a += __shfl_xor_sync(0xffffffffu, s1a, 2);
            s2a += __shfl_xor_sync(0xffffffffu, s2a, 1);
            s2a += __shfl_xor_sync(0xffffffffu, s2a, 2);
            s1b += __shfl_xor_sync(0xffffffffu, s1b, 1);
            s1b += __shfl_xor_sync(0xffffffffu, s1b, 2);
            s2b += __shfl_xor_sync(0xffffffffu, s2b, 1);
            s2b += __shfl_xor_sync(0xffffffffu, s2b, 2);
            if (tig == 0) {
                if (r0 < NNODES) {
                    atomicAdd(&g_ls1[r0], s1a);
                    atomicAdd(&g_ls2[r0], s2a);
                }
                if (r1 < NNODES) {
                    atomicAdd(&g_ls1[r1], s1b);
                    atomicAdd(&g_ls2[r1], s2b);
                }
            }
        }
    }
    if (MODE == 2) {
#pragma unroll
        for (int nt = 0; nt < 4; nt++) {
            int c = bn + wn * 32 + nt * 8 + tig * 2;
            float b0 = bias[c], b1 = bias[c + 1];
            float p0 = 0.f, p1 = 0.f;
#pragma unroll
            for (int mt = 0; mt < 4; mt++) {
                int r0 = bm + wm * 64 + mt * 16 + gid;
                int r1 = r0 + 8;
                if (r0 < NNODES) {
                    p0 += fmaxf(acc[mt][nt][0] + b0, 0.f);
                    p1 += fmaxf(acc[mt][nt][1] + b1, 0.f);
                }
                if (r1 < NNODES) {
                    p0 += fmaxf(acc[mt][nt][2] + b0, 0.f);
                    p1 += fmaxf(acc[mt][nt][3] + b1, 0.f);
                }
            }
#pragma unroll
            for (int o = 4; o <= 16; o <<= 1) {
                p0 += __shfl_xor_sync(0xffffffffu, p0, o);
                p1 += __shfl_xor_sync(0xffffffffu, p1, o);
            }
            if (gid == 0) {
                atomicAdd(&g_s[c], p0);
                atomicAdd(&g_s[c + 1], p1);
            }
        }
        // ---- last block computes FC heads, zeroes g_s, resets counter ----
        __shared__ bool isLast;
        __shared__ float sh_s[256];
        __threadfence();
        if (tid == 0) isLast = (atomicAdd(&c_sig, 1) == 2 * 391 - 1);
        __syncthreads();
        if (isLast) {
            sh_s[tid] = g_s[tid];
            __syncthreads();
            float a1 = fc1_b[tid], a2 = fc2_b[tid];
            float a3 = (tid < 128) ? fc3_b[tid] : 0.f;
            float a4 = (tid < 128) ? fc4_b[tid] : 0.f;
            for (int k = 0; k < 256; k++) {
                float sv = sh_s[k];
                a1 += fc1_w[tid * 256 + k] * sv;
                a2 += fc2_w[tid * 256 + k] * sv;
                if (tid < 128) {
                    a3 += fc3_w[tid * 256 + k] * sv;
                    a4 += fc4_w[tid * 256 + k] * sv;
                }
            }
            g_gamma1[tid] = tanhf(a1);
            g_beta1[tid]  = tanhf(a2);
            if (tid < 128) {
                g_gamma2[tid] = tanhf(a3);
                g_beta2[tid]  = tanhf(a4);
            }
            g_s[tid] = 0.0f;
            if (tid == 0) c_sig = 0;
        }
    }
}

// ---------------- final: agg(h2) + film + LN; tail blocks clean scratch -------
__global__ void __launch_bounds__(256) k_agg2(const float* __restrict__ bias,
                                              float* __restrict__ out)
{
    if (blockIdx.x >= NNODES / 8) {
        // cleanup blocks: restore zero state for next graph replay
        int cb = blockIdx.x - NNODES / 8;
        int stride = 64 * 256;
        for (int i = cb * 256 + threadIdx.x; i < NNODES; i += stride) {
            g_degi[i] = 0;
            g_count[i] = 0;
            g_fill[i] = 0;
            g_ls1[i] = 0.0f;
            g_ls2[i] = 0.0f;
        }
        return;
    }
    int d = blockIdx.x * 8 + (threadIdx.x >> 5);
    int lane = threadIdx.x & 31;
    int c = lane * 4;
    float dv = g_dinv[d];
    float w0 = dv * dv;
    float4 v = *(const float4*)&g_h2[(size_t)d * 128 + c];
    float4 acc = make_float4(w0 * v.x, w0 * v.y, w0 * v.z, w0 * v.w);
    int beg = row_beg(d), end = row_end(d);
    int j = beg;
    for (; j + 4 <= end; j += 4) {
        int2 e0 = g_csr[j],     e1 = g_csr[j + 1];
        int2 e2 = g_csr[j + 2], e3 = g_csr[j + 3];
        float wa = __int_as_float(e0.y), wb = __int_as_float(e1.y);
        float wc = __int_as_float(e2.y), wd = __int_as_float(e3.y);
        float4 a = *(const float4*)&g_h2[(size_t)e0.x * 128 + c];
        float4 b = *(const float4*)&g_h2[(size_t)e1.x * 128 + c];
        float4 cc = *(const float4*)&g_h2[(size_t)e2.x * 128 + c];
        float4 dd = *(const float4*)&g_h2[(size_t)e3.x * 128 + c];
        acc.x += wa * a.x + wb * b.x + wc * cc.x + wd * dd.x;
        acc.y += wa * a.y + wb * b.y + wc * cc.y + wd * dd.y;
        acc.z += wa * a.z + wb * b.z + wc * cc.z + wd * dd.z;
        acc.w += wa * a.w + wb * b.w + wc * cc.w + wd * dd.w;
    }
    for (; j < end; j++) {
        int2 e0 = g_csr[j];
        float w = __int_as_float(e0.y);
        float4 a = *(const float4*)&g_h2[(size_t)e0.x * 128 + c];
        acc.x += w * a.x; acc.y += w * a.y; acc.z += w * a.z; acc.w += w * a.w;
    }
    float4 y;
    y.x = g_gamma2[c + 0] * acc.x + g_beta2[c + 0] + bias[c + 0];
    y.y = g_gamma2[c + 1] * acc.y + g_beta2[c + 1] + bias[c + 1];
    y.z = g_gamma2[c + 2] * acc.z + g_beta2[c + 2] + bias[c + 2];
    y.w = g_gamma2[c + 3] * acc.w + g_beta2[c + 3] + bias[c + 3];

    float s1 = y.x + y.y + y.z + y.w;
    float s2 = y.x * y.x + y.y * y.y + y.z * y.z + y.w * y.w;
#pragma unroll
    for (int o = 16; o; o >>= 1) {
        s1 += __shfl_xor_sync(0xffffffffu, s1, o);
        s2 += __shfl_xor_sync(0xffffffffu, s2, o);
    }
    float mu = s1 * (1.0f / 128.0f);
    float var = s2 * (1.0f / 128.0f) - mu * mu;
    float rstd = rsqrtf(var + 1e-5f);
    float4 o4;
    o4.x = (y.x - mu) * rstd;
    o4.y = (y.y - mu) * rstd;
    o4.z = (y.z - mu) * rstd;
    o4.w = (y.w - mu) * rstd;
    *(float4*)&out[(size_t)d * 128 + c] = o4;
}

// ---------------- launch ----------------
extern "C" void kernel_launch(void* const* d_in, const int* in_sizes, int n_in,
                              void* d_out, int out_size)
{
    const float* x       = (const float*)d_in[0];
    const int*   ei      = (const int*)d_in[1];
    const float* conv1_w = (const float*)d_in[2];
    const float* conv1_b = (const float*)d_in[3];
    const float* conv2_w = (const float*)d_in[4];
    const float* conv2_b = (const float*)d_in[5];
    const float* sig_w   = (const float*)d_in[6];
    const float* sig_b   = (const float*)d_in[7];
    const float* fc1_w   = (const float*)d_in[8];
    const float* fc1_b   = (const float*)d_in[9];
    const float* fc2_w   = (const float*)d_in[10];
    const float* fc2_b   = (const float*)d_in[11];
    const float* fc3_w   = (const float*)d_in[12];
    const float* fc3_b   = (const float*)d_in[13];
    const float* fc4_w   = (const float*)d_in[14];
    const float* fc4_b   = (const float*)d_in[15];
    float*       out     = (float*)d_out;

    const int TB = 256;
    k_deg_count<<<(NEDGES + TB - 1) / TB, TB>>>(ei);
    k_scan1<<<NSB, 1024>>>();
    k_fill<<<(NEDGES + TB - 1) / TB, TB>>>(ei);
    k_agg1<<<NNODES / 4, 256>>>(x);

    dim3 g256(2, (NNODES + 127) / 128);   // 2 x 391
    dim3 g128(1, (NNODES + 127) / 128);

    k_gemm<2, 256><<<g256, 256>>>(sig_w, sig_b,
                                  fc1_w, fc1_b, fc2_w, fc2_b,
                                  fc3_w, fc3_b, fc4_w, fc4_b);
    k_gemm<1, 256><<<g256, 256>>>(conv1_w, conv1_b,
                                  nullptr, nullptr, nullptr, nullptr,
                                  nullptr, nullptr, nullptr, nullptr);
    k_gemm<0, 128><<<g128, 256>>>(conv2_w, nullptr,
                                  nullptr, nullptr, nullptr, nullptr,
                                  nullptr, nullptr, nullptr, nullptr);
    k_agg2<<<NNODES / 8 + 64, 256>>>(conv2_b, out);
}

// round 9
// speedup vs baseline: 2.3945x; 1.0219x over previous
#include <cuda_runtime.h>
#include <cuda_fp16.h>
#include <math.h>

#define NNODES 50000
#define NEDGES 800000
#define NSB ((NNODES + 1023) / 1024)
#define NEB ((NEDGES + 255) / 256)           // edge blocks in deg_count
#define NCB ((NNODES * 256 / 8 + 255) / 256) // conversion blocks (8 elems/thread)

// ---------------- scratch (zero-initialized .bss; restored to zero each run) ---
__device__ int   g_degi[NNODES];
__device__ int   g_count[NNODES];
__device__ int   g_fill[NNODES];
__device__ float g_ls1[NNODES], g_ls2[NNODES];
__device__ float g_s[256];
__device__ int   c_scan, c_sig;

__device__ float g_dinv[NNODES];
__device__ int   g_rowptr[NNODES + 1];
__device__ int   g_bsum[64];
__device__ int   g_boff[64];
__device__ int2  g_csr[NEDGES];
__device__ __half g_xh[(size_t)NNODES * 256];    // fp16 copy of x (gather source)
__device__ float g_xa[(size_t)NNODES * 256];
__device__ float g_h [(size_t)NNODES * 256];
__device__ __half g_h2h[(size_t)NNODES * 128];   // conv2 output in fp16
__device__ float g_gamma1[256], g_beta1[256];
__device__ float g_gamma2[128], g_beta2[128];

// ---- bit casts (these intrinsics don't exist in cuda_fp16.h; define our own) --
__device__ __forceinline__ unsigned h2u(__half2 h) {
    union { __half2 h; unsigned u; } c; c.h = h; return c.u;
}
__device__ __forceinline__ __half2 u2h(unsigned u) {
    union { __half2 h; unsigned u; } c; c.u = u; return c.h;
}

__device__ __forceinline__ unsigned to_tf32(float f) {
    unsigned r; asm("cvt.rna.tf32.f32 %0, %1;" : "=r"(r) : "f"(f)); return r;
}
__device__ __forceinline__ uint4 cvt4(float4 v) {
    return make_uint4(to_tf32(v.x), to_tf32(v.y), to_tf32(v.z), to_tf32(v.w));
}
__device__ __forceinline__ void mma_tf32(float& c0, float& c1, float& c2, float& c3,
                                         unsigned a0, unsigned a1, unsigned a2, unsigned a3,
                                         unsigned b0, unsigned b1)
{
    asm("mma.sync.aligned.m16n8k8.row.col.f32.tf32.tf32.f32 "
        "{%0,%1,%2,%3},{%4,%5,%6,%7},{%8,%9},{%0,%1,%2,%3};"
        : "+f"(c0), "+f"(c1), "+f"(c2), "+f"(c3)
        : "r"(a0), "r"(a1), "r"(a2), "r"(a3), "r"(b0), "r"(b1));
}

// ---------------- degree + histogram + x->fp16 conversion (grid-split) --------
__global__ void k_deg_count(const int* __restrict__ ei, const float* __restrict__ x)
{
    if (blockIdx.x < NEB) {
        int e = blockIdx.x * 256 + threadIdx.x;
        if (e < NEDGES) {
            atomicAdd(&g_degi[ei[e]], 1);
            atomicAdd(&g_count[ei[NEDGES + e]], 1);
        }
        return;
    }
    size_t i = ((size_t)(blockIdx.x - NEB) * 256 + threadIdx.x) * 8;
    if (i < (size_t)NNODES * 256) {
        float4 a = *(const float4*)&x[i];
        float4 b = *(const float4*)&x[i + 4];
        uint4 o;
        o.x = h2u(__float22half2_rn(make_float2(a.x, a.y)));
        o.y = h2u(__float22half2_rn(make_float2(a.z, a.w)));
        o.z = h2u(__float22half2_rn(make_float2(b.x, b.y)));
        o.w = h2u(__float22half2_rn(make_float2(b.z, b.w)));
        *(uint4*)&g_xh[i] = o;
    }
}

// ---------------- scan (local scan + dinv; last block reduces block sums) -----
__global__ void k_scan1()
{
    __shared__ int sh[1024];
    __shared__ bool isLast;
    int t = threadIdx.x;
    int i = blockIdx.x * 1024 + t;
    if (i < NNODES) g_dinv[i] = rsqrtf(1.0f + (float)g_degi[i]);
    int v = (i < NNODES) ? g_count[i] : 0;
    sh[t] = v;
    __syncthreads();
#pragma unroll
    for (int ofs = 1; ofs < 1024; ofs <<= 1) {
        int a = (t >= ofs) ? sh[t - ofs] : 0;
        __syncthreads();
        sh[t] += a;
        __syncthreads();
    }
    if (i < NNODES) g_rowptr[i] = sh[t] - v;
    if (t == 1023) g_bsum[blockIdx.x] = sh[1023];

    __threadfence();
    if (t == 0) isLast = (atomicAdd(&c_scan, 1) == NSB - 1);
    __syncthreads();
    if (isLast) {
        if (t < 64) sh[t] = (t < NSB) ? g_bsum[t] : 0;
        __syncthreads();
        if (t < 64) {
            int acc = 0;
            for (int k = 0; k < t; k++) acc += sh[k];
            g_boff[t] = acc;
        }
        if (t == 0) c_scan = 0;
    }
}

__device__ __forceinline__ int row_beg(int d) { return g_rowptr[d] + g_boff[d >> 10]; }
__device__ __forceinline__ int row_end(int d) {
    return (d + 1 == NNODES) ? NEDGES : g_rowptr[d + 1] + g_boff[(d + 1) >> 10];
}

// ---------------- CSR fill (packed) ----------------
__global__ void k_fill(const int* __restrict__ ei)
{
    int e = blockIdx.x * blockDim.x + threadIdx.x;
    if (e < NEDGES) {
        int s = ei[e];
        int d = ei[NEDGES + e];
        int p = g_rowptr[d] + g_boff[d >> 10] + atomicAdd(&g_fill[d], 1);
        float w = g_dinv[s] * g_dinv[d];
        g_csr[p] = make_int2(s, __float_as_int(w));
    }
}

// ---------------- xa = A @ x  (1 warp/node, fp16 gather, 8 cols/lane) ---------
__global__ void __launch_bounds__(256) k_agg1(const float* __restrict__ x)
{
    int d = blockIdx.x * 8 + (threadIdx.x >> 5);
    int lane = threadIdx.x & 31;
    int c = lane * 8;
    float dv = g_dinv[d];
    float w0 = dv * dv;
    float acc[8];
    {
        float4 a = *(const float4*)&x[(size_t)d * 256 + c];
        float4 b = *(const float4*)&x[(size_t)d * 256 + c + 4];
        acc[0] = w0 * a.x; acc[1] = w0 * a.y; acc[2] = w0 * a.z; acc[3] = w0 * a.w;
        acc[4] = w0 * b.x; acc[5] = w0 * b.y; acc[6] = w0 * b.z; acc[7] = w0 * b.w;
    }
    int beg = row_beg(d), end = row_end(d);
    int j = beg;
    for (; j + 2 <= end; j += 2) {
        int2 e0 = g_csr[j], e1 = g_csr[j + 1];
        float wa = __int_as_float(e0.y), wb = __int_as_float(e1.y);
        uint4 ha = *(const uint4*)&g_xh[(size_t)e0.x * 256 + c];
        uint4 hb = *(const uint4*)&g_xh[(size_t)e1.x * 256 + c];
#pragma unroll
        for (int q = 0; q < 4; q++) {
            float2 fa = __half22float2(u2h(((const unsigned*)&ha)[q]));
            float2 fb = __half22float2(u2h(((const unsigned*)&hb)[q]));
            acc[2 * q]     += wa * fa.x + wb * fb.x;
            acc[2 * q + 1] += wa * fa.y + wb * fb.y;
        }
    }
    if (j < end) {
        int2 e0 = g_csr[j];
        float wa = __int_as_float(e0.y);
        uint4 ha = *(const uint4*)&g_xh[(size_t)e0.x * 256 + c];
#pragma unroll
        for (int q = 0; q < 4; q++) {
            float2 fa = __half22float2(u2h(((const unsigned*)&ha)[q]));
            acc[2 * q]     += wa * fa.x;
            acc[2 * q + 1] += wa * fa.y;
        }
    }
    *(float4*)&g_xa[(size_t)d * 256 + c]     = make_float4(acc[0], acc[1], acc[2], acc[3]);
    *(float4*)&g_xa[(size_t)d * 256 + c + 4] = make_float4(acc[4], acc[5], acc[6], acc[7]);
}

// ---------------- TF32 tensor-core GEMM (double-buffered) ----------------
// MODE 0: A=LN(g_h), C=g_h2h (N=128, half out)                 [conv2]
// MODE 1: A=g_xa,    C=g_h  (N=256, film+bias+relu, LN stats)  [conv1]
// MODE 2: A=g_xa, no C (N=256, bias+relu -> colsum, + FC heads)[sig]
template <int MODE, int NN>
__global__ void __launch_bounds__(256, 2)
k_gemm(const float* __restrict__ B, const float* __restrict__ bias,
       const float* __restrict__ fc1_w, const float* __restrict__ fc1_b,
       const float* __restrict__ fc2_w, const float* __restrict__ fc2_b,
       const float* __restrict__ fc3_w, const float* __restrict__ fc3_b,
       const float* __restrict__ fc4_w, const float* __restrict__ fc4_b)
{
    const float* A = (MODE == 0) ? g_h : g_xa;
    __shared__ unsigned As[2][128][20];
    __shared__ unsigned Bs[2][16][136];
    const int bm = blockIdx.y * 128;
    const int bn = blockIdx.x * 128;
    const int tid = threadIdx.x;

    const int wid = tid >> 5;
    const int wm = wid >> 2;
    const int wn = wid & 3;
    const int lane = tid & 31;
    const int gid = lane >> 2;
    const int tig = lane & 3;

    float acc[4][4][4];
#pragma unroll
    for (int mt = 0; mt < 4; mt++)
#pragma unroll
        for (int nt = 0; nt < 4; nt++)
#pragma unroll
            for (int r = 0; r < 4; r++) acc[mt][nt][r] = 0.0f;

    const int arow = tid >> 2, akq = tid & 3;
    const int brow = tid >> 5, bcol = (tid & 31) * 4;
    const int g0 = bm + arow, g1 = bm + arow + 64;
    const bool v0ok = (g0 < NNODES), v1ok = (g1 < NNODES);

    float4 aereg[2], bereg[2];
    float mu0 = 0.f, rs0 = 0.f, mu1 = 0.f, rs1 = 0.f;
    if (MODE == 0) {
        if (v0ok) {
            float s1 = g_ls1[g0], s2 = g_ls2[g0];
            mu0 = s1 * (1.0f / 256.0f);
            rs0 = rsqrtf(s2 * (1.0f / 256.0f) - mu0 * mu0 + 1e-5f);
        }
        if (v1ok) {
            float s1 = g_ls1[g1], s2 = g_ls2[g1];
            mu1 = s1 * (1.0f / 256.0f);
            rs1 = rsqrtf(s2 * (1.0f / 256.0f) - mu1 * mu1 + 1e-5f);
        }
    }

    auto load_tile = [&](int k0) {
        aereg[0] = make_float4(0.f, 0.f, 0.f, 0.f);
        aereg[1] = make_float4(0.f, 0.f, 0.f, 0.f);
        if (v0ok) aereg[0] = *(const float4*)&A[(size_t)g0 * 256 + k0 + akq * 4];
        if (v1ok) aereg[1] = *(const float4*)&A[(size_t)g1 * 256 + k0 + akq * 4];
        bereg[0] = *(const float4*)&B[(size_t)(k0 + brow) * NN + bn + bcol];
        bereg[1] = *(const float4*)&B[(size_t)(k0 + brow + 8) * NN + bn + bcol];
    };
    auto stage = [&](int buf) {
        float4 v0 = aereg[0], v1 = aereg[1];
        if (MODE == 0) {
            v0.x = (v0.x - mu0) * rs0; v0.y = (v0.y - mu0) * rs0;
            v0.z = (v0.z - mu0) * rs0; v0.w = (v0.w - mu0) * rs0;
            v1.x = (v1.x - mu1) * rs1; v1.y = (v1.y - mu1) * rs1;
            v1.z = (v1.z - mu1) * rs1; v1.w = (v1.w - mu1) * rs1;
        }
        *(uint4*)&As[buf][arow][akq * 4]      = cvt4(v0);
        *(uint4*)&As[buf][arow + 64][akq * 4] = cvt4(v1);
        *(uint4*)&Bs[buf][brow][bcol]         = cvt4(bereg[0]);
        *(uint4*)&Bs[buf][brow + 8][bcol]     = cvt4(bereg[1]);
    };

    load_tile(0);
    stage(0);
    load_tile(16);
    __syncthreads();

    const int NT = 256 / 16;
    for (int t = 0; t < NT; t++) {
        int cur = t & 1;
        if (t + 1 < NT) stage(cur ^ 1);
        if (t + 2 < NT) load_tile((t + 2) * 16);
#pragma unroll
        for (int kb = 0; kb < 16; kb += 8) {
            unsigned af[4][4], bf[4][2];
#pragma unroll
            for (int mt = 0; mt < 4; mt++) {
                int mr = wm * 64 + mt * 16 + gid;
                af[mt][0] = As[cur][mr][kb + tig];
                af[mt][1] = As[cur][mr + 8][kb + tig];
                af[mt][2] = As[cur][mr][kb + tig + 4];
                af[mt][3] = As[cur][mr + 8][kb + tig + 4];
            }
#pragma unroll
            for (int nt = 0; nt < 4; nt++) {
                int nc = wn * 32 + nt * 8 + gid;
                bf[nt][0] = Bs[cur][kb + tig][nc];
                bf[nt][1] = Bs[cur][kb + tig + 4][nc];
            }
#pragma unroll
            for (int mt = 0; mt < 4; mt++)
#pragma unroll
                for (int nt = 0; nt < 4; nt++)
                    mma_tf32(acc[mt][nt][0], acc[mt][nt][1], acc[mt][nt][2], acc[mt][nt][3],
                             af[mt][0], af[mt][1], af[mt][2], af[mt][3],
                             bf[nt][0], bf[nt][1]);
        }
        __syncthreads();
    }

    // ---------------- epilogues ----------------
    if (MODE == 0) {
#pragma unroll
        for (int mt = 0; mt < 4; mt++) {
            int r0 = bm + wm * 64 + mt * 16 + gid;
            int r1 = r0 + 8;
#pragma unroll
            for (int nt = 0; nt < 4; nt++) {
                int c = wn * 32 + nt * 8 + tig * 2;
                if (r0 < NNODES) {
                    __half2 o = __float22half2_rn(make_float2(acc[mt][nt][0], acc[mt][nt][1]));
                    *(__half2*)&g_h2h[(size_t)r0 * 128 + c] = o;
                }
                if (r1 < NNODES) {
                    __half2 o = __float22half2_rn(make_float2(acc[mt][nt][2], acc[mt][nt][3]));
                    *(__half2*)&g_h2h[(size_t)r1 * 128 + c] = o;
                }
            }
        }
    }
    if (MODE == 1) {
        float ga[4][2], be[4][2];
#pragma unroll
        for (int nt = 0; nt < 4; nt++) {
            int c = bn + wn * 32 + nt * 8 + tig * 2;
            ga[nt][0] = g_gamma1[c];     be[nt][0] = g_beta1[c] + bias[c];
            ga[nt][1] = g_gamma1[c + 1]; be[nt][1] = g_beta1[c + 1] + bias[c + 1];
        }
#pragma unroll
        for (int mt = 0; mt < 4; mt++) {
            int r0 = bm + wm * 64 + mt * 16 + gid;
            int r1 = r0 + 8;
            float s1a = 0.f, s2a = 0.f, s1b = 0.f, s2b = 0.f;
#pragma unroll
            for (int nt = 0; nt < 4; nt++) {
                int c = bn + wn * 32 + nt * 8 + tig * 2;
                float o0 = fmaxf(ga[nt][0] * acc[mt][nt][0] + be[nt][0], 0.f);
                float o1 = fmaxf(ga[nt][1] * acc[mt][nt][1] + be[nt][1], 0.f);
                float o2 = fmaxf(ga[nt][0] * acc[mt][nt][2] + be[nt][0], 0.f);
                float o3 = fmaxf(ga[nt][1] * acc[mt][nt][3] + be[nt][1], 0.f);
                if (r0 < NNODES) *(float2*)&g_h[(size_t)r0 * 256 + c] = make_float2(o0, o1);
                if (r1 < NNODES) *(float2*)&g_h[(size_t)r1 * 256 + c] = make_float2(o2, o3);
                s1a += o0 + o1;  s2a += o0 * o0 + o1 * o1;
                s1b += o2 + o3;  s2b += o2 * o2 + o3 * o3;
            }
            s1a += __shfl_xor_sync(0xffffffffu, s1a, 1);
            s1a += __shfl_xor_sync(0xffffffffu, s1a, 2);
            s2a += __shfl_xor_sync(0xffffffffu, s2a, 1);
            s2a += __shfl_xor_sync(0xffffffffu, s2a, 2);
            s1b += __shfl_xor_sync(0xffffffffu, s1b, 1);
            s1b += __shfl_xor_sync(0xffffffffu, s1b, 2);
            s2b += __shfl_xor_sync(0xffffffffu, s2b, 1);
            s2b += __shfl_xor_sync(0xffffffffu, s2b, 2);
            if (tig == 0) {
                if (r0 < NNODES) {
                    atomicAdd(&g_ls1[r0], s1a);
                    atomicAdd(&g_ls2[r0], s2a);
                }
                if (r1 < NNODES) {
                    atomicAdd(&g_ls1[r1], s1b);
                    atomicAdd(&g_ls2[r1], s2b);
                }
            }
        }
    }
    if (MODE == 2) {
#pragma unroll
        for (int nt = 0; nt < 4; nt++) {
            int c = bn + wn * 32 + nt * 8 + tig * 2;
            float b0 = bias[c], b1 = bias[c + 1];
            float p0 = 0.f, p1 = 0.f;
#pragma unroll
            for (int mt = 0; mt < 4; mt++) {
                int r0 = bm + wm * 64 + mt * 16 + gid;
                int r1 = r0 + 8;
                if (r0 < NNODES) {
                    p0 += fmaxf(acc[mt][nt][0] + b0, 0.f);
                    p1 += fmaxf(acc[mt][nt][1] + b1, 0.f);
                }
                if (r1 < NNODES) {
                    p0 += fmaxf(acc[mt][nt][2] + b0, 0.f);
                    p1 += fmaxf(acc[mt][nt][3] + b1, 0.f);
                }
            }
#pragma unroll
            for (int o = 4; o <= 16; o <<= 1) {
                p0 += __shfl_xor_sync(0xffffffffu, p0, o);
                p1 += __shfl_xor_sync(0xffffffffu, p1, o);
            }
            if (gid == 0) {
                atomicAdd(&g_s[c], p0);
                atomicAdd(&g_s[c + 1], p1);
            }
        }
        __shared__ bool isLast;
        __shared__ float sh_s[256];
        __threadfence();
        if (tid == 0) isLast = (atomicAdd(&c_sig, 1) == 2 * 391 - 1);
        __syncthreads();
        if (isLast) {
            sh_s[tid] = g_s[tid];
            __syncthreads();
            float a1 = fc1_b[tid], a2 = fc2_b[tid];
            float a3 = (tid < 128) ? fc3_b[tid] : 0.f;
            float a4 = (tid < 128) ? fc4_b[tid] : 0.f;
            for (int k = 0; k < 256; k++) {
                float sv = sh_s[k];
                a1 += fc1_w[tid * 256 + k] * sv;
                a2 += fc2_w[tid * 256 + k] * sv;
                if (tid < 128) {
                    a3 += fc3_w[tid * 256 + k] * sv;
                    a4 += fc4_w[tid * 256 + k] * sv;
                }
            }
            g_gamma1[tid] = tanhf(a1);
            g_beta1[tid]  = tanhf(a2);
            if (tid < 128) {
                g_gamma2[tid] = tanhf(a3);
                g_beta2[tid]  = tanhf(a4);
            }
            g_s[tid] = 0.0f;
            if (tid == 0) c_sig = 0;
        }
    }
}

// ---------------- final: agg(h2 fp16) + film + LN; tail blocks clean scratch --
__global__ void __launch_bounds__(256) k_agg2(const float* __restrict__ bias,
                                              float* __restrict__ out)
{
    if (blockIdx.x >= NNODES / 8) {
        int cb = blockIdx.x - NNODES / 8;
        int stride = 64 * 256;
        for (int i = cb * 256 + threadIdx.x; i < NNODES; i += stride) {
            g_degi[i] = 0;
            g_count[i] = 0;
            g_fill[i] = 0;
            g_ls1[i] = 0.0f;
            g_ls2[i] = 0.0f;
        }
        return;
    }
    int d = blockIdx.x * 8 + (threadIdx.x >> 5);
    int lane = threadIdx.x & 31;
    int c = lane * 4;
    float dv = g_dinv[d];
    float w0 = dv * dv;
    float4 acc;
    {
        uint2 hv = *(const uint2*)&g_h2h[(size_t)d * 128 + c];
        float2 f0 = __half22float2(u2h(hv.x));
        float2 f1 = __half22float2(u2h(hv.y));
        acc = make_float4(w0 * f0.x, w0 * f0.y, w0 * f1.x, w0 * f1.y);
    }
    int beg = row_beg(d), end = row_end(d);
    int j = beg;
    for (; j + 2 <= end; j += 2) {
        int2 e0 = g_csr[j], e1 = g_csr[j + 1];
        float wa = __int_as_float(e0.y), wb = __int_as_float(e1.y);
        uint2 ha = *(const uint2*)&g_h2h[(size_t)e0.x * 128 + c];
        uint2 hb = *(const uint2*)&g_h2h[(size_t)e1.x * 128 + c];
        float2 a0 = __half22float2(u2h(ha.x));
        float2 a1 = __half22float2(u2h(ha.y));
        float2 b0 = __half22float2(u2h(hb.x));
        float2 b1 = __half22float2(u2h(hb.y));
        acc.x += wa * a0.x + wb * b0.x;
        acc.y += wa * a0.y + wb * b0.y;
        acc.z += wa * a1.x + wb * b1.x;
        acc.w += wa * a1.y + wb * b1.y;
    }
    if (j < end) {
        int2 e0 = g_csr[j];
        float wa = __int_as_float(e0.y);
        uint2 ha = *(const uint2*)&g_h2h[(size_t)e0.x * 128 + c];
        float2 a0 = __half22float2(u2h(ha.x));
        float2 a1 = __half22float2(u2h(ha.y));
        acc.x += wa * a0.x; acc.y += wa * a0.y;
        acc.z += wa * a1.x; acc.w += wa * a1.y;
    }
    float4 y;
    y.x = g_gamma2[c + 0] * acc.x + g_beta2[c + 0] + bias[c + 0];
    y.y = g_gamma2[c + 1] * acc.y + g_beta2[c + 1] + bias[c + 1];
    y.z = g_gamma2[c + 2] * acc.z + g_beta2[c + 2] + bias[c + 2];
    y.w = g_gamma2[c + 3] * acc.w + g_beta2[c + 3] + bias[c + 3];

    float s1 = y.x + y.y + y.z + y.w;
    float s2 = y.x * y.x + y.y * y.y + y.z * y.z + y.w * y.w;
#pragma unroll
    for (int o = 16; o; o >>= 1) {
        s1 += __shfl_xor_sync(0xffffffffu, s1, o);
        s2 += __shfl_xor_sync(0xffffffffu, s2, o);
    }
    float mu = s1 * (1.0f / 128.0f);
    float var = s2 * (1.0f / 128.0f) - mu * mu;
    float rstd = rsqrtf(var + 1e-5f);
    float4 o4;
    o4.x = (y.x - mu) * rstd;
    o4.y = (y.y - mu) * rstd;
    o4.z = (y.z - mu) * rstd;
    o4.w = (y.w - mu) * rstd;
    *(float4*)&out[(size_t)d * 128 + c] = o4;
}

// ---------------- launch ----------------
extern "C" void kernel_launch(void* const* d_in, const int* in_sizes, int n_in,
                              void* d_out, int out_size)
{
    const float* x       = (const float*)d_in[0];
    const int*   ei      = (const int*)d_in[1];
    const float* conv1_w = (const float*)d_in[2];
    const float* conv1_b = (const float*)d_in[3];
    const float* conv2_w = (const float*)d_in[4];
    const float* conv2_b = (const float*)d_in[5];
    const float* sig_w   = (const float*)d_in[6];
    const float* sig_b   = (const float*)d_in[7];
    const float* fc1_w   = (const float*)d_in[8];
    const float* fc1_b   = (const float*)d_in[9];
    const float* fc2_w   = (const float*)d_in[10];
    const float* fc2_b   = (const float*)d_in[11];
    const float* fc3_w   = (const float*)d_in[12];
    const float* fc3_b   = (const float*)d_in[13];
    const float* fc4_w   = (const float*)d_in[14];
    const float* fc4_b   = (const float*)d_in[15];
    float*       out     = (float*)d_out;

    k_deg_count<<<NEB + NCB, 256>>>(ei, x);
    k_scan1<<<NSB, 1024>>>();
    k_fill<<<(NEDGES + 255) / 256, 256>>>(ei);
    k_agg1<<<NNODES / 8, 256>>>(x);

    dim3 g256(2, (NNODES + 127) / 128);
    dim3 g128(1, (NNODES + 127) / 128);

    k_gemm<2, 256><<<g256, 256>>>(sig_w, sig_b,
                                  fc1_w, fc1_b, fc2_w, fc2_b,
                                  fc3_w, fc3_b, fc4_w, fc4_b);
    k_gemm<1, 256><<<g256, 256>>>(conv1_w, conv1_b,
                                  nullptr, nullptr, nullptr, nullptr,
                                  nullptr, nullptr, nullptr, nullptr);
    k_gemm<0, 128><<<g128, 256>>>(conv2_w, nullptr,
                                  nullptr, nullptr, nullptr, nullptr,
                                  nullptr, nullptr, nullptr, nullptr);
    k_agg2<<<NNODES / 8 + 64, 256>>>(conv2_b, out);
}

// round 10
// speedup vs baseline: 2.7074x; 1.1307x over previous
#include <cuda_runtime.h>
#include <cuda_fp16.h>
#include <math.h>

#define NNODES 50000
#define NEDGES 800000
#define NSB ((NNODES + 1023) / 1024)
#define NEB ((NEDGES + 255) / 256)
#define NCB ((NNODES * 256 / 8 + 255) / 256)

// ---------------- scratch (zero-initialized .bss; restored each run) ----------
__device__ int   g_degi[NNODES];
__device__ int   g_count[NNODES];
__device__ int   g_fill[NNODES];
__device__ float g_ls1[NNODES], g_ls2[NNODES];
__device__ float g_s[256];
__device__ int   c_scan, c_sig;

__device__ float g_dinv[NNODES];
__device__ int   g_rowptr[NNODES + 1];
__device__ int   g_bsum[64];
__device__ int   g_boff[64];
__device__ int2  g_csr[NEDGES];
__device__ __half g_xh [(size_t)NNODES * 256];   // fp16 x      (gather source)
__device__ __half g_xah[(size_t)NNODES * 256];   // fp16 A@x    (GEMM A source)
__device__ __half g_hh [(size_t)NNODES * 256];   // fp16 conv1 out (pre-LN)
__device__ __half g_h2h[(size_t)NNODES * 128];   // fp16 conv2 out
__device__ float g_gamma1[256], g_beta1[256];
__device__ float g_gamma2[128], g_beta2[128];

// ---- bit helpers ----
__device__ __forceinline__ unsigned h2u(__half2 h) {
    union { __half2 h; unsigned u; } c; c.h = h; return c.u;
}
__device__ __forceinline__ __half2 u2h(unsigned u) {
    union { __half2 h; unsigned u; } c; c.u = u; return c.h;
}
__device__ __forceinline__ unsigned hpack(__half lo, __half hi) {
    return (unsigned)__half_as_ushort(lo) | ((unsigned)__half_as_ushort(hi) << 16);
}

__device__ __forceinline__ void mma_f16(float& c0, float& c1, float& c2, float& c3,
                                        unsigned a0, unsigned a1, unsigned a2, unsigned a3,
                                        unsigned b0, unsigned b1)
{
    asm("mma.sync.aligned.m16n8k16.row.col.f32.f16.f16.f32 "
        "{%0,%1,%2,%3},{%4,%5,%6,%7},{%8,%9},{%0,%1,%2,%3};"
        : "+f"(c0), "+f"(c1), "+f"(c2), "+f"(c3)
        : "r"(a0), "r"(a1), "r"(a2), "r"(a3), "r"(b0), "r"(b1));
}

// ---------------- degree + histogram + x->fp16 conversion (grid-split) --------
__global__ void k_deg_count(const int* __restrict__ ei, const float* __restrict__ x)
{
    if (blockIdx.x < NEB) {
        int e = blockIdx.x * 256 + threadIdx.x;
        if (e < NEDGES) {
            atomicAdd(&g_degi[ei[e]], 1);
            atomicAdd(&g_count[ei[NEDGES + e]], 1);
        }
        return;
    }
    size_t i = ((size_t)(blockIdx.x - NEB) * 256 + threadIdx.x) * 8;
    if (i < (size_t)NNODES * 256) {
        float4 a = *(const float4*)&x[i];
        float4 b = *(const float4*)&x[i + 4];
        uint4 o;
        o.x = h2u(__float22half2_rn(make_float2(a.x, a.y)));
        o.y = h2u(__float22half2_rn(make_float2(a.z, a.w)));
        o.z = h2u(__float22half2_rn(make_float2(b.x, b.y)));
        o.w = h2u(__float22half2_rn(make_float2(b.z, b.w)));
        *(uint4*)&g_xh[i] = o;
    }
}

// ---------------- scan ----------------
__global__ void k_scan1()
{
    __shared__ int sh[1024];
    __shared__ bool isLast;
    int t = threadIdx.x;
    int i = blockIdx.x * 1024 + t;
    if (i < NNODES) g_dinv[i] = rsqrtf(1.0f + (float)g_degi[i]);
    int v = (i < NNODES) ? g_count[i] : 0;
    sh[t] = v;
    __syncthreads();
#pragma unroll
    for (int ofs = 1; ofs < 1024; ofs <<= 1) {
        int a = (t >= ofs) ? sh[t - ofs] : 0;
        __syncthreads();
        sh[t] += a;
        __syncthreads();
    }
    if (i < NNODES) g_rowptr[i] = sh[t] - v;
    if (t == 1023) g_bsum[blockIdx.x] = sh[1023];

    __threadfence();
    if (t == 0) isLast = (atomicAdd(&c_scan, 1) == NSB - 1);
    __syncthreads();
    if (isLast) {
        if (t < 64) sh[t] = (t < NSB) ? g_bsum[t] : 0;
        __syncthreads();
        if (t < 64) {
            int acc = 0;
            for (int k = 0; k < t; k++) acc += sh[k];
            g_boff[t] = acc;
        }
        if (t == 0) c_scan = 0;
    }
}

__device__ __forceinline__ int row_beg(int d) { return g_rowptr[d] + g_boff[d >> 10]; }
__device__ __forceinline__ int row_end(int d) {
    return (d + 1 == NNODES) ? NEDGES : g_rowptr[d + 1] + g_boff[(d + 1) >> 10];
}

// ---------------- CSR fill ----------------
__global__ void k_fill(const int* __restrict__ ei)
{
    int e = blockIdx.x * blockDim.x + threadIdx.x;
    if (e < NEDGES) {
        int s = ei[e];
        int d = ei[NEDGES + e];
        int p = g_rowptr[d] + g_boff[d >> 10] + atomicAdd(&g_fill[d], 1);
        float w = g_dinv[s] * g_dinv[d];
        g_csr[p] = make_int2(s, __float_as_int(w));
    }
}

// ---------------- xa = A @ x  (1 warp/node, fp16 gather, fp16 out) ------------
__global__ void __launch_bounds__(256) k_agg1(const float* __restrict__ x)
{
    int d = blockIdx.x * 8 + (threadIdx.x >> 5);
    int lane = threadIdx.x & 31;
    int c = lane * 8;
    float dv = g_dinv[d];
    float w0 = dv * dv;
    float acc[8];
    {
        float4 a = *(const float4*)&x[(size_t)d * 256 + c];
        float4 b = *(const float4*)&x[(size_t)d * 256 + c + 4];
        acc[0] = w0 * a.x; acc[1] = w0 * a.y; acc[2] = w0 * a.z; acc[3] = w0 * a.w;
        acc[4] = w0 * b.x; acc[5] = w0 * b.y; acc[6] = w0 * b.z; acc[7] = w0 * b.w;
    }
    int beg = row_beg(d), end = row_end(d);
    int j = beg;
    for (; j + 2 <= end; j += 2) {
        int2 e0 = g_csr[j], e1 = g_csr[j + 1];
        float wa = __int_as_float(e0.y), wb = __int_as_float(e1.y);
        uint4 ha = *(const uint4*)&g_xh[(size_t)e0.x * 256 + c];
        uint4 hb = *(const uint4*)&g_xh[(size_t)e1.x * 256 + c];
#pragma unroll
        for (int q = 0; q < 4; q++) {
            float2 fa = __half22float2(u2h(((const unsigned*)&ha)[q]));
            float2 fb = __half22float2(u2h(((const unsigned*)&hb)[q]));
            acc[2 * q]     += wa * fa.x + wb * fb.x;
            acc[2 * q + 1] += wa * fa.y + wb * fb.y;
        }
    }
    if (j < end) {
        int2 e0 = g_csr[j];
        float wa = __int_as_float(e0.y);
        uint4 ha = *(const uint4*)&g_xh[(size_t)e0.x * 256 + c];
#pragma unroll
        for (int q = 0; q < 4; q++) {
            float2 fa = __half22float2(u2h(((const unsigned*)&ha)[q]));
            acc[2 * q]     += wa * fa.x;
            acc[2 * q + 1] += wa * fa.y;
        }
    }
    uint4 o;
    o.x = h2u(__float22half2_rn(make_float2(acc[0], acc[1])));
    o.y = h2u(__float22half2_rn(make_float2(acc[2], acc[3])));
    o.z = h2u(__float22half2_rn(make_float2(acc[4], acc[5])));
    o.w = h2u(__float22half2_rn(make_float2(acc[6], acc[7])));
    *(uint4*)&g_xah[(size_t)d * 256 + c] = o;
}

// ---------------- fp16 HMMA GEMM (double-buffered) ----------------
// MODE 0: A=LN(g_hh), C=g_h2h (N=128)                           [conv2]
// MODE 1: A=g_xah,    C=g_hh (N=256, film+bias+relu, LN stats)  [conv1]
// MODE 2: A=g_xah, no C (N=256, bias+relu -> colsum, + FC heads)[sig]
template <int MODE, int NN>
__global__ void __launch_bounds__(256, 2)
k_gemm(const float* __restrict__ B, const float* __restrict__ bias,
       const float* __restrict__ fc1_w, const float* __restrict__ fc1_b,
       const float* __restrict__ fc2_w, const float* __restrict__ fc2_b,
       const float* __restrict__ fc3_w, const float* __restrict__ fc3_b,
       const float* __restrict__ fc4_w, const float* __restrict__ fc4_b)
{
    const __half* Ah = (MODE == 0) ? g_hh : g_xah;
    __shared__ alignas(16) __half As[2][128][24];   // [m][k] pad 24 -> conflict-free frags
    __shared__ alignas(16) __half Bs[2][16][136];   // [k][n] pad 136
    const int bm = blockIdx.y * 128;
    const int bn = blockIdx.x * 128;
    const int tid = threadIdx.x;

    const int wid = tid >> 5;
    const int wm = wid >> 2;
    const int wn = wid & 3;
    const int lane = tid & 31;
    const int gid = lane >> 2;
    const int tig = lane & 3;

    float acc[4][4][4];
#pragma unroll
    for (int mt = 0; mt < 4; mt++)
#pragma unroll
        for (int nt = 0; nt < 4; nt++)
#pragma unroll
            for (int r = 0; r < 4; r++) acc[mt][nt][r] = 0.0f;

    // A staging: 256 threads, 1 row each handled by 2 threads (8 halves each)
    const int arow = tid >> 1, akh = tid & 1;
    const int ga = bm + arow;
    const bool gaok = (ga < NNODES);
    // B staging: 16 k-rows x 128 n; thread: row=tid>>4, two float4 quads
    const int brow = tid >> 4, bq = (tid & 15) * 4;

    uint4 areg;
    float4 breg0, breg1;
    float mu = 0.f, rs = 0.f;
    if (MODE == 0 && gaok) {
        float s1 = g_ls1[ga], s2 = g_ls2[ga];
        mu = s1 * (1.0f / 256.0f);
        rs = rsqrtf(s2 * (1.0f / 256.0f) - mu * mu + 1e-5f);
    }

    auto load_tile = [&](int k0) {
        areg = make_uint4(0, 0, 0, 0);
        if (gaok) areg = *(const uint4*)&Ah[(size_t)ga * 256 + k0 + akh * 8];
        breg0 = *(const float4*)&B[(size_t)(k0 + brow) * NN + bn + bq];
        breg1 = *(const float4*)&B[(size_t)(k0 + brow) * NN + bn + bq + 64];
    };
    auto stage = [&](int buf) {
        uint4 av = areg;
        if (MODE == 0) {
#pragma unroll
            for (int q = 0; q < 4; q++) {
                float2 f = __half22float2(u2h(((const unsigned*)&av)[q]));
                f.x = (f.x - mu) * rs;
                f.y = (f.y - mu) * rs;
                ((unsigned*)&av)[q] = h2u(__float22half2_rn(f));
            }
        }
        *(uint4*)&As[buf][arow][akh * 8] = av;
        uint2 b0, b1;
        b0.x = h2u(__float22half2_rn(make_float2(breg0.x, breg0.y)));
        b0.y = h2u(__float22half2_rn(make_float2(breg0.z, breg0.w)));
        b1.x = h2u(__float22half2_rn(make_float2(breg1.x, breg1.y)));
        b1.y = h2u(__float22half2_rn(make_float2(breg1.z, breg1.w)));
        *(uint2*)&Bs[buf][brow][bq]      = b0;
        *(uint2*)&Bs[buf][brow][bq + 64] = b1;
    };

    load_tile(0);
    stage(0);
    load_tile(16);
    __syncthreads();

    const int NT = 256 / 16;
    for (int t = 0; t < NT; t++) {
        int cur = t & 1;
        if (t + 1 < NT) stage(cur ^ 1);
        if (t + 2 < NT) load_tile((t + 2) * 16);

        unsigned af[4][4], bf[4][2];
#pragma unroll
        for (int mt = 0; mt < 4; mt++) {
            int mr = wm * 64 + mt * 16 + gid;
            af[mt][0] = *(const unsigned*)&As[cur][mr][tig * 2];
            af[mt][1] = *(const unsigned*)&As[cur][mr + 8][tig * 2];
            af[mt][2] = *(const unsigned*)&As[cur][mr][tig * 2 + 8];
            af[mt][3] = *(const unsigned*)&As[cur][mr + 8][tig * 2 + 8];
        }
#pragma unroll
        for (int nt = 0; nt < 4; nt++) {
            int nc = wn * 32 + nt * 8 + gid;
            bf[nt][0] = hpack(Bs[cur][tig * 2][nc],     Bs[cur][tig * 2 + 1][nc]);
            bf[nt][1] = hpack(Bs[cur][tig * 2 + 8][nc], Bs[cur][tig * 2 + 9][nc]);
        }
#pragma unroll
        for (int mt = 0; mt < 4; mt++)
#pragma unroll
            for (int nt = 0; nt < 4; nt++)
                mma_f16(acc[mt][nt][0], acc[mt][nt][1], acc[mt][nt][2], acc[mt][nt][3],
                        af[mt][0], af[mt][1], af[mt][2], af[mt][3],
                        bf[nt][0], bf[nt][1]);
        __syncthreads();
    }

    // ---------------- epilogues (same C fragment mapping as tf32 version) -----
    if (MODE == 0) {
#pragma unroll
        for (int mt = 0; mt < 4; mt++) {
            int r0 = bm + wm * 64 + mt * 16 + gid;
            int r1 = r0 + 8;
#pragma unroll
            for (int nt = 0; nt < 4; nt++) {
                int c = wn * 32 + nt * 8 + tig * 2;
                if (r0 < NNODES) {
                    __half2 o = __float22half2_rn(make_float2(acc[mt][nt][0], acc[mt][nt][1]));
                    *(__half2*)&g_h2h[(size_t)r0 * 128 + c] = o;
                }
                if (r1 < NNODES) {
                    __half2 o = __float22half2_rn(make_float2(acc[mt][nt][2], acc[mt][nt][3]));
                    *(__half2*)&g_h2h[(size_t)r1 * 128 + c] = o;
                }
            }
        }
    }
    if (MODE == 1) {
        float ga2[4][2], be[4][2];
#pragma unroll
        for (int nt = 0; nt < 4; nt++) {
            int c = bn + wn * 32 + nt * 8 + tig * 2;
            ga2[nt][0] = g_gamma1[c];     be[nt][0] = g_beta1[c] + bias[c];
            ga2[nt][1] = g_gamma1[c + 1]; be[nt][1] = g_beta1[c + 1] + bias[c + 1];
        }
#pragma unroll
        for (int mt = 0; mt < 4; mt++) {
            int r0 = bm + wm * 64 + mt * 16 + gid;
            int r1 = r0 + 8;
            float s1a = 0.f, s2a = 0.f, s1b = 0.f, s2b = 0.f;
#pragma unroll
            for (int nt = 0; nt < 4; nt++) {
                int c = bn + wn * 32 + nt * 8 + tig * 2;
                float o0 = fmaxf(ga2[nt][0] * acc[mt][nt][0] + be[nt][0], 0.f);
                float o1 = fmaxf(ga2[nt][1] * acc[mt][nt][1] + be[nt][1], 0.f);
                float o2 = fmaxf(ga2[nt][0] * acc[mt][nt][2] + be[nt][0], 0.f);
                float o3 = fmaxf(ga2[nt][1] * acc[mt][nt][3] + be[nt][1], 0.f);
                if (r0 < NNODES)
                    *(__half2*)&g_hh[(size_t)r0 * 256 + c] =
                        __float22half2_rn(make_float2(o0, o1));
                if (r1 < NNODES)
                    *(__half2*)&g_hh[(size_t)r1 * 256 + c] =
                        __float22half2_rn(make_float2(o2, o3));
                s1a += o0 + o1;  s2a += o0 * o0 + o1 * o1;
                s1b += o2 + o3;  s2b += o2 * o2 + o3 * o3;
            }
            s1a += __shfl_xor_sync(0xffffffffu, s1a, 1);
            s1a += __shfl_xor_sync(0xffffffffu, s1a, 2);
            s2a += __shfl_xor_sync(0xffffffffu, s2a, 1);
            s2a += __shfl_xor_sync(0xffffffffu, s2a, 2);
            s1b += __shfl_xor_sync(0xffffffffu, s1b, 1);
            s1b += __shfl_xor_sync(0xffffffffu, s1b, 2);
            s2b += __shfl_xor_sync(0xffffffffu, s2b, 1);
            s2b += __shfl_xor_sync(0xffffffffu, s2b, 2);
            if (tig == 0) {
                if (r0 < NNODES) {
                    atomicAdd(&g_ls1[r0], s1a);
                    atomicAdd(&g_ls2[r0], s2a);
                }
                if (r1 < NNODES) {
                    atomicAdd(&g_ls1[r1], s1b);
                    atomicAdd(&g_ls2[r1], s2b);
                }
            }
        }
    }
    if (MODE == 2) {
#pragma unroll
        for (int nt = 0; nt < 4; nt++) {
            int c = bn + wn * 32 + nt * 8 + tig * 2;
            float b0 = bias[c], b1 = bias[c + 1];
            float p0 = 0.f, p1 = 0.f;
#pragma unroll
            for (int mt = 0; mt < 4; mt++) {
                int r0 = bm + wm * 64 + mt * 16 + gid;
                int r1 = r0 + 8;
                if (r0 < NNODES) {
                    p0 += fmaxf(acc[mt][nt][0] + b0, 0.f);
                    p1 += fmaxf(acc[mt][nt][1] + b1, 0.f);
                }
                if (r1 < NNODES) {
                    p0 += fmaxf(acc[mt][nt][2] + b0, 0.f);
                    p1 += fmaxf(acc[mt][nt][3] + b1, 0.f);
                }
            }
#pragma unroll
            for (int o = 4; o <= 16; o <<= 1) {
                p0 += __shfl_xor_sync(0xffffffffu, p0, o);
                p1 += __shfl_xor_sync(0xffffffffu, p1, o);
            }
            if (gid == 0) {
                atomicAdd(&g_s[c], p0);
                atomicAdd(&g_s[c + 1], p1);
            }
        }
        __shared__ bool isLast;
        __shared__ float sh_s[256];
        __threadfence();
        if (tid == 0) isLast = (atomicAdd(&c_sig, 1) == 2 * 391 - 1);
        __syncthreads();
        if (isLast) {
            sh_s[tid] = g_s[tid];
            __syncthreads();
            float a1 = fc1_b[tid], a2 = fc2_b[tid];
            float a3 = (tid < 128) ? fc3_b[tid] : 0.f;
            float a4 = (tid < 128) ? fc4_b[tid] : 0.f;
            for (int k = 0; k < 256; k++) {
                float sv = sh_s[k];
                a1 += fc1_w[tid * 256 + k] * sv;
                a2 += fc2_w[tid * 256 + k] * sv;
                if (tid < 128) {
                    a3 += fc3_w[tid * 256 + k] * sv;
                    a4 += fc4_w[tid * 256 + k] * sv;
                }
            }
            g_gamma1[tid] = tanhf(a1);
            g_beta1[tid]  = tanhf(a2);
            if (tid < 128) {
                g_gamma2[tid] = tanhf(a3);
                g_beta2[tid]  = tanhf(a4);
            }
            g_s[tid] = 0.0f;
            if (tid == 0) c_sig = 0;
        }
    }
}

// ---------------- final: agg(h2 fp16) + film + LN; tail blocks clean scratch --
__global__ void __launch_bounds__(256) k_agg2(const float* __restrict__ bias,
                                              float* __restrict__ out)
{
    if (blockIdx.x >= NNODES / 8) {
        int cb = blockIdx.x - NNODES / 8;
        int stride = 64 * 256;
        for (int i = cb * 256 + threadIdx.x; i < NNODES; i += stride) {
            g_degi[i] = 0;
            g_count[i] = 0;
            g_fill[i] = 0;
            g_ls1[i] = 0.0f;
            g_ls2[i] = 0.0f;
        }
        return;
    }
    int d = blockIdx.x * 8 + (threadIdx.x >> 5);
    int lane = threadIdx.x & 31;
    int c = lane * 4;
    float dv = g_dinv[d];
    float w0 = dv * dv;
    float4 acc;
    {
        uint2 hv = *(const uint2*)&g_h2h[(size_t)d * 128 + c];
        float2 f0 = __half22float2(u2h(hv.x));
        float2 f1 = __half22float2(u2h(hv.y));
        acc = make_float4(w0 * f0.x, w0 * f0.y, w0 * f1.x, w0 * f1.y);
    }
    int beg = row_beg(d), end = row_end(d);
    int j = beg;
    for (; j + 2 <= end; j += 2) {
        int2 e0 = g_csr[j], e1 = g_csr[j + 1];
        float wa = __int_as_float(e0.y), wb = __int_as_float(e1.y);
        uint2 ha = *(const uint2*)&g_h2h[(size_t)e0.x * 128 + c];
        uint2 hb = *(const uint2*)&g_h2h[(size_t)e1.x * 128 + c];
        float2 a0 = __half22float2(u2h(ha.x));
        float2 a1 = __half22float2(u2h(ha.y));
        float2 b0 = __half22float2(u2h(hb.x));
        float2 b1 = __half22float2(u2h(hb.y));
        acc.x += wa * a0.x + wb * b0.x;
        acc.y += wa * a0.y + wb * b0.y;
        acc.z += wa * a1.x + wb * b1.x;
        acc.w += wa * a1.y + wb * b1.y;
    }
    if (j < end) {
        int2 e0 = g_csr[j];
        float wa = __int_as_float(e0.y);
        uint2 ha = *(const uint2*)&g_h2h[(size_t)e0.x * 128 + c];
        float2 a0 = __half22float2(u2h(ha.x));
        float2 a1 = __half22float2(u2h(ha.y));
        acc.x += wa * a0.x; acc.y += wa * a0.y;
        acc.z += wa * a1.x; acc.w += wa * a1.y;
    }
    float4 y;
    y.x = g_gamma2[c + 0] * acc.x + g_beta2[c + 0] + bias[c + 0];
    y.y = g_gamma2[c + 1] * acc.y + g_beta2[c + 1] + bias[c + 1];
    y.z = g_gamma2[c + 2] * acc.z + g_beta2[c + 2] + bias[c + 2];
    y.w = g_gamma2[c + 3] * acc.w + g_beta2[c + 3] + bias[c + 3];

    float s1 = y.x + y.y + y.z + y.w;
    float s2 = y.x * y.x + y.y * y.y + y.z * y.z + y.w * y.w;
#pragma unroll
    for (int o = 16; o; o >>= 1) {
        s1 += __shfl_xor_sync(0xffffffffu, s1, o);
        s2 += __shfl_xor_sync(0xffffffffu, s2, o);
    }
    float mu = s1 * (1.0f / 128.0f);
    float var = s2 * (1.0f / 128.0f) - mu * mu;
    float rstd = rsqrtf(var + 1e-5f);
    float4 o4;
    o4.x = (y.x - mu) * rstd;
    o4.y = (y.y - mu) * rstd;
    o4.z = (y.z - mu) * rstd;
    o4.w = (y.w - mu) * rstd;
    *(float4*)&out[(size_t)d * 128 + c] = o4;
}

// ---------------- launch ----------------
extern "C" void kernel_launch(void* const* d_in, const int* in_sizes, int n_in,
                              void* d_out, int out_size)
{
    const float* x       = (const float*)d_in[0];
    const int*   ei      = (const int*)d_in[1];
    const float* conv1_w = (const float*)d_in[2];
    const float* conv1_b = (const float*)d_in[3];
    const float* conv2_w = (const float*)d_in[4];
    const float* conv2_b = (const float*)d_in[5];
    const float* sig_w   = (const float*)d_in[6];
    const float* sig_b   = (const float*)d_in[7];
    const float* fc1_w   = (const float*)d_in[8];
    const float* fc1_b   = (const float*)d_in[9];
    const float* fc2_w   = (const float*)d_in[10];
    const float* fc2_b   = (const float*)d_in[11];
    const float* fc3_w   = (const float*)d_in[12];
    const float* fc3_b   = (const float*)d_in[13];
    const float* fc4_w   = (const float*)d_in[14];
    const float* fc4_b   = (const float*)d_in[15];
    float*       out     = (float*)d_out;

    k_deg_count<<<NEB + NCB, 256>>>(ei, x);
    k_scan1<<<NSB, 1024>>>();
    k_fill<<<(NEDGES + 255) / 256, 256>>>(ei);
    k_agg1<<<NNODES / 8, 256>>>(x);

    dim3 g256(2, (NNODES + 127) / 128);
    dim3 g128(1, (NNODES + 127) / 128);

    k_gemm<2, 256><<<g256, 256>>>(sig_w, sig_b,
                                  fc1_w, fc1_b, fc2_w, fc2_b,
                                  fc3_w, fc3_b, fc4_w, fc4_b);
    k_gemm<1, 256><<<g256, 256>>>(conv1_w, conv1_b,
                                  nullptr, nullptr, nullptr, nullptr,
                                  nullptr, nullptr, nullptr, nullptr);
    k_gemm<0, 128><<<g128, 256>>>(conv2_w, nullptr,
                                  nullptr, nullptr, nullptr, nullptr,
                                  nullptr, nullptr, nullptr, nullptr);
    k_agg2<<<NNODES / 8 + 64, 256>>>(conv2_b, out);
}

// round 11
// speedup vs baseline: 2.8296x; 1.0451x over previous
#include <cuda_runtime.h>
#include <cuda_fp16.h>
#include <math.h>

#define NNODES 50000
#define NEDGES 800000
#define NSB ((NNODES + 1023) / 1024)
#define NEB ((NEDGES + 255) / 256)
#define NCB ((NNODES * 256 / 8 + 255) / 256)

// ---------------- scratch (zero-initialized .bss; restored each run) ----------
__device__ int   g_degi[NNODES];
__device__ int   g_count[NNODES];
__device__ int   g_fill[NNODES];
__device__ float g_ls1[NNODES], g_ls2[NNODES];
__device__ float g_s[256];
__device__ int   c_scan, c_sig;

__device__ float g_dinv[NNODES];
__device__ int   g_rowptr[NNODES + 1];
__device__ int   g_bsum[64];
__device__ int   g_boff[64];
__device__ int2  g_csr[NEDGES];
__device__ __half g_xh [(size_t)NNODES * 256];   // fp16 x      (gather source)
__device__ __half g_xah[(size_t)NNODES * 256];   // fp16 A@x    (GEMM A source)
__device__ __half g_hh [(size_t)NNODES * 256];   // fp16 conv1 out (pre-LN)
__device__ __half g_h2h[(size_t)NNODES * 128];   // fp16 conv2 out
__device__ float g_gamma1[256], g_beta1[256];
__device__ float g_gamma2[128], g_beta2[128];

// ---- bit helpers ----
__device__ __forceinline__ unsigned h2u(__half2 h) {
    union { __half2 h; unsigned u; } c; c.h = h; return c.u;
}
__device__ __forceinline__ __half2 u2h(unsigned u) {
    union { __half2 h; unsigned u; } c; c.u = u; return c.h;
}

__device__ __forceinline__ void mma_f16(float& c0, float& c1, float& c2, float& c3,
                                        unsigned a0, unsigned a1, unsigned a2, unsigned a3,
                                        unsigned b0, unsigned b1)
{
    asm("mma.sync.aligned.m16n8k16.row.col.f32.f16.f16.f32 "
        "{%0,%1,%2,%3},{%4,%5,%6,%7},{%8,%9},{%0,%1,%2,%3};"
        : "+f"(c0), "+f"(c1), "+f"(c2), "+f"(c3)
        : "r"(a0), "r"(a1), "r"(a2), "r"(a3), "r"(b0), "r"(b1));
}

// ---------------- degree + histogram + x->fp16 conversion (grid-split) --------
__global__ void k_deg_count(const int* __restrict__ ei, const float* __restrict__ x)
{
    if (blockIdx.x < NEB) {
        int e = blockIdx.x * 256 + threadIdx.x;
        if (e < NEDGES) {
            atomicAdd(&g_degi[ei[e]], 1);
            atomicAdd(&g_count[ei[NEDGES + e]], 1);
        }
        return;
    }
    size_t i = ((size_t)(blockIdx.x - NEB) * 256 + threadIdx.x) * 8;
    if (i < (size_t)NNODES * 256) {
        float4 a = *(const float4*)&x[i];
        float4 b = *(const float4*)&x[i + 4];
        uint4 o;
        o.x = h2u(__float22half2_rn(make_float2(a.x, a.y)));
        o.y = h2u(__float22half2_rn(make_float2(a.z, a.w)));
        o.z = h2u(__float22half2_rn(make_float2(b.x, b.y)));
        o.w = h2u(__float22half2_rn(make_float2(b.z, b.w)));
        *(uint4*)&g_xh[i] = o;
    }
}

// ---------------- scan ----------------
__global__ void k_scan1()
{
    __shared__ int sh[1024];
    __shared__ bool isLast;
    int t = threadIdx.x;
    int i = blockIdx.x * 1024 + t;
    if (i < NNODES) g_dinv[i] = rsqrtf(1.0f + (float)g_degi[i]);
    int v = (i < NNODES) ? g_count[i] : 0;
    sh[t] = v;
    __syncthreads();
#pragma unroll
    for (int ofs = 1; ofs < 1024; ofs <<= 1) {
        int a = (t >= ofs) ? sh[t - ofs] : 0;
        __syncthreads();
        sh[t] += a;
        __syncthreads();
    }
    if (i < NNODES) g_rowptr[i] = sh[t] - v;
    if (t == 1023) g_bsum[blockIdx.x] = sh[1023];

    __threadfence();
    if (t == 0) isLast = (atomicAdd(&c_scan, 1) == NSB - 1);
    __syncthreads();
    if (isLast) {
        if (t < 64) sh[t] = (t < NSB) ? g_bsum[t] : 0;
        __syncthreads();
        if (t < 64) {
            int acc = 0;
            for (int k = 0; k < t; k++) acc += sh[k];
            g_boff[t] = acc;
        }
        if (t == 0) c_scan = 0;
    }
}

__device__ __forceinline__ int row_beg(int d) { return g_rowptr[d] + g_boff[d >> 10]; }
__device__ __forceinline__ int row_end(int d) {
    return (d + 1 == NNODES) ? NEDGES : g_rowptr[d + 1] + g_boff[(d + 1) >> 10];
}

// ---------------- CSR fill ----------------
__global__ void k_fill(const int* __restrict__ ei)
{
    int e = blockIdx.x * blockDim.x + threadIdx.x;
    if (e < NEDGES) {
        int s = ei[e];
        int d = ei[NEDGES + e];
        int p = g_rowptr[d] + g_boff[d >> 10] + atomicAdd(&g_fill[d], 1);
        float w = g_dinv[s] * g_dinv[d];
        g_csr[p] = make_int2(s, __float_as_int(w));
    }
}

// ---------------- xa = A @ x  (1 warp/node, all-fp16 traffic) -----------------
__global__ void __launch_bounds__(256) k_agg1()
{
    int d = blockIdx.x * 8 + (threadIdx.x >> 5);
    int lane = threadIdx.x & 31;
    int c = lane * 8;
    float dv = g_dinv[d];
    float w0 = dv * dv;
    float acc[8];
    {
        uint4 hs = *(const uint4*)&g_xh[(size_t)d * 256 + c];
#pragma unroll
        for (int q = 0; q < 4; q++) {
            float2 f = __half22float2(u2h(((const unsigned*)&hs)[q]));
            acc[2 * q]     = w0 * f.x;
            acc[2 * q + 1] = w0 * f.y;
        }
    }
    int beg = row_beg(d), end = row_end(d);
    int j = beg;
    for (; j + 2 <= end; j += 2) {
        int2 e0 = g_csr[j], e1 = g_csr[j + 1];
        float wa = __int_as_float(e0.y), wb = __int_as_float(e1.y);
        uint4 ha = *(const uint4*)&g_xh[(size_t)e0.x * 256 + c];
        uint4 hb = *(const uint4*)&g_xh[(size_t)e1.x * 256 + c];
#pragma unroll
        for (int q = 0; q < 4; q++) {
            float2 fa = __half22float2(u2h(((const unsigned*)&ha)[q]));
            float2 fb = __half22float2(u2h(((const unsigned*)&hb)[q]));
            acc[2 * q]     += wa * fa.x + wb * fb.x;
            acc[2 * q + 1] += wa * fa.y + wb * fb.y;
        }
    }
    if (j < end) {
        int2 e0 = g_csr[j];
        float wa = __int_as_float(e0.y);
        uint4 ha = *(const uint4*)&g_xh[(size_t)e0.x * 256 + c];
#pragma unroll
        for (int q = 0; q < 4; q++) {
            float2 fa = __half22float2(u2h(((const unsigned*)&ha)[q]));
            acc[2 * q]     += wa * fa.x;
            acc[2 * q + 1] += wa * fa.y;
        }
    }
    uint4 o;
    o.x = h2u(__float22half2_rn(make_float2(acc[0], acc[1])));
    o.y = h2u(__float22half2_rn(make_float2(acc[2], acc[3])));
    o.z = h2u(__float22half2_rn(make_float2(acc[4], acc[5])));
    o.w = h2u(__float22half2_rn(make_float2(acc[6], acc[7])));
    *(uint4*)&g_xah[(size_t)d * 256 + c] = o;
}

// ---------------- fp16 HMMA GEMM (double-buffered, packed-pair Bs) ------------
// MODE 0: A=LN(g_hh), C=g_h2h (N=128)                           [conv2]
// MODE 1: A=g_xah,    C=g_hh (N=256, film+bias+relu, LN stats)  [conv1]
// MODE 2: A=g_xah, no C (N=256, bias+relu -> colsum, + FC heads)[sig]
template <int MODE, int NN>
__global__ void __launch_bounds__(256, 2)
k_gemm(const float* __restrict__ B, const float* __restrict__ bias,
       const float* __restrict__ fc1_w, const float* __restrict__ fc1_b,
       const float* __restrict__ fc2_w, const float* __restrict__ fc2_b,
       const float* __restrict__ fc3_w, const float* __restrict__ fc3_b,
       const float* __restrict__ fc4_w, const float* __restrict__ fc4_b)
{
    const __half* Ah = (MODE == 0) ? g_hh : g_xah;
    __shared__ alignas(16) __half    As[2][128][24];   // [m][k] pad 24
    __shared__ alignas(16) unsigned Bs2[2][8][136];    // [k/2][n] half2 {k even, k odd}
    const int bm = blockIdx.y * 128;
    const int bn = blockIdx.x * 128;
    const int tid = threadIdx.x;

    const int wid = tid >> 5;
    const int wm = wid >> 2;
    const int wn = wid & 3;
    const int lane = tid & 31;
    const int gid = lane >> 2;
    const int tig = lane & 3;

    float acc[4][4][4];
#pragma unroll
    for (int mt = 0; mt < 4; mt++)
#pragma unroll
        for (int nt = 0; nt < 4; nt++)
#pragma unroll
            for (int r = 0; r < 4; r++) acc[mt][nt][r] = 0.0f;

    // A staging: 2 threads/row, 8 halves each
    const int arow = tid >> 1, akh = tid & 1;
    const int ga = bm + arow;
    const bool gaok = (ga < NNODES);
    // B staging: thread covers k-pair row rowp=tid>>5 (k=2*rowp, 2*rowp+1), 4 n-cols
    const int browp = tid >> 5, bq = (tid & 31) * 4;

    uint4 areg;
    float4 breg0, breg1;   // k = 2*browp, 2*browp+1
    float mu = 0.f, rs = 0.f;
    if (MODE == 0 && gaok) {
        float s1 = g_ls1[ga], s2 = g_ls2[ga];
        mu = s1 * (1.0f / 256.0f);
        rs = rsqrtf(s2 * (1.0f / 256.0f) - mu * mu + 1e-5f);
    }

    auto load_tile = [&](int k0) {
        areg = make_uint4(0, 0, 0, 0);
        if (gaok) areg = *(const uint4*)&Ah[(size_t)ga * 256 + k0 + akh * 8];
        breg0 = *(const float4*)&B[(size_t)(k0 + 2 * browp) * NN + bn + bq];
        breg1 = *(const float4*)&B[(size_t)(k0 + 2 * browp + 1) * NN + bn + bq];
    };
    auto stage = [&](int buf) {
        uint4 av = areg;
        if (MODE == 0) {
#pragma unroll
            for (int q = 0; q < 4; q++) {
                float2 f = __half22float2(u2h(((const unsigned*)&av)[q]));
                f.x = (f.x - mu) * rs;
                f.y = (f.y - mu) * rs;
                ((unsigned*)&av)[q] = h2u(__float22half2_rn(f));
            }
        }
        *(uint4*)&As[buf][arow][akh * 8] = av;
        uint4 bv;
        bv.x = h2u(__float22half2_rn(make_float2(breg0.x, breg1.x)));
        bv.y = h2u(__float22half2_rn(make_float2(breg0.y, breg1.y)));
        bv.z = h2u(__float22half2_rn(make_float2(breg0.z, breg1.z)));
        bv.w = h2u(__float22half2_rn(make_float2(breg0.w, breg1.w)));
        *(uint4*)&Bs2[buf][browp][bq] = bv;
    };

    load_tile(0);
    stage(0);
    load_tile(16);
    __syncthreads();

    const int NT = 256 / 16;
    for (int t = 0; t < NT; t++) {
        int cur = t & 1;
        if (t + 1 < NT) stage(cur ^ 1);
        if (t + 2 < NT) load_tile((t + 2) * 16);

        unsigned af[4][4], bf[4][2];
#pragma unroll
        for (int mt = 0; mt < 4; mt++) {
            int mr = wm * 64 + mt * 16 + gid;
            af[mt][0] = *(const unsigned*)&As[cur][mr][tig * 2];
            af[mt][1] = *(const unsigned*)&As[cur][mr + 8][tig * 2];
            af[mt][2] = *(const unsigned*)&As[cur][mr][tig * 2 + 8];
            af[mt][3] = *(const unsigned*)&As[cur][mr + 8][tig * 2 + 8];
        }
#pragma unroll
        for (int nt = 0; nt < 4; nt++) {
            int nc = wn * 32 + nt * 8 + gid;
            bf[nt][0] = Bs2[cur][tig][nc];       // {k=2tig,   2tig+1}
            bf[nt][1] = Bs2[cur][tig + 4][nc];   // {k=2tig+8, 2tig+9}
        }
#pragma unroll
        for (int mt = 0; mt < 4; mt++)
#pragma unroll
            for (int nt = 0; nt < 4; nt++)
                mma_f16(acc[mt][nt][0], acc[mt][nt][1], acc[mt][nt][2], acc[mt][nt][3],
                        af[mt][0], af[mt][1], af[mt][2], af[mt][3],
                        bf[nt][0], bf[nt][1]);
        __syncthreads();
    }

    // ---------------- epilogues ----------------
    if (MODE == 0) {
#pragma unroll
        for (int mt = 0; mt < 4; mt++) {
            int r0 = bm + wm * 64 + mt * 16 + gid;
            int r1 = r0 + 8;
#pragma unroll
            for (int nt = 0; nt < 4; nt++) {
                int c = wn * 32 + nt * 8 + tig * 2;
                if (r0 < NNODES) {
                    __half2 o = __float22half2_rn(make_float2(acc[mt][nt][0], acc[mt][nt][1]));
                    *(__half2*)&g_h2h[(size_t)r0 * 128 + c] = o;
                }
                if (r1 < NNODES) {
                    __half2 o = __float22half2_rn(make_float2(acc[mt][nt][2], acc[mt][nt][3]));
                    *(__half2*)&g_h2h[(size_t)r1 * 128 + c] = o;
                }
            }
        }
    }
    if (MODE == 1) {
        float ga2[4][2], be[4][2];
#pragma unroll
        for (int nt = 0; nt < 4; nt++) {
            int c = bn + wn * 32 + nt * 8 + tig * 2;
            ga2[nt][0] = g_gamma1[c];     be[nt][0] = g_beta1[c] + bias[c];
            ga2[nt][1] = g_gamma1[c + 1]; be[nt][1] = g_beta1[c + 1] + bias[c + 1];
        }
#pragma unroll
        for (int mt = 0; mt < 4; mt++) {
            int r0 = bm + wm * 64 + mt * 16 + gid;
            int r1 = r0 + 8;
            float s1a = 0.f, s2a = 0.f, s1b = 0.f, s2b = 0.f;
#pragma unroll
            for (int nt = 0; nt < 4; nt++) {
                int c = bn + wn * 32 + nt * 8 + tig * 2;
                float o0 = fmaxf(ga2[nt][0] * acc[mt][nt][0] + be[nt][0], 0.f);
                float o1 = fmaxf(ga2[nt][1] * acc[mt][nt][1] + be[nt][1], 0.f);
                float o2 = fmaxf(ga2[nt][0] * acc[mt][nt][2] + be[nt][0], 0.f);
                float o3 = fmaxf(ga2[nt][1] * acc[mt][nt][3] + be[nt][1], 0.f);
                if (r0 < NNODES)
                    *(__half2*)&g_hh[(size_t)r0 * 256 + c] =
                        __float22half2_rn(make_float2(o0, o1));
                if (r1 < NNODES)
                    *(__half2*)&g_hh[(size_t)r1 * 256 + c] =
                        __float22half2_rn(make_float2(o2, o3));
                s1a += o0 + o1;  s2a += o0 * o0 + o1 * o1;
                s1b += o2 + o3;  s2b += o2 * o2 + o3 * o3;
            }
            s1a += __shfl_xor_sync(0xffffffffu, s1a, 1);
            s1a += __shfl_xor_sync(0xffffffffu, s1a, 2);
            s2a += __shfl_xor_sync(0xffffffffu, s2a, 1);
            s2a += __shfl_xor_sync(0xffffffffu, s2a, 2);
            s1b += __shfl_xor_sync(0xffffffffu, s1b, 1);
            s1b += __shfl_xor_sync(0xffffffffu, s1b, 2);
            s2b += __shfl_xor_sync(0xffffffffu, s2b, 1);
            s2b += __shfl_xor_sync(0xffffffffu, s2b, 2);
            if (tig == 0) {
                if (r0 < NNODES) {
                    atomicAdd(&g_ls1[r0], s1a);
                    atomicAdd(&g_ls2[r0], s2a);
                }
                if (r1 < NNODES) {
                    atomicAdd(&g_ls1[r1], s1b);
                    atomicAdd(&g_ls2[r1], s2b);
                }
            }
        }
    }
    if (MODE == 2) {
#pragma unroll
        for (int nt = 0; nt < 4; nt++) {
            int c = bn + wn * 32 + nt * 8 + tig * 2;
            float b0 = bias[c], b1 = bias[c + 1];
            float p0 = 0.f, p1 = 0.f;
#pragma unroll
            for (int mt = 0; mt < 4; mt++) {
                int r0 = bm + wm * 64 + mt * 16 + gid;
                int r1 = r0 + 8;
                if (r0 < NNODES) {
                    p0 += fmaxf(acc[mt][nt][0] + b0, 0.f);
                    p1 += fmaxf(acc[mt][nt][1] + b1, 0.f);
                }
                if (r1 < NNODES) {
                    p0 += fmaxf(acc[mt][nt][2] + b0, 0.f);
                    p1 += fmaxf(acc[mt][nt][3] + b1, 0.f);
                }
            }
#pragma unroll
            for (int o = 4; o <= 16; o <<= 1) {
                p0 += __shfl_xor_sync(0xffffffffu, p0, o);
                p1 += __shfl_xor_sync(0xffffffffu, p1, o);
            }
            if (gid == 0) {
                atomicAdd(&g_s[c], p0);
                atomicAdd(&g_s[c + 1], p1);
            }
        }
        __shared__ bool isLast;
        __shared__ float sh_s[256];
        __threadfence();
        if (tid == 0) isLast = (atomicAdd(&c_sig, 1) == 2 * 391 - 1);
        __syncthreads();
        if (isLast) {
            sh_s[tid] = g_s[tid];
            __syncthreads();
            float a1 = fc1_b[tid], a2 = fc2_b[tid];
            float a3 = (tid < 128) ? fc3_b[tid] : 0.f;
            float a4 = (tid < 128) ? fc4_b[tid] : 0.f;
            for (int k = 0; k < 256; k++) {
                float sv = sh_s[k];
                a1 += fc1_w[tid * 256 + k] * sv;
                a2 += fc2_w[tid * 256 + k] * sv;
                if (tid < 128) {
                    a3 += fc3_w[tid * 256 + k] * sv;
                    a4 += fc4_w[tid * 256 + k] * sv;
                }
            }
            g_gamma1[tid] = tanhf(a1);
            g_beta1[tid]  = tanhf(a2);
            if (tid < 128) {
                g_gamma2[tid] = tanhf(a3);
                g_beta2[tid]  = tanhf(a4);
            }
            g_s[tid] = 0.0f;
            if (tid == 0) c_sig = 0;
        }
    }
}

// ---------------- final: agg(h2 fp16) + film + LN; tail blocks clean scratch --
__global__ void __launch_bounds__(256) k_agg2(const float* __restrict__ bias,
                                              float* __restrict__ out)
{
    if (blockIdx.x >= NNODES / 8) {
        int cb = blockIdx.x - NNODES / 8;
        int stride = 64 * 256;
        for (int i = cb * 256 + threadIdx.x; i < NNODES; i += stride) {
            g_degi[i] = 0;
            g_count[i] = 0;
            g_fill[i] = 0;
            g_ls1[i] = 0.0f;
            g_ls2[i] = 0.0f;
        }
        return;
    }
    int d = blockIdx.x * 8 + (threadIdx.x >> 5);
    int lane = threadIdx.x & 31;
    int c = lane * 4;
    float dv = g_dinv[d];
    float w0 = dv * dv;
    float4 acc;
    {
        uint2 hv = *(const uint2*)&g_h2h[(size_t)d * 128 + c];
        float2 f0 = __half22float2(u2h(hv.x));
        float2 f1 = __half22float2(u2h(hv.y));
        acc = make_float4(w0 * f0.x, w0 * f0.y, w0 * f1.x, w0 * f1.y);
    }
    int beg = row_beg(d), end = row_end(d);
    int j = beg;
    for (; j + 2 <= end; j += 2) {
        int2 e0 = g_csr[j], e1 = g_csr[j + 1];
        float wa = __int_as_float(e0.y), wb = __int_as_float(e1.y);
        uint2 ha = *(const uint2*)&g_h2h[(size_t)e0.x * 128 + c];
        uint2 hb = *(const uint2*)&g_h2h[(size_t)e1.x * 128 + c];
        float2 a0 = __half22float2(u2h(ha.x));
        float2 a1 = __half22float2(u2h(ha.y));
        float2 b0 = __half22float2(u2h(hb.x));
        float2 b1 = __half22float2(u2h(hb.y));
        acc.x += wa * a0.x + wb * b0.x;
        acc.y += wa * a0.y + wb * b0.y;
        acc.z += wa * a1.x + wb * b1.x;
        acc.w += wa * a1.y + wb * b1.y;
    }
    if (j < end) {
        int2 e0 = g_csr[j];
        float wa = __int_as_float(e0.y);
        uint2 ha = *(const uint2*)&g_h2h[(size_t)e0.x * 128 + c];
        float2 a0 = __half22float2(u2h(ha.x));
        float2 a1 = __half22float2(u2h(ha.y));
        acc.x += wa * a0.x; acc.y += wa * a0.y;
        acc.z += wa * a1.x; acc.w += wa * a1.y;
    }
    float4 y;
    y.x = g_gamma2[c + 0] * acc.x + g_beta2[c + 0] + bias[c + 0];
    y.y = g_gamma2[c + 1] * acc.y + g_beta2[c + 1] + bias[c + 1];
    y.z = g_gamma2[c + 2] * acc.z + g_beta2[c + 2] + bias[c + 2];
    y.w = g_gamma2[c + 3] * acc.w + g_beta2[c + 3] + bias[c + 3];

    float s1 = y.x + y.y + y.z + y.w;
    float s2 = y.x * y.x + y.y * y.y + y.z * y.z + y.w * y.w;
#pragma unroll
    for (int o = 16; o; o >>= 1) {
        s1 += __shfl_xor_sync(0xffffffffu, s1, o);
        s2 += __shfl_xor_sync(0xffffffffu, s2, o);
    }
    float mu = s1 * (1.0f / 128.0f);
    float var = s2 * (1.0f / 128.0f) - mu * mu;
    float rstd = rsqrtf(var + 1e-5f);
    float4 o4;
    o4.x = (y.x - mu) * rstd;
    o4.y = (y.y - mu) * rstd;
    o4.z = (y.z - mu) * rstd;
    o4.w = (y.w - mu) * rstd;
    *(float4*)&out[(size_t)d * 128 + c] = o4;
}

// ---------------- launch ----------------
extern "C" void kernel_launch(void* const* d_in, const int* in_sizes, int n_in,
                              void* d_out, int out_size)
{
    const float* x       = (const float*)d_in[0];
    const int*   ei      = (const int*)d_in[1];
    const float* conv1_w = (const float*)d_in[2];
    const float* conv1_b = (const float*)d_in[3];
    const float* conv2_w = (const float*)d_in[4];
    const float* conv2_b = (const float*)d_in[5];
    const float* sig_w   = (const float*)d_in[6];
    const float* sig_b   = (const float*)d_in[7];
    const float* fc1_w   = (const float*)d_in[8];
    const float* fc1_b   = (const float*)d_in[9];
    const float* fc2_w   = (const float*)d_in[10];
    const float* fc2_b   = (const float*)d_in[11];
    const float* fc3_w   = (const float*)d_in[12];
    const float* fc3_b   = (const float*)d_in[13];
    const float* fc4_w   = (const float*)d_in[14];
    const float* fc4_b   = (const float*)d_in[15];
    float*       out     = (float*)d_out;

    k_deg_count<<<NEB + NCB, 256>>>(ei, x);
    k_scan1<<<NSB, 1024>>>();
    k_fill<<<(NEDGES + 255) / 256, 256>>>(ei);
    k_agg1<<<NNODES / 8, 256>>>();

    dim3 g256(2, (NNODES + 127) / 128);
    dim3 g128(1, (NNODES + 127) / 128);

    k_gemm<2, 256><<<g256, 256>>>(sig_w, sig_b,
                                  fc1_w, fc1_b, fc2_w, fc2_b,
                                  fc3_w, fc3_b, fc4_w, fc4_b);
    k_gemm<1, 256><<<g256, 256>>>(conv1_w, conv1_b,
                                  nullptr, nullptr, nullptr, nullptr,
                                  nullptr, nullptr, nullptr, nullptr);
    k_gemm<0, 128><<<g128, 256>>>(conv2_w, nullptr,
                                  nullptr, nullptr, nullptr, nullptr,
                                  nullptr, nullptr, nullptr, nullptr);
    k_agg2<<<NNODES / 8 + 64, 256>>>(conv2_b, out);
}

// round 12
// speedup vs baseline: 2.8607x; 1.0110x over previous
#include <cuda_runtime.h>
#include <cuda_fp16.h>
#include <math.h>

#define NNODES 50000
#define NEDGES 800000
#define NSB ((NNODES + 1023) / 1024)
#define NEB ((NEDGES + 255) / 256)
#define NCB ((NNODES * 256 / 8 + 255) / 256)

// ---------------- scratch (zero-initialized .bss; restored each run) ----------
__device__ int   g_degi[NNODES];
__device__ int   g_count[NNODES];
__device__ int   g_fill[NNODES];
__device__ float g_ls1[NNODES], g_ls2[NNODES];
__device__ float g_s[256];
__device__ int   c_scan, c_sig;

__device__ float g_dinv[NNODES];
__device__ int   g_rowptr[NNODES + 1];
__device__ int   g_bsum[64];
__device__ int   g_boff[64];
__device__ int2  g_csr[NEDGES];
__device__ __half g_xh [(size_t)NNODES * 256];
__device__ __half g_xah[(size_t)NNODES * 256];
__device__ __half g_hh [(size_t)NNODES * 256];
__device__ __half g_h2h[(size_t)NNODES * 128];
__device__ float g_gamma1[256], g_beta1[256];
__device__ float g_gamma2[128], g_beta2[128];

// ---- bit helpers ----
__device__ __forceinline__ unsigned h2u(__half2 h) {
    union { __half2 h; unsigned u; } c; c.h = h; return c.u;
}
__device__ __forceinline__ __half2 u2h(unsigned u) {
    union { __half2 h; unsigned u; } c; c.u = u; return c.h;
}

__device__ __forceinline__ void mma_f16(float& c0, float& c1, float& c2, float& c3,
                                        unsigned a0, unsigned a1, unsigned a2, unsigned a3,
                                        unsigned b0, unsigned b1)
{
    asm("mma.sync.aligned.m16n8k16.row.col.f32.f16.f16.f32 "
        "{%0,%1,%2,%3},{%4,%5,%6,%7},{%8,%9},{%0,%1,%2,%3};"
        : "+f"(c0), "+f"(c1), "+f"(c2), "+f"(c3)
        : "r"(a0), "r"(a1), "r"(a2), "r"(a3), "r"(b0), "r"(b1));
}

__device__ __forceinline__ void ldsm_x4(unsigned& r0, unsigned& r1,
                                        unsigned& r2, unsigned& r3, unsigned addr)
{
    asm volatile("ldmatrix.sync.aligned.m8n8.x4.shared.b16 {%0,%1,%2,%3}, [%4];"
                 : "=r"(r0), "=r"(r1), "=r"(r2), "=r"(r3) : "r"(addr));
}

// ---------------- degree + histogram + x->fp16 conversion (grid-split) --------
__global__ void k_deg_count(const int* __restrict__ ei, const float* __restrict__ x)
{
    if (blockIdx.x < NEB) {
        int e = blockIdx.x * 256 + threadIdx.x;
        if (e < NEDGES) {
            atomicAdd(&g_degi[ei[e]], 1);
            atomicAdd(&g_count[ei[NEDGES + e]], 1);
        }
        return;
    }
    size_t i = ((size_t)(blockIdx.x - NEB) * 256 + threadIdx.x) * 8;
    if (i < (size_t)NNODES * 256) {
        float4 a = *(const float4*)&x[i];
        float4 b = *(const float4*)&x[i + 4];
        uint4 o;
        o.x = h2u(__float22half2_rn(make_float2(a.x, a.y)));
        o.y = h2u(__float22half2_rn(make_float2(a.z, a.w)));
        o.z = h2u(__float22half2_rn(make_float2(b.x, b.y)));
        o.w = h2u(__float22half2_rn(make_float2(b.z, b.w)));
        *(uint4*)&g_xh[i] = o;
    }
}

// ---------------- scan ----------------
__global__ void k_scan1()
{
    __shared__ int sh[1024];
    __shared__ bool isLast;
    int t = threadIdx.x;
    int i = blockIdx.x * 1024 + t;
    if (i < NNODES) g_dinv[i] = rsqrtf(1.0f + (float)g_degi[i]);
    int v = (i < NNODES) ? g_count[i] : 0;
    sh[t] = v;
    __syncthreads();
#pragma unroll
    for (int ofs = 1; ofs < 1024; ofs <<= 1) {
        int a = (t >= ofs) ? sh[t - ofs] : 0;
        __syncthreads();
        sh[t] += a;
        __syncthreads();
    }
    if (i < NNODES) g_rowptr[i] = sh[t] - v;
    if (t == 1023) g_bsum[blockIdx.x] = sh[1023];

    __threadfence();
    if (t == 0) isLast = (atomicAdd(&c_scan, 1) == NSB - 1);
    __syncthreads();
    if (isLast) {
        if (t < 64) sh[t] = (t < NSB) ? g_bsum[t] : 0;
        __syncthreads();
        if (t < 64) {
            int acc = 0;
            for (int k = 0; k < t; k++) acc += sh[k];
            g_boff[t] = acc;
        }
        if (t == 0) c_scan = 0;
    }
}

__device__ __forceinline__ int row_beg(int d) { return g_rowptr[d] + g_boff[d >> 10]; }
__device__ __forceinline__ int row_end(int d) {
    return (d + 1 == NNODES) ? NEDGES : g_rowptr[d + 1] + g_boff[(d + 1) >> 10];
}

// ---------------- CSR fill ----------------
__global__ void k_fill(const int* __restrict__ ei)
{
    int e = blockIdx.x * blockDim.x + threadIdx.x;
    if (e < NEDGES) {
        int s = ei[e];
        int d = ei[NEDGES + e];
        int p = g_rowptr[d] + g_boff[d >> 10] + atomicAdd(&g_fill[d], 1);
        float w = g_dinv[s] * g_dinv[d];
        g_csr[p] = make_int2(s, __float_as_int(w));
    }
}

// ---------------- xa = A @ x  (1 warp/node, 4-edge unroll) --------------------
__global__ void __launch_bounds__(256) k_agg1()
{
    int d = blockIdx.x * 8 + (threadIdx.x >> 5);
    int lane = threadIdx.x & 31;
    int c = lane * 8;
    float dv = g_dinv[d];
    float w0 = dv * dv;
    float acc[8];
    {
        uint4 hs = *(const uint4*)&g_xh[(size_t)d * 256 + c];
#pragma unroll
        for (int q = 0; q < 4; q++) {
            float2 f = __half22float2(u2h(((const unsigned*)&hs)[q]));
            acc[2 * q]     = w0 * f.x;
            acc[2 * q + 1] = w0 * f.y;
        }
    }
    int beg = row_beg(d), end = row_end(d);
    int j = beg;
    for (; j + 4 <= end; j += 4) {
        int2 e0 = g_csr[j],     e1 = g_csr[j + 1];
        int2 e2 = g_csr[j + 2], e3 = g_csr[j + 3];
        float wa = __int_as_float(e0.y), wb = __int_as_float(e1.y);
        float wc = __int_as_float(e2.y), wd = __int_as_float(e3.y);
        uint4 ha = *(const uint4*)&g_xh[(size_t)e0.x * 256 + c];
        uint4 hb = *(const uint4*)&g_xh[(size_t)e1.x * 256 + c];
        uint4 hc = *(const uint4*)&g_xh[(size_t)e2.x * 256 + c];
        uint4 hd = *(const uint4*)&g_xh[(size_t)e3.x * 256 + c];
#pragma unroll
        for (int q = 0; q < 4; q++) {
            float2 fa = __half22float2(u2h(((const unsigned*)&ha)[q]));
            float2 fb = __half22float2(u2h(((const unsigned*)&hb)[q]));
            float2 fc = __half22float2(u2h(((const unsigned*)&hc)[q]));
            float2 fd = __half22float2(u2h(((const unsigned*)&hd)[q]));
            acc[2 * q]     += wa * fa.x + wb * fb.x + wc * fc.x + wd * fd.x;
            acc[2 * q + 1] += wa * fa.y + wb * fb.y + wc * fc.y + wd * fd.y;
        }
    }
    for (; j < end; j++) {
        int2 e0 = g_csr[j];
        float wa = __int_as_float(e0.y);
        uint4 ha = *(const uint4*)&g_xh[(size_t)e0.x * 256 + c];
#pragma unroll
        for (int q = 0; q < 4; q++) {
            float2 fa = __half22float2(u2h(((const unsigned*)&ha)[q]));
            acc[2 * q]     += wa * fa.x;
            acc[2 * q + 1] += wa * fa.y;
        }
    }
    uint4 o;
    o.x = h2u(__float22half2_rn(make_float2(acc[0], acc[1])));
    o.y = h2u(__float22half2_rn(make_float2(acc[2], acc[3])));
    o.z = h2u(__float22half2_rn(make_float2(acc[4], acc[5])));
    o.w = h2u(__float22half2_rn(make_float2(acc[6], acc[7])));
    *(uint4*)&g_xah[(size_t)d * 256 + c] = o;
}

// ---------------- fp16 HMMA GEMM (double-buffered, LDSM A-frags) --------------
// MODE 0: A=LN(g_hh), C=g_h2h (N=128)                           [conv2]
// MODE 1: A=g_xah,    C=g_hh (N=256, film+bias+relu, LN stats)  [conv1]
// MODE 2: A=g_xah, no C (N=256, bias+relu -> colsum, + FC heads)[sig]
template <int MODE, int NN>
__global__ void __launch_bounds__(256, 2)
k_gemm(const float* __restrict__ B, const float* __restrict__ bias,
       const float* __restrict__ fc1_w, const float* __restrict__ fc1_b,
       const float* __restrict__ fc2_w, const float* __restrict__ fc2_b,
       const float* __restrict__ fc3_w, const float* __restrict__ fc3_b,
       const float* __restrict__ fc4_w, const float* __restrict__ fc4_b)
{
    const __half* Ah = (MODE == 0) ? g_hh : g_xah;
    __shared__ alignas(16) __half    As[2][128][24];   // pitch 48B -> LDSM conflict-free
    __shared__ alignas(16) unsigned Bs2[2][8][136];    // [k/2][n] half2 pairs
    const int bm = blockIdx.y * 128;
    const int bn = blockIdx.x * 128;
    const int tid = threadIdx.x;

    const int wid = tid >> 5;
    const int wm = wid >> 2;
    const int wn = wid & 3;
    const int lane = tid & 31;
    const int gid = lane >> 2;
    const int tig = lane & 3;

    float acc[4][4][4];
#pragma unroll
    for (int mt = 0; mt < 4; mt++)
#pragma unroll
        for (int nt = 0; nt < 4; nt++)
#pragma unroll
            for (int r = 0; r < 4; r++) acc[mt][nt][r] = 0.0f;

    const int arow = tid >> 1, akh = tid & 1;
    const int ga = bm + arow;
    const bool gaok = (ga < NNODES);
    const int browp = tid >> 5, bq = (tid & 31) * 4;

    // ldmatrix lane address pieces: row = mr0 + (lane & 15), +16B for lanes >= 16
    const unsigned as_base = (unsigned)__cvta_generic_to_shared(&As[0][0][0]);
    const unsigned lrow = lane & 15;
    const unsigned lkoff = (lane >> 4) * 16;   // bytes

    uint4 areg;
    float4 breg0, breg1;
    float mu = 0.f, rs = 0.f;
    if (MODE == 0 && gaok) {
        float s1 = g_ls1[ga], s2 = g_ls2[ga];
        mu = s1 * (1.0f / 256.0f);
        rs = rsqrtf(s2 * (1.0f / 256.0f) - mu * mu + 1e-5f);
    }

    auto load_tile = [&](int k0) {
        areg = make_uint4(0, 0, 0, 0);
        if (gaok) areg = *(const uint4*)&Ah[(size_t)ga * 256 + k0 + akh * 8];
        breg0 = *(const float4*)&B[(size_t)(k0 + 2 * browp) * NN + bn + bq];
        breg1 = *(const float4*)&B[(size_t)(k0 + 2 * browp + 1) * NN + bn + bq];
    };
    auto stage = [&](int buf) {
        uint4 av = areg;
        if (MODE == 0) {
#pragma unroll
            for (int q = 0; q < 4; q++) {
                float2 f = __half22float2(u2h(((const unsigned*)&av)[q]));
                f.x = (f.x - mu) * rs;
                f.y = (f.y - mu) * rs;
                ((unsigned*)&av)[q] = h2u(__float22half2_rn(f));
            }
        }
        *(uint4*)&As[buf][arow][akh * 8] = av;
        uint4 bv;
        bv.x = h2u(__float22half2_rn(make_float2(breg0.x, breg1.x)));
        bv.y = h2u(__float22half2_rn(make_float2(breg0.y, breg1.y)));
        bv.z = h2u(__float22half2_rn(make_float2(breg0.z, breg1.z)));
        bv.w = h2u(__float22half2_rn(make_float2(breg0.w, breg1.w)));
        *(uint4*)&Bs2[buf][browp][bq] = bv;
    };

    load_tile(0);
    stage(0);
    load_tile(16);
    __syncthreads();

    const int NT = 256 / 16;
    for (int t = 0; t < NT; t++) {
        int cur = t & 1;
        if (t + 1 < NT) stage(cur ^ 1);
        if (t + 2 < NT) load_tile((t + 2) * 16);

        unsigned af[4][4], bf[4][2];
        const unsigned as_cur = as_base + (unsigned)(cur * 128 * 48);
#pragma unroll
        for (int mt = 0; mt < 4; mt++) {
            unsigned row = (unsigned)(wm * 64 + mt * 16) + lrow;
            unsigned addr = as_cur + row * 48u + lkoff;
            ldsm_x4(af[mt][0], af[mt][1], af[mt][2], af[mt][3], addr);
        }
#pragma unroll
        for (int nt = 0; nt < 4; nt++) {
            int nc = wn * 32 + nt * 8 + gid;
            bf[nt][0] = Bs2[cur][tig][nc];
            bf[nt][1] = Bs2[cur][tig + 4][nc];
        }
#pragma unroll
        for (int mt = 0; mt < 4; mt++)
#pragma unroll
            for (int nt = 0; nt < 4; nt++)
                mma_f16(acc[mt][nt][0], acc[mt][nt][1], acc[mt][nt][2], acc[mt][nt][3],
                        af[mt][0], af[mt][1], af[mt][2], af[mt][3],
                        bf[nt][0], bf[nt][1]);
        __syncthreads();
    }

    // ---------------- epilogues ----------------
    if (MODE == 0) {
#pragma unroll
        for (int mt = 0; mt < 4; mt++) {
            int r0 = bm + wm * 64 + mt * 16 + gid;
            int r1 = r0 + 8;
#pragma unroll
            for (int nt = 0; nt < 4; nt++) {
                int c = wn * 32 + nt * 8 + tig * 2;
                if (r0 < NNODES) {
                    __half2 o = __float22half2_rn(make_float2(acc[mt][nt][0], acc[mt][nt][1]));
                    *(__half2*)&g_h2h[(size_t)r0 * 128 + c] = o;
                }
                if (r1 < NNODES) {
                    __half2 o = __float22half2_rn(make_float2(acc[mt][nt][2], acc[mt][nt][3]));
                    *(__half2*)&g_h2h[(size_t)r1 * 128 + c] = o;
                }
            }
        }
    }
    if (MODE == 1) {
        float ga2[4][2], be[4][2];
#pragma unroll
        for (int nt = 0; nt < 4; nt++) {
            int c = bn + wn * 32 + nt * 8 + tig * 2;
            ga2[nt][0] = g_gamma1[c];     be[nt][0] = g_beta1[c] + bias[c];
            ga2[nt][1] = g_gamma1[c + 1]; be[nt][1] = g_beta1[c + 1] + bias[c + 1];
        }
#pragma unroll
        for (int mt = 0; mt < 4; mt++) {
            int r0 = bm + wm * 64 + mt * 16 + gid;
            int r1 = r0 + 8;
            float s1a = 0.f, s2a = 0.f, s1b = 0.f, s2b = 0.f;
#pragma unroll
            for (int nt = 0; nt < 4; nt++) {
                int c = bn + wn * 32 + nt * 8 + tig * 2;
                float o0 = fmaxf(ga2[nt][0] * acc[mt][nt][0] + be[nt][0], 0.f);
                float o1 = fmaxf(ga2[nt][1] * acc[mt][nt][1] + be[nt][1], 0.f);
                float o2 = fmaxf(ga2[nt][0] * acc[mt][nt][2] + be[nt][0], 0.f);
                float o3 = fmaxf(ga2[nt][1] * acc[mt][nt][3] + be[nt][1], 0.f);
                if (r0 < NNODES)
                    *(__half2*)&g_hh[(size_t)r0 * 256 + c] =
                        __float22half2_rn(make_float2(o0, o1));
                if (r1 < NNODES)
                    *(__half2*)&g_hh[(size_t)r1 * 256 + c] =
                        __float22half2_rn(make_float2(o2, o3));
                s1a += o0 + o1;  s2a += o0 * o0 + o1 * o1;
                s1b += o2 + o3;  s2b += o2 * o2 + o3 * o3;
            }
            s1a += __shfl_xor_sync(0xffffffffu, s1a, 1);
            s1a += __shfl_xor_sync(0xffffffffu, s1a, 2);
            s2a += __shfl_xor_sync(0xffffffffu, s2a, 1);
            s2a += __shfl_xor_sync(0xffffffffu, s2a, 2);
            s1b += __shfl_xor_sync(0xffffffffu, s1b, 1);
            s1b += __shfl_xor_sync(0xffffffffu, s1b, 2);
            s2b += __shfl_xor_sync(0xffffffffu, s2b, 1);
            s2b += __shfl_xor_sync(0xffffffffu, s2b, 2);
            if (tig == 0) {
                if (r0 < NNODES) {
                    atomicAdd(&g_ls1[r0], s1a);
                    atomicAdd(&g_ls2[r0], s2a);
                }
                if (r1 < NNODES) {
                    atomicAdd(&g_ls1[r1], s1b);
                    atomicAdd(&g_ls2[r1], s2b);
                }
            }
        }
    }
    if (MODE == 2) {
#pragma unroll
        for (int nt = 0; nt < 4; nt++) {
            int c = bn + wn * 32 + nt * 8 + tig * 2;
            float b0 = bias[c], b1 = bias[c + 1];
            float p0 = 0.f, p1 = 0.f;
#pragma unroll
            for (int mt = 0; mt < 4; mt++) {
                int r0 = bm + wm * 64 + mt * 16 + gid;
                int r1 = r0 + 8;
                if (r0 < NNODES) {
                    p0 += fmaxf(acc[mt][nt][0] + b0, 0.f);
                    p1 += fmaxf(acc[mt][nt][1] + b1, 0.f);
                }
                if (r1 < NNODES) {
                    p0 += fmaxf(acc[mt][nt][2] + b0, 0.f);
                    p1 += fmaxf(acc[mt][nt][3] + b1, 0.f);
                }
            }
#pragma unroll
            for (int o = 4; o <= 16; o <<= 1) {
                p0 += __shfl_xor_sync(0xffffffffu, p0, o);
                p1 += __shfl_xor_sync(0xffffffffu, p1, o);
            }
            if (gid == 0) {
                atomicAdd(&g_s[c], p0);
                atomicAdd(&g_s[c + 1], p1);
            }
        }
        __shared__ bool isLast;
        __shared__ float sh_s[256];
        __threadfence();
        if (tid == 0) isLast = (atomicAdd(&c_sig, 1) == 2 * 391 - 1);
        __syncthreads();
        if (isLast) {
            sh_s[tid] = g_s[tid];
            __syncthreads();
            float a1 = fc1_b[tid], a2 = fc2_b[tid];
            float a3 = (tid < 128) ? fc3_b[tid] : 0.f;
            float a4 = (tid < 128) ? fc4_b[tid] : 0.f;
            for (int k = 0; k < 256; k++) {
                float sv = sh_s[k];
                a1 += fc1_w[tid * 256 + k] * sv;
                a2 += fc2_w[tid * 256 + k] * sv;
                if (tid < 128) {
                    a3 += fc3_w[tid * 256 + k] * sv;
                    a4 += fc4_w[tid * 256 + k] * sv;
                }
            }
            g_gamma1[tid] = tanhf(a1);
            g_beta1[tid]  = tanhf(a2);
            if (tid < 128) {
                g_gamma2[tid] = tanhf(a3);
                g_beta2[tid]  = tanhf(a4);
            }
            g_s[tid] = 0.0f;
            if (tid == 0) c_sig = 0;
        }
    }
}

// ---------------- final: agg(h2 fp16) + film + LN; tail blocks clean scratch --
__global__ void __launch_bounds__(256) k_agg2(const float* __restrict__ bias,
                                              float* __restrict__ out)
{
    if (blockIdx.x >= NNODES / 8) {
        int cb = blockIdx.x - NNODES / 8;
        int stride = 64 * 256;
        for (int i = cb * 256 + threadIdx.x; i < NNODES; i += stride) {
            g_degi[i] = 0;
            g_count[i] = 0;
            g_fill[i] = 0;
            g_ls1[i] = 0.0f;
            g_ls2[i] = 0.0f;
        }
        return;
    }
    int d = blockIdx.x * 8 + (threadIdx.x >> 5);
    int lane = threadIdx.x & 31;
    int c = lane * 4;
    float dv = g_dinv[d];
    float w0 = dv * dv;
    float4 acc;
    {
        uint2 hv = *(const uint2*)&g_h2h[(size_t)d * 128 + c];
        float2 f0 = __half22float2(u2h(hv.x));
        float2 f1 = __half22float2(u2h(hv.y));
        acc = make_float4(w0 * f0.x, w0 * f0.y, w0 * f1.x, w0 * f1.y);
    }
    int beg = row_beg(d), end = row_end(d);
    int j = beg;
    for (; j + 4 <= end; j += 4) {
        int2 e0 = g_csr[j],     e1 = g_csr[j + 1];
        int2 e2 = g_csr[j + 2], e3 = g_csr[j + 3];
        float wa = __int_as_float(e0.y), wb = __int_as_float(e1.y);
        float wc = __int_as_float(e2.y), wd = __int_as_float(e3.y);
        uint2 ha = *(const uint2*)&g_h2h[(size_t)e0.x * 128 + c];
        uint2 hb = *(const uint2*)&g_h2h[(size_t)e1.x * 128 + c];
        uint2 hc = *(const uint2*)&g_h2h[(size_t)e2.x * 128 + c];
        uint2 hd = *(const uint2*)&g_h2h[(size_t)e3.x * 128 + c];
        float2 a0 = __half22float2(u2h(ha.x)), a1 = __half22float2(u2h(ha.y));
        float2 b0 = __half22float2(u2h(hb.x)), b1 = __half22float2(u2h(hb.y));
        float2 c0 = __half22float2(u2h(hc.x)), c1 = __half22float2(u2h(hc.y));
        float2 d0 = __half22float2(u2h(hd.x)), d1 = __half22float2(u2h(hd.y));
        acc.x += wa * a0.x + wb * b0.x + wc * c0.x + wd * d0.x;
        acc.y += wa * a0.y + wb * b0.y + wc * c0.y + wd * d0.y;
        acc.z += wa * a1.x + wb * b1.x + wc * c1.x + wd * d1.x;
        acc.w += wa * a1.y + wb * b1.y + wc * c1.y + wd * d1.y;
    }
    for (; j < end; j++) {
        int2 e0 = g_csr[j];
        float wa = __int_as_float(e0.y);
        uint2 ha = *(const uint2*)&g_h2h[(size_t)e0.x * 128 + c];
        float2 a0 = __half22float2(u2h(ha.x));
        float2 a1 = __half22float2(u2h(ha.y));
        acc.x += wa * a0.x; acc.y += wa * a0.y;
        acc.z += wa * a1.x; acc.w += wa * a1.y;
    }
    float4 y;
    y.x = g_gamma2[c + 0] * acc.x + g_beta2[c + 0] + bias[c + 0];
    y.y = g_gamma2[c + 1] * acc.y + g_beta2[c + 1] + bias[c + 1];
    y.z = g_gamma2[c + 2] * acc.z + g_beta2[c + 2] + bias[c + 2];
    y.w = g_gamma2[c + 3] * acc.w + g_beta2[c + 3] + bias[c + 3];

    float s1 = y.x + y.y + y.z + y.w;
    float s2 = y.x * y.x + y.y * y.y + y.z * y.z + y.w * y.w;
#pragma unroll
    for (int o = 16; o; o >>= 1) {
        s1 += __shfl_xor_sync(0xffffffffu, s1, o);
        s2 += __shfl_xor_sync(0xffffffffu, s2, o);
    }
    float mu = s1 * (1.0f / 128.0f);
    float var = s2 * (1.0f / 128.0f) - mu * mu;
    float rstd = rsqrtf(var + 1e-5f);
    float4 o4;
    o4.x = (y.x - mu) * rstd;
    o4.y = (y.y - mu) * rstd;
    o4.z = (y.z - mu) * rstd;
    o4.w = (y.w - mu) * rstd;
    *(float4*)&out[(size_t)d * 128 + c] = o4;
}

// ---------------- launch ----------------
extern "C" void kernel_launch(void* const* d_in, const int* in_sizes, int n_in,
                              void* d_out, int out_size)
{
    const float* x       = (const float*)d_in[0];
    const int*   ei      = (const int*)d_in[1];
    const float* conv1_w = (const float*)d_in[2];
    const float* conv1_b = (const float*)d_in[3];
    const float* conv2_w = (const float*)d_in[4];
    const float* conv2_b = (const float*)d_in[5];
    const float* sig_w   = (const float*)d_in[6];
    const float* sig_b   = (const float*)d_in[7];
    const float* fc1_w   = (const float*)d_in[8];
    const float* fc1_b   = (const float*)d_in[9];
    const float* fc2_w   = (const float*)d_in[10];
    const float* fc2_b   = (const float*)d_in[11];
    const float* fc3_w   = (const float*)d_in[12];
    const float* fc3_b   = (const float*)d_in[13];
    const float* fc4_w   = (const float*)d_in[14];
    const float* fc4_b   = (const float*)d_in[15];
    float*       out     = (float*)d_out;

    k_deg_count<<<NEB + NCB, 256>>>(ei, x);
    k_scan1<<<NSB, 1024>>>();
    k_fill<<<(NEDGES + 255) / 256, 256>>>(ei);
    k_agg1<<<NNODES / 8, 256>>>();

    dim3 g256(2, (NNODES + 127) / 128);
    dim3 g128(1, (NNODES + 127) / 128);

    k_gemm<2, 256><<<g256, 256>>>(sig_w, sig_b,
                                  fc1_w, fc1_b, fc2_w, fc2_b,
                                  fc3_w, fc3_b, fc4_w, fc4_b);
    k_gemm<1, 256><<<g256, 256>>>(conv1_w, conv1_b,
                                  nullptr, nullptr, nullptr, nullptr,
                                  nullptr, nullptr, nullptr, nullptr);
    k_gemm<0, 128><<<g128, 256>>>(conv2_w, nullptr,
                                  nullptr, nullptr, nullptr, nullptr,
                                  nullptr, nullptr, nullptr, nullptr);
    k_agg2<<<NNODES / 8 + 64, 256>>>(conv2_b, out);
}